// round 1
// baseline (speedup 1.0000x reference)
#include <cuda_runtime.h>
#include <cstdint>

#define EMB   768
#define EMB3  2304
#define NHEAD 12
#define HDIM  64
#define SEQ   1024
#define BATCH 8

// Scratch (no cudaMalloc allowed): qkv activations + attention output.
__device__ float g_qkv[(size_t)BATCH * SEQ * EMB3];   // [B,T,3C]  75.5 MB
__device__ float g_att[(size_t)BATCH * SEQ * EMB];    // [B,T,C]   25.2 MB

// ---------------------------------------------------------------------------
// SGEMM: C[M,N] = A[M,K] @ B[K,N] + bias[N].  128x128 block tile, BK=8,
// 256 threads, 8x8 per thread.  M%128==0, N%128==0, K%8==0 (holds here).
// ---------------------------------------------------------------------------
__global__ __launch_bounds__(256, 2)
void sgemm_bias_kernel(const float* __restrict__ A, const float* __restrict__ B,
                       const float* __restrict__ bias, float* __restrict__ C,
                       int M, int N, int K)
{
    __shared__ float As[8][128];   // k-major (transposed A tile)
    __shared__ float Bs[8][128];

    const int tid  = threadIdx.x;
    const int tx   = tid & 15;
    const int ty   = tid >> 4;
    const int brow = blockIdx.y * 128;
    const int bcol = blockIdx.x * 128;

    float acc[8][8];
#pragma unroll
    for (int i = 0; i < 8; i++)
#pragma unroll
        for (int j = 0; j < 8; j++) acc[i][j] = 0.f;

    const int ar  = tid >> 1;          // 0..127
    const int ak4 = (tid & 1) * 4;     // 0 or 4
    const int bk  = tid >> 5;          // 0..7
    const int bc4 = (tid & 31) * 4;    // 0..124

    const float* Aptr = A + (size_t)(brow + ar) * K + ak4;
    const float* Bptr = B + (size_t)bk * N + bcol + bc4;

    for (int k0 = 0; k0 < K; k0 += 8) {
        float4 av = *(const float4*)(Aptr + k0);
        As[ak4 + 0][ar] = av.x;
        As[ak4 + 1][ar] = av.y;
        As[ak4 + 2][ar] = av.z;
        As[ak4 + 3][ar] = av.w;
        *(float4*)&Bs[bk][bc4] = *(const float4*)(Bptr + (size_t)k0 * N);
        __syncthreads();

#pragma unroll
        for (int kk = 0; kk < 8; kk++) {
            float4 a0 = *(const float4*)&As[kk][ty * 8];
            float4 a1 = *(const float4*)&As[kk][ty * 8 + 4];
            float4 b0 = *(const float4*)&Bs[kk][tx * 8];
            float4 b1 = *(const float4*)&Bs[kk][tx * 8 + 4];
            float a[8]  = {a0.x, a0.y, a0.z, a0.w, a1.x, a1.y, a1.z, a1.w};
            float bb[8] = {b0.x, b0.y, b0.z, b0.w, b1.x, b1.y, b1.z, b1.w};
#pragma unroll
            for (int i = 0; i < 8; i++)
#pragma unroll
                for (int j = 0; j < 8; j++)
                    acc[i][j] += a[i] * bb[j];
        }
        __syncthreads();
    }

    const float* bptr = bias + bcol + tx * 8;
    float4 bb0 = *(const float4*)(bptr);
    float4 bb1 = *(const float4*)(bptr + 4);
#pragma unroll
    for (int i = 0; i < 8; i++) {
        int row = brow + ty * 8 + i;
        float* Crow = C + (size_t)row * N + bcol + tx * 8;
        float4 o0, o1;
        o0.x = acc[i][0] + bb0.x;  o0.y = acc[i][1] + bb0.y;
        o0.z = acc[i][2] + bb0.z;  o0.w = acc[i][3] + bb0.w;
        o1.x = acc[i][4] + bb1.x;  o1.y = acc[i][5] + bb1.y;
        o1.z = acc[i][6] + bb1.z;  o1.w = acc[i][7] + bb1.w;
        *(float4*)(Crow)     = o0;
        *(float4*)(Crow + 4) = o1;
    }
}

// ---------------------------------------------------------------------------
// Flash-attention (causal, fp32).  One block per (b, h, 64-query tile).
// K-tiles of 64 keys; masked tiles (kt > qt) are skipped entirely; only the
// diagonal tile applies the causal mask.  Online softmax.
//
// Shared layouts (all pitch 64 floats):
//   Qt[d][r]  - Q transposed (d-major)         16 KB
//   Kt[d][c]  - K transposed (d-major)         16 KB
//   Vs[c][d]  - V as-is                        16 KB
//   St[c][r]  - scores transposed (key-major)  16 KB
// St key-major makes BOTH GEMMs float4-vectorizable per 4x4 register tile.
// ---------------------------------------------------------------------------
#define ATTN_SMEM ((4 * 64 * 64 + 3 * 64) * 4)

__global__ __launch_bounds__(256)
void attn_kernel(const float* __restrict__ qkv, float* __restrict__ out)
{
    extern __shared__ float sm[];
    float* Qt   = sm;
    float* Kt   = Qt + 64 * 64;
    float* Vs   = Kt + 64 * 64;
    float* St   = Vs + 64 * 64;
    float* mrow = St + 64 * 64;   // running max per query
    float* lrow = mrow + 64;      // running sum per query
    float* arow = lrow + 64;      // rescale factor per query

    const int tid = threadIdx.x;
    const int bh  = blockIdx.y;
    const int b   = bh / NHEAD;
    const int h   = bh % NHEAD;
    const int qt  = 15 - blockIdx.x;          // heavy tiles scheduled first
    const int qbase = qt * 64;

    // Load Q tile transposed: Qt[d][r]
    {
        const int r  = tid >> 2;
        const int d0 = (tid & 3) * 16;
        const float* src = qkv + ((size_t)(b * SEQ + qbase + r)) * EMB3 + h * HDIM + d0;
#pragma unroll
        for (int i = 0; i < 4; i++) {
            float4 v = *(const float4*)(src + 4 * i);
            Qt[(d0 + 4 * i + 0) * 64 + r] = v.x;
            Qt[(d0 + 4 * i + 1) * 64 + r] = v.y;
            Qt[(d0 + 4 * i + 2) * 64 + r] = v.z;
            Qt[(d0 + 4 * i + 3) * 64 + r] = v.w;
        }
    }
    if (tid < 64) { mrow[tid] = -1e30f; lrow[tid] = 0.f; }

    const int tx = tid & 15;   // query sub-index (cols of St, rows of O)
    const int ty = tid >> 4;   // key sub-index (S) / head-dim sub-index (O)

    float accO[4][4];
#pragma unroll
    for (int i = 0; i < 4; i++)
#pragma unroll
        for (int j = 0; j < 4; j++) accO[i][j] = 0.f;

    for (int kt = 0; kt <= qt; kt++) {
        const int kbase = kt * 64;
        __syncthreads();   // previous iteration's St/Vs readers done

        // Load K (transposed) and V tiles
        {
            const int c  = tid >> 2;
            const int d0 = (tid & 3) * 16;
            const float* ksrc = qkv + ((size_t)(b * SEQ + kbase + c)) * EMB3 + EMB     + h * HDIM + d0;
            const float* vsrc = qkv + ((size_t)(b * SEQ + kbase + c)) * EMB3 + 2 * EMB + h * HDIM + d0;
#pragma unroll
            for (int i = 0; i < 4; i++) {
                float4 kv = *(const float4*)(ksrc + 4 * i);
                Kt[(d0 + 4 * i + 0) * 64 + c] = kv.x;
                Kt[(d0 + 4 * i + 1) * 64 + c] = kv.y;
                Kt[(d0 + 4 * i + 2) * 64 + c] = kv.z;
                Kt[(d0 + 4 * i + 3) * 64 + c] = kv.w;
                *(float4*)&Vs[c * 64 + d0 + 4 * i] = *(const float4*)(vsrc + 4 * i);
            }
        }
        __syncthreads();

        // S GEMM: St[c][r] = sum_d Kt[d][c] * Qt[d][r].  4x4 per thread.
        float accS[4][4];
#pragma unroll
        for (int i = 0; i < 4; i++)
#pragma unroll
            for (int j = 0; j < 4; j++) accS[i][j] = 0.f;

#pragma unroll 8
        for (int d = 0; d < 64; d++) {
            float4 kv = *(const float4*)&Kt[d * 64 + 4 * ty];
            float4 qv = *(const float4*)&Qt[d * 64 + 4 * tx];
            float kk[4] = {kv.x, kv.y, kv.z, kv.w};
            float qq[4] = {qv.x, qv.y, qv.z, qv.w};
#pragma unroll
            for (int i = 0; i < 4; i++)
#pragma unroll
                for (int j = 0; j < 4; j++)
                    accS[i][j] += kk[i] * qq[j];
        }

        // Scale + causal mask (only diagonal tile) + store key-major
        const bool diag = (kt == qt);
#pragma unroll
        for (int i = 0; i < 4; i++) {
            const int kg = kbase + 4 * ty + i;
            float v[4];
#pragma unroll
            for (int j = 0; j < 4; j++) {
                const int qg = qbase + 4 * tx + j;
                float s = accS[i][j] * 0.125f;   // HEAD_DIM^-0.5
                if (diag && kg > qg) s = -1e30f;
                v[j] = s;
            }
            float4 o = {v[0], v[1], v[2], v[3]};
            *(float4*)&St[(4 * ty + i) * 64 + 4 * tx] = o;
        }
        __syncthreads();

        // Online softmax: thread r owns query r (contiguous smem column reads)
        if (tid < 64) {
            const int r = tid;
            float mold = mrow[r];
            float mnew = mold;
            for (int c = 0; c < 64; c++)
                mnew = fmaxf(mnew, St[c * 64 + r]);
            float alpha = __expf(mold - mnew);
            float s = 0.f;
            for (int c = 0; c < 64; c++) {
                float p = __expf(St[c * 64 + r] - mnew);
                St[c * 64 + r] = p;
                s += p;
            }
            mrow[r] = mnew;
            lrow[r] = lrow[r] * alpha + s;
            arow[r] = alpha;
        }
        __syncthreads();

        // Rescale O, then P@V:  O[r][dd] += sum_c St[c][r] * Vs[c][dd]
#pragma unroll
        for (int qi = 0; qi < 4; qi++) {
            float al = arow[4 * tx + qi];
#pragma unroll
            for (int dj = 0; dj < 4; dj++) accO[qi][dj] *= al;
        }
#pragma unroll 8
        for (int c = 0; c < 64; c++) {
            float4 p = *(const float4*)&St[c * 64 + 4 * tx];
            float4 v = *(const float4*)&Vs[c * 64 + 4 * ty];
            float pp[4] = {p.x, p.y, p.z, p.w};
            float vv[4] = {v.x, v.y, v.z, v.w};
#pragma unroll
            for (int qi = 0; qi < 4; qi++)
#pragma unroll
                for (int dj = 0; dj < 4; dj++)
                    accO[qi][dj] += pp[qi] * vv[dj];
        }
    }

    // Epilogue: normalize and write [B,T,C] (head-concat layout for proj GEMM)
    const int r0 = 4 * tx;
    const int d0 = 4 * ty;
#pragma unroll
    for (int qi = 0; qi < 4; qi++) {
        float inv = 1.f / lrow[r0 + qi];
        float4 o;
        o.x = accO[qi][0] * inv;
        o.y = accO[qi][1] * inv;
        o.z = accO[qi][2] * inv;
        o.w = accO[qi][3] * inv;
        *(float4*)&out[((size_t)(b * SEQ + qbase + r0 + qi)) * EMB + h * HDIM + d0] = o;
    }
}

// ---------------------------------------------------------------------------
extern "C" void kernel_launch(void* const* d_in, const int* in_sizes, int n_in,
                              void* d_out, int out_size)
{
    const float* x      = (const float*)d_in[0];   // [8,1024,768]
    const float* W_attn = (const float*)d_in[1];   // [768,2304]
    const float* b_attn = (const float*)d_in[2];   // [2304]
    const float* W_proj = (const float*)d_in[3];   // [768,768]
    const float* b_proj = (const float*)d_in[4];   // [768]
    float* out = (float*)d_out;                    // [8,1024,768]

    float *qkv = nullptr, *att = nullptr;
    cudaGetSymbolAddress((void**)&qkv, g_qkv);
    cudaGetSymbolAddress((void**)&att, g_att);

    cudaFuncSetAttribute(attn_kernel,
                         cudaFuncAttributeMaxDynamicSharedMemorySize, ATTN_SMEM);

    const int M = BATCH * SEQ;  // 8192

    // 1) QKV = x @ W_attn + b_attn
    sgemm_bias_kernel<<<dim3(EMB3 / 128, M / 128), 256>>>(
        x, W_attn, b_attn, qkv, M, EMB3, EMB);

    // 2) causal multi-head attention -> [B,T,C]
    attn_kernel<<<dim3(SEQ / 64, BATCH * NHEAD), 256, ATTN_SMEM>>>(qkv, att);

    // 3) out = att @ W_proj + b_proj
    sgemm_bias_kernel<<<dim3(EMB / 128, M / 128), 256>>>(
        att, W_proj, b_proj, out, M, EMB, EMB);
}

// round 2
// speedup vs baseline: 1.6922x; 1.6922x over previous
#include <cuda_runtime.h>
#include <cstdint>

#define EMB   768
#define EMB3  2304
#define NHEAD 12
#define HDIM  64
#define SEQ   1024
#define BATCH 8

// Scratch (no cudaMalloc allowed): qkv activations + attention output.
__device__ float g_qkv[(size_t)BATCH * SEQ * EMB3];   // [B,T,3C]  75.5 MB
__device__ float g_att[(size_t)BATCH * SEQ * EMB];    // [B,T,C]   25.2 MB

// ---------------------------------------------------------------------------
// Helpers: tf32 convert, cp.async
// ---------------------------------------------------------------------------
__device__ __forceinline__ uint32_t f2tf32(float f) {
    uint32_t u;
    asm("cvt.rna.tf32.f32 %0, %1;" : "=r"(u) : "f"(f));
    return u;
}

__device__ __forceinline__ void cpa16(void* smem_dst, const void* gmem_src) {
    uint32_t s = (uint32_t)__cvta_generic_to_shared(smem_dst);
    asm volatile("cp.async.cg.shared.global [%0], [%1], 16;\n" :: "r"(s), "l"(gmem_src));
}
__device__ __forceinline__ void cpa_commit() { asm volatile("cp.async.commit_group;\n"); }
__device__ __forceinline__ void cpa_wait0()  { asm volatile("cp.async.wait_group 0;\n" ::: "memory"); }

__device__ __forceinline__ void mma_tf32(float& d0, float& d1, float& d2, float& d3,
                                         uint32_t a0, uint32_t a1, uint32_t a2, uint32_t a3,
                                         uint32_t b0, uint32_t b1) {
    asm volatile(
        "mma.sync.aligned.m16n8k8.row.col.f32.tf32.tf32.f32 "
        "{%0,%1,%2,%3}, {%4,%5,%6,%7}, {%8,%9}, {%0,%1,%2,%3};\n"
        : "+f"(d0), "+f"(d1), "+f"(d2), "+f"(d3)
        : "r"(a0), "r"(a1), "r"(a2), "r"(a3), "r"(b0), "r"(b1));
}

// ---------------------------------------------------------------------------
// TF32 tensor-core GEMM: C[M,N] = A[M,K] @ B[K,N] + bias[N]
// 128x128 block tile, BK=16, 256 threads = 8 warps in 2(m) x 4(n) grid,
// 64x32 warp tile, mma.sync m16n8k8.  cp.async double-buffered pipeline.
// Requires M%128==0, N%128==0, K%16==0 (holds for all uses here).
// ---------------------------------------------------------------------------
#define APITCH 20    // 16 + 4 pad (floats) — conflict-free A frag loads
#define BPITCH 132   // 128 + 4 pad (floats)

__global__ __launch_bounds__(256)
void gemm_tf32_kernel(const float* __restrict__ A, const float* __restrict__ B,
                      const float* __restrict__ bias, float* __restrict__ C,
                      int M, int N, int K)
{
    __shared__ float As[2][128 * APITCH];   // [m][k] padded
    __shared__ float Bs[2][16 * BPITCH];    // [k][n] padded

    const int tid    = threadIdx.x;
    const int lane   = tid & 31;
    const int warp   = tid >> 5;
    const int warp_m = warp >> 2;           // 0..1  -> 64-row slab
    const int warp_n = warp & 3;            // 0..3  -> 32-col slab
    const int gr     = lane >> 2;           // groupID 0..7
    const int gc     = lane & 3;            // threadInGroup 0..3

    const int brow = blockIdx.y * 128;
    const int bcol = blockIdx.x * 128;

    // Global->smem load indexing (two float4 per thread per tile)
    const int a_row = tid >> 1;             // 0..127
    const int a_c4  = (tid & 1) * 2;        // float4 index 0 or 2 (loads 2)
    const int b_row = tid >> 4;             // 0..15
    const int b_c4  = (tid & 15) * 2;       // float4 index (loads 2)

    const float* gA = A + (size_t)(brow + a_row) * K + a_c4 * 4;
    const float* gB = B + (size_t)b_row * N + bcol + b_c4 * 4;

    float acc[4][4][4];
#pragma unroll
    for (int i = 0; i < 4; i++)
#pragma unroll
        for (int j = 0; j < 4; j++)
#pragma unroll
            for (int v = 0; v < 4; v++) acc[i][j][v] = 0.f;

    const int KT = K / 16;

    // Prologue: load tile 0 into buffer 0
    {
        float* as = &As[0][a_row * APITCH + a_c4 * 4];
        cpa16(as,     gA);
        cpa16(as + 4, gA + 4);
        float* bs = &Bs[0][b_row * BPITCH + b_c4 * 4];
        cpa16(bs,     gB);
        cpa16(bs + 4, gB + 4);
        cpa_commit();
    }

    int buf = 0;
    for (int kt = 0; kt < KT; kt++) {
        cpa_wait0();
        __syncthreads();

        if (kt + 1 < KT) {
            const int k0 = (kt + 1) * 16;
            float* as = &As[buf ^ 1][a_row * APITCH + a_c4 * 4];
            cpa16(as,     gA + k0);
            cpa16(as + 4, gA + k0 + 4);
            float* bs = &Bs[buf ^ 1][b_row * BPITCH + b_c4 * 4];
            cpa16(bs,     gB + (size_t)k0 * N);
            cpa16(bs + 4, gB + (size_t)k0 * N + 4);
            cpa_commit();
        }

        const float* as = As[buf];
        const float* bs = Bs[buf];

#pragma unroll
        for (int ks = 0; ks < 2; ks++) {
            const int k8 = ks * 8;
            uint32_t af[4][4], bf[4][2];
#pragma unroll
            for (int mi = 0; mi < 4; mi++) {
                const int m0 = warp_m * 64 + mi * 16;
                af[mi][0] = f2tf32(as[(m0 + gr)     * APITCH + k8 + gc]);
                af[mi][1] = f2tf32(as[(m0 + gr + 8) * APITCH + k8 + gc]);
                af[mi][2] = f2tf32(as[(m0 + gr)     * APITCH + k8 + gc + 4]);
                af[mi][3] = f2tf32(as[(m0 + gr + 8) * APITCH + k8 + gc + 4]);
            }
#pragma unroll
            for (int ni = 0; ni < 4; ni++) {
                const int n0 = warp_n * 32 + ni * 8;
                bf[ni][0] = f2tf32(bs[(k8 + gc)     * BPITCH + n0 + gr]);
                bf[ni][1] = f2tf32(bs[(k8 + gc + 4) * BPITCH + n0 + gr]);
            }
#pragma unroll
            for (int mi = 0; mi < 4; mi++)
#pragma unroll
                for (int ni = 0; ni < 4; ni++)
                    mma_tf32(acc[mi][ni][0], acc[mi][ni][1],
                             acc[mi][ni][2], acc[mi][ni][3],
                             af[mi][0], af[mi][1], af[mi][2], af[mi][3],
                             bf[ni][0], bf[ni][1]);
        }
        __syncthreads();
        buf ^= 1;
    }

    // Epilogue: C = acc + bias.  c0,c1 at (row=gr, col=2*gc,2*gc+1); c2,c3 row+8.
#pragma unroll
    for (int ni = 0; ni < 4; ni++) {
        const int col = bcol + warp_n * 32 + ni * 8 + 2 * gc;
        const float bv0 = bias[col];
        const float bv1 = bias[col + 1];
#pragma unroll
        for (int mi = 0; mi < 4; mi++) {
            const int row = brow + warp_m * 64 + mi * 16 + gr;
            float2 o0 = {acc[mi][ni][0] + bv0, acc[mi][ni][1] + bv1};
            float2 o1 = {acc[mi][ni][2] + bv0, acc[mi][ni][3] + bv1};
            *(float2*)&C[(size_t)row * N + col]       = o0;
            *(float2*)&C[(size_t)(row + 8) * N + col] = o1;
        }
    }
}

// ---------------------------------------------------------------------------
// Flash-attention (causal, fp32) — unchanged from round 1.
// ---------------------------------------------------------------------------
#define ATTN_SMEM ((4 * 64 * 64 + 3 * 64) * 4)

__global__ __launch_bounds__(256)
void attn_kernel(const float* __restrict__ qkv, float* __restrict__ out)
{
    extern __shared__ float sm[];
    float* Qt   = sm;
    float* Kt   = Qt + 64 * 64;
    float* Vs   = Kt + 64 * 64;
    float* St   = Vs + 64 * 64;
    float* mrow = St + 64 * 64;
    float* lrow = mrow + 64;
    float* arow = lrow + 64;

    const int tid = threadIdx.x;
    const int bh  = blockIdx.y;
    const int b   = bh / NHEAD;
    const int h   = bh % NHEAD;
    const int qt  = 15 - blockIdx.x;
    const int qbase = qt * 64;

    {
        const int r  = tid >> 2;
        const int d0 = (tid & 3) * 16;
        const float* src = qkv + ((size_t)(b * SEQ + qbase + r)) * EMB3 + h * HDIM + d0;
#pragma unroll
        for (int i = 0; i < 4; i++) {
            float4 v = *(const float4*)(src + 4 * i);
            Qt[(d0 + 4 * i + 0) * 64 + r] = v.x;
            Qt[(d0 + 4 * i + 1) * 64 + r] = v.y;
            Qt[(d0 + 4 * i + 2) * 64 + r] = v.z;
            Qt[(d0 + 4 * i + 3) * 64 + r] = v.w;
        }
    }
    if (tid < 64) { mrow[tid] = -1e30f; lrow[tid] = 0.f; }

    const int tx = tid & 15;
    const int ty = tid >> 4;

    float accO[4][4];
#pragma unroll
    for (int i = 0; i < 4; i++)
#pragma unroll
        for (int j = 0; j < 4; j++) accO[i][j] = 0.f;

    for (int kt = 0; kt <= qt; kt++) {
        const int kbase = kt * 64;
        __syncthreads();

        {
            const int c  = tid >> 2;
            const int d0 = (tid & 3) * 16;
            const float* ksrc = qkv + ((size_t)(b * SEQ + kbase + c)) * EMB3 + EMB     + h * HDIM + d0;
            const float* vsrc = qkv + ((size_t)(b * SEQ + kbase + c)) * EMB3 + 2 * EMB + h * HDIM + d0;
#pragma unroll
            for (int i = 0; i < 4; i++) {
                float4 kv = *(const float4*)(ksrc + 4 * i);
                Kt[(d0 + 4 * i + 0) * 64 + c] = kv.x;
                Kt[(d0 + 4 * i + 1) * 64 + c] = kv.y;
                Kt[(d0 + 4 * i + 2) * 64 + c] = kv.z;
                Kt[(d0 + 4 * i + 3) * 64 + c] = kv.w;
                *(float4*)&Vs[c * 64 + d0 + 4 * i] = *(const float4*)(vsrc + 4 * i);
            }
        }
        __syncthreads();

        float accS[4][4];
#pragma unroll
        for (int i = 0; i < 4; i++)
#pragma unroll
            for (int j = 0; j < 4; j++) accS[i][j] = 0.f;

#pragma unroll 8
        for (int d = 0; d < 64; d++) {
            float4 kv = *(const float4*)&Kt[d * 64 + 4 * ty];
            float4 qv = *(const float4*)&Qt[d * 64 + 4 * tx];
            float kk[4] = {kv.x, kv.y, kv.z, kv.w};
            float qq[4] = {qv.x, qv.y, qv.z, qv.w};
#pragma unroll
            for (int i = 0; i < 4; i++)
#pragma unroll
                for (int j = 0; j < 4; j++)
                    accS[i][j] += kk[i] * qq[j];
        }

        const bool diag = (kt == qt);
#pragma unroll
        for (int i = 0; i < 4; i++) {
            const int kg = kbase + 4 * ty + i;
            float v[4];
#pragma unroll
            for (int j = 0; j < 4; j++) {
                const int qg = qbase + 4 * tx + j;
                float s = accS[i][j] * 0.125f;
                if (diag && kg > qg) s = -1e30f;
                v[j] = s;
            }
            float4 o = {v[0], v[1], v[2], v[3]};
            *(float4*)&St[(4 * ty + i) * 64 + 4 * tx] = o;
        }
        __syncthreads();

        if (tid < 64) {
            const int r = tid;
            float mold = mrow[r];
            float mnew = mold;
            for (int c = 0; c < 64; c++)
                mnew = fmaxf(mnew, St[c * 64 + r]);
            float alpha = __expf(mold - mnew);
            float s = 0.f;
            for (int c = 0; c < 64; c++) {
                float p = __expf(St[c * 64 + r] - mnew);
                St[c * 64 + r] = p;
                s += p;
            }
            mrow[r] = mnew;
            lrow[r] = lrow[r] * alpha + s;
            arow[r] = alpha;
        }
        __syncthreads();

#pragma unroll
        for (int qi = 0; qi < 4; qi++) {
            float al = arow[4 * tx + qi];
#pragma unroll
            for (int dj = 0; dj < 4; dj++) accO[qi][dj] *= al;
        }
#pragma unroll 8
        for (int c = 0; c < 64; c++) {
            float4 p = *(const float4*)&St[c * 64 + 4 * tx];
            float4 v = *(const float4*)&Vs[c * 64 + 4 * ty];
            float pp[4] = {p.x, p.y, p.z, p.w};
            float vv[4] = {v.x, v.y, v.z, v.w};
#pragma unroll
            for (int qi = 0; qi < 4; qi++)
#pragma unroll
                for (int dj = 0; dj < 4; dj++)
                    accO[qi][dj] += pp[qi] * vv[dj];
        }
    }

    const int r0 = 4 * tx;
    const int d0 = 4 * ty;
#pragma unroll
    for (int qi = 0; qi < 4; qi++) {
        float inv = 1.f / lrow[r0 + qi];
        float4 o;
        o.x = accO[qi][0] * inv;
        o.y = accO[qi][1] * inv;
        o.z = accO[qi][2] * inv;
        o.w = accO[qi][3] * inv;
        *(float4*)&out[((size_t)(b * SEQ + qbase + r0 + qi)) * EMB + h * HDIM + d0] = o;
    }
}

// ---------------------------------------------------------------------------
extern "C" void kernel_launch(void* const* d_in, const int* in_sizes, int n_in,
                              void* d_out, int out_size)
{
    const float* x      = (const float*)d_in[0];   // [8,1024,768]
    const float* W_attn = (const float*)d_in[1];   // [768,2304]
    const float* b_attn = (const float*)d_in[2];   // [2304]
    const float* W_proj = (const float*)d_in[3];   // [768,768]
    const float* b_proj = (const float*)d_in[4];   // [768]
    float* out = (float*)d_out;                    // [8,1024,768]

    float *qkv = nullptr, *att = nullptr;
    cudaGetSymbolAddress((void**)&qkv, g_qkv);
    cudaGetSymbolAddress((void**)&att, g_att);

    cudaFuncSetAttribute(attn_kernel,
                         cudaFuncAttributeMaxDynamicSharedMemorySize, ATTN_SMEM);

    const int M = BATCH * SEQ;  // 8192

    // 1) QKV = x @ W_attn + b_attn   (tf32 tensor cores)
    gemm_tf32_kernel<<<dim3(EMB3 / 128, M / 128), 256>>>(
        x, W_attn, b_attn, qkv, M, EMB3, EMB);

    // 2) causal multi-head attention -> [B,T,C]
    attn_kernel<<<dim3(SEQ / 64, BATCH * NHEAD), 256, ATTN_SMEM>>>(qkv, att);

    // 3) out = att @ W_proj + b_proj  (tf32 tensor cores)
    gemm_tf32_kernel<<<dim3(EMB / 128, M / 128), 256>>>(
        att, W_proj, b_proj, out, M, EMB, EMB);
}

// round 3
// speedup vs baseline: 2.5221x; 1.4904x over previous
#include <cuda_runtime.h>
#include <cstdint>

#define EMB   768
#define EMB3  2304
#define NHEAD 12
#define HDIM  64
#define SEQ   1024
#define BATCH 8

// Scratch (no cudaMalloc allowed): qkv activations + attention output.
__device__ float g_qkv[(size_t)BATCH * SEQ * EMB3];   // [B,T,3C]  75.5 MB
__device__ float g_att[(size_t)BATCH * SEQ * EMB];    // [B,T,C]   25.2 MB

// ---------------------------------------------------------------------------
// Helpers: tf32 convert, cp.async, mma
// ---------------------------------------------------------------------------
__device__ __forceinline__ uint32_t f2tf32(float f) {
    uint32_t u;
    asm("cvt.rna.tf32.f32 %0, %1;" : "=r"(u) : "f"(f));
    return u;
}

__device__ __forceinline__ void cpa16(void* smem_dst, const void* gmem_src) {
    uint32_t s = (uint32_t)__cvta_generic_to_shared(smem_dst);
    asm volatile("cp.async.cg.shared.global [%0], [%1], 16;\n" :: "r"(s), "l"(gmem_src));
}
__device__ __forceinline__ void cpa_commit() { asm volatile("cp.async.commit_group;\n"); }
__device__ __forceinline__ void cpa_wait0()  { asm volatile("cp.async.wait_group 0;\n" ::: "memory"); }

__device__ __forceinline__ void mma_tf32(float& d0, float& d1, float& d2, float& d3,
                                         uint32_t a0, uint32_t a1, uint32_t a2, uint32_t a3,
                                         uint32_t b0, uint32_t b1) {
    asm volatile(
        "mma.sync.aligned.m16n8k8.row.col.f32.tf32.tf32.f32 "
        "{%0,%1,%2,%3}, {%4,%5,%6,%7}, {%8,%9}, {%0,%1,%2,%3};\n"
        : "+f"(d0), "+f"(d1), "+f"(d2), "+f"(d3)
        : "r"(a0), "r"(a1), "r"(a2), "r"(a3), "r"(b0), "r"(b1));
}

// ---------------------------------------------------------------------------
// TF32 tensor-core GEMM (unchanged from round 2):
// C[M,N] = A[M,K] @ B[K,N] + bias[N]; 128x128 tile, BK=16, 256 thr, m16n8k8.
// ---------------------------------------------------------------------------
#define APITCH 20
#define BPITCH 132

__global__ __launch_bounds__(256)
void gemm_tf32_kernel(const float* __restrict__ A, const float* __restrict__ B,
                      const float* __restrict__ bias, float* __restrict__ C,
                      int M, int N, int K)
{
    __shared__ float As[2][128 * APITCH];
    __shared__ float Bs[2][16 * BPITCH];

    const int tid    = threadIdx.x;
    const int lane   = tid & 31;
    const int warp   = tid >> 5;
    const int warp_m = warp >> 2;
    const int warp_n = warp & 3;
    const int gr     = lane >> 2;
    const int gc     = lane & 3;

    const int brow = blockIdx.y * 128;
    const int bcol = blockIdx.x * 128;

    const int a_row = tid >> 1;
    const int a_c4  = (tid & 1) * 2;
    const int b_row = tid >> 4;
    const int b_c4  = (tid & 15) * 2;

    const float* gA = A + (size_t)(brow + a_row) * K + a_c4 * 4;
    const float* gB = B + (size_t)b_row * N + bcol + b_c4 * 4;

    float acc[4][4][4];
#pragma unroll
    for (int i = 0; i < 4; i++)
#pragma unroll
        for (int j = 0; j < 4; j++)
#pragma unroll
            for (int v = 0; v < 4; v++) acc[i][j][v] = 0.f;

    const int KT = K / 16;

    {
        float* as = &As[0][a_row * APITCH + a_c4 * 4];
        cpa16(as,     gA);
        cpa16(as + 4, gA + 4);
        float* bs = &Bs[0][b_row * BPITCH + b_c4 * 4];
        cpa16(bs,     gB);
        cpa16(bs + 4, gB + 4);
        cpa_commit();
    }

    int buf = 0;
    for (int kt = 0; kt < KT; kt++) {
        cpa_wait0();
        __syncthreads();

        if (kt + 1 < KT) {
            const int k0 = (kt + 1) * 16;
            float* as = &As[buf ^ 1][a_row * APITCH + a_c4 * 4];
            cpa16(as,     gA + k0);
            cpa16(as + 4, gA + k0 + 4);
            float* bs = &Bs[buf ^ 1][b_row * BPITCH + b_c4 * 4];
            cpa16(bs,     gB + (size_t)k0 * N);
            cpa16(bs + 4, gB + (size_t)k0 * N + 4);
            cpa_commit();
        }

        const float* as = As[buf];
        const float* bs = Bs[buf];

#pragma unroll
        for (int ks = 0; ks < 2; ks++) {
            const int k8 = ks * 8;
            uint32_t af[4][4], bf[4][2];
#pragma unroll
            for (int mi = 0; mi < 4; mi++) {
                const int m0 = warp_m * 64 + mi * 16;
                af[mi][0] = f2tf32(as[(m0 + gr)     * APITCH + k8 + gc]);
                af[mi][1] = f2tf32(as[(m0 + gr + 8) * APITCH + k8 + gc]);
                af[mi][2] = f2tf32(as[(m0 + gr)     * APITCH + k8 + gc + 4]);
                af[mi][3] = f2tf32(as[(m0 + gr + 8) * APITCH + k8 + gc + 4]);
            }
#pragma unroll
            for (int ni = 0; ni < 4; ni++) {
                const int n0 = warp_n * 32 + ni * 8;
                bf[ni][0] = f2tf32(bs[(k8 + gc)     * BPITCH + n0 + gr]);
                bf[ni][1] = f2tf32(bs[(k8 + gc + 4) * BPITCH + n0 + gr]);
            }
#pragma unroll
            for (int mi = 0; mi < 4; mi++)
#pragma unroll
                for (int ni = 0; ni < 4; ni++)
                    mma_tf32(acc[mi][ni][0], acc[mi][ni][1],
                             acc[mi][ni][2], acc[mi][ni][3],
                             af[mi][0], af[mi][1], af[mi][2], af[mi][3],
                             bf[ni][0], bf[ni][1]);
        }
        __syncthreads();
        buf ^= 1;
    }

#pragma unroll
    for (int ni = 0; ni < 4; ni++) {
        const int col = bcol + warp_n * 32 + ni * 8 + 2 * gc;
        const float bv0 = bias[col];
        const float bv1 = bias[col + 1];
#pragma unroll
        for (int mi = 0; mi < 4; mi++) {
            const int row = brow + warp_m * 64 + mi * 16 + gr;
            float2 o0 = {acc[mi][ni][0] + bv0, acc[mi][ni][1] + bv1};
            float2 o1 = {acc[mi][ni][2] + bv0, acc[mi][ni][3] + bv1};
            *(float2*)&C[(size_t)row * N + col]       = o0;
            *(float2*)&C[(size_t)(row + 8) * N + col] = o1;
        }
    }
}

// ---------------------------------------------------------------------------
// Tensor-core flash attention (causal, tf32 mma, fp32 accum).
// Block = 128 threads (4 warps), one (b,h) and one 64-query tile.
// Warp w owns query rows [16w, 16w+16).  Online softmax in registers using
// the m16n8 fragment layout (row r owned by quad lanes 4r..4r+3).
//
// Shared:
//   QP[64][68]    Q tile (natural [q][d]), later reused as P[q][key]
//   Ks[2][64][68] K tiles (natural [key][d]), double-buffered cp.async
//   Vs[2][64][72] V tiles (natural [key][d]); pitch 72 => conflict-free
//                 B-fragment reads (row index varies with gc)
// ---------------------------------------------------------------------------
#define QPP 68
#define KPP 68
#define VPP 72

__global__ __launch_bounds__(128)
void attn_mma_kernel(const float* __restrict__ qkv, float* __restrict__ out)
{
    __shared__ float QP[64 * QPP];
    __shared__ float Ks[2][64 * KPP];
    __shared__ float Vs[2][64 * VPP];

    const int tid  = threadIdx.x;
    const int lane = tid & 31;
    const int warp = tid >> 5;
    const int gr   = lane >> 2;
    const int gc   = lane & 3;

    const int bh = blockIdx.y;
    const int b  = bh / NHEAD;
    const int h  = bh % NHEAD;
    const int qt = 15 - blockIdx.x;       // heavy tiles first
    const int qbase = qt * 64;

    const int ldr  = tid >> 1;            // 0..63 (row for coop loads)
    const int ldc  = (tid & 1) * 32;      // 0 or 32

    // Load Q tile (natural layout)
    {
        const float* src = qkv + (size_t)(b * SEQ + qbase + ldr) * EMB3 + h * HDIM + ldc;
        float* dst = &QP[ldr * QPP + ldc];
#pragma unroll
        for (int i = 0; i < 8; i++)
            *(float4*)(dst + 4 * i) = *(const float4*)(src + 4 * i);
    }

    // Prologue: async-load K/V tile 0
    {
        const float* kp = qkv + (size_t)(b * SEQ + ldr) * EMB3 + EMB + h * HDIM + ldc;
        float* ks = &Ks[0][ldr * KPP + ldc];
        float* vs = &Vs[0][ldr * VPP + ldc];
#pragma unroll
        for (int i = 0; i < 8; i++) {
            cpa16(ks + 4 * i, kp + 4 * i);
            cpa16(vs + 4 * i, kp + EMB + 4 * i);
        }
        cpa_commit();
    }
    __syncthreads();   // Q tile visible

    // Q fragments in registers (held across the whole K loop)
    uint32_t qf[8][4];
    {
        const int m0 = warp * 16;
#pragma unroll
        for (int ks = 0; ks < 8; ks++) {
            const int k8 = ks * 8;
            qf[ks][0] = f2tf32(QP[(m0 + gr)     * QPP + k8 + gc]);
            qf[ks][1] = f2tf32(QP[(m0 + gr + 8) * QPP + k8 + gc]);
            qf[ks][2] = f2tf32(QP[(m0 + gr)     * QPP + k8 + gc + 4]);
            qf[ks][3] = f2tf32(QP[(m0 + gr + 8) * QPP + k8 + gc + 4]);
        }
    }

    float o[8][4];
#pragma unroll
    for (int i = 0; i < 8; i++)
#pragma unroll
        for (int j = 0; j < 4; j++) o[i][j] = 0.f;
    float mr0 = -1e30f, mr1 = -1e30f, l0 = 0.f, l1 = 0.f;

    const int prow0 = (warp * 16 + gr) * QPP;       // P row bases (warp-local strip)
    const int prow1 = (warp * 16 + gr + 8) * QPP;

    int buf = 0;
    for (int kt = 0; kt <= qt; kt++) {
        cpa_wait0();
        __syncthreads();   // tile(kt) ready; all reads of buf^1 from kt-1 done

        if (kt < qt) {     // prefetch tile kt+1
            const float* kp = qkv + (size_t)(b * SEQ + (kt + 1) * 64 + ldr) * EMB3
                              + EMB + h * HDIM + ldc;
            float* ks = &Ks[buf ^ 1][ldr * KPP + ldc];
            float* vs = &Vs[buf ^ 1][ldr * VPP + ldc];
#pragma unroll
            for (int i = 0; i < 8; i++) {
                cpa16(ks + 4 * i, kp + 4 * i);
                cpa16(vs + 4 * i, kp + EMB + 4 * i);
            }
            cpa_commit();
        }

        // ---- S = Q @ K^T  (warp strip: 16 x 64) ----
        float s[8][4];
#pragma unroll
        for (int i = 0; i < 8; i++)
#pragma unroll
            for (int j = 0; j < 4; j++) s[i][j] = 0.f;

        const float* ksm = Ks[buf];
#pragma unroll
        for (int ks = 0; ks < 8; ks++) {
            const int k8 = ks * 8;
            uint32_t bf[8][2];
#pragma unroll
            for (int nt = 0; nt < 8; nt++) {
                bf[nt][0] = f2tf32(ksm[(nt * 8 + gr) * KPP + k8 + gc]);
                bf[nt][1] = f2tf32(ksm[(nt * 8 + gr) * KPP + k8 + gc + 4]);
            }
#pragma unroll
            for (int nt = 0; nt < 8; nt++)
                mma_tf32(s[nt][0], s[nt][1], s[nt][2], s[nt][3],
                         qf[ks][0], qf[ks][1], qf[ks][2], qf[ks][3],
                         bf[nt][0], bf[nt][1]);
        }

        // ---- scale + causal mask (diagonal tile only) ----
        if (kt == qt) {
            const int lr0 = warp * 16 + gr;
            const int lr1 = lr0 + 8;
#pragma unroll
            for (int nt = 0; nt < 8; nt++) {
                const int c0 = nt * 8 + 2 * gc;
                s[nt][0] = (c0     > lr0) ? -1e30f : s[nt][0] * 0.125f;
                s[nt][1] = (c0 + 1 > lr0) ? -1e30f : s[nt][1] * 0.125f;
                s[nt][2] = (c0     > lr1) ? -1e30f : s[nt][2] * 0.125f;
                s[nt][3] = (c0 + 1 > lr1) ? -1e30f : s[nt][3] * 0.125f;
            }
        } else {
#pragma unroll
            for (int nt = 0; nt < 8; nt++) {
                s[nt][0] *= 0.125f; s[nt][1] *= 0.125f;
                s[nt][2] *= 0.125f; s[nt][3] *= 0.125f;
            }
        }

        // ---- online softmax (register, quad-shuffle row reduce) ----
        float mx0 = -1e30f, mx1 = -1e30f;
#pragma unroll
        for (int nt = 0; nt < 8; nt++) {
            mx0 = fmaxf(mx0, fmaxf(s[nt][0], s[nt][1]));
            mx1 = fmaxf(mx1, fmaxf(s[nt][2], s[nt][3]));
        }
        mx0 = fmaxf(mx0, __shfl_xor_sync(0xffffffffu, mx0, 1));
        mx0 = fmaxf(mx0, __shfl_xor_sync(0xffffffffu, mx0, 2));
        mx1 = fmaxf(mx1, __shfl_xor_sync(0xffffffffu, mx1, 1));
        mx1 = fmaxf(mx1, __shfl_xor_sync(0xffffffffu, mx1, 2));

        const float mn0 = fmaxf(mr0, mx0);
        const float mn1 = fmaxf(mr1, mx1);
        const float a0  = __expf(mr0 - mn0);
        const float a1  = __expf(mr1 - mn1);
        mr0 = mn0; mr1 = mn1;

        float sum0 = 0.f, sum1 = 0.f;
#pragma unroll
        for (int nt = 0; nt < 8; nt++) {
            s[nt][0] = __expf(s[nt][0] - mn0);
            s[nt][1] = __expf(s[nt][1] - mn0);
            s[nt][2] = __expf(s[nt][2] - mn1);
            s[nt][3] = __expf(s[nt][3] - mn1);
            sum0 += s[nt][0] + s[nt][1];
            sum1 += s[nt][2] + s[nt][3];
        }
        sum0 += __shfl_xor_sync(0xffffffffu, sum0, 1);
        sum0 += __shfl_xor_sync(0xffffffffu, sum0, 2);
        sum1 += __shfl_xor_sync(0xffffffffu, sum1, 1);
        sum1 += __shfl_xor_sync(0xffffffffu, sum1, 2);
        l0 = l0 * a0 + sum0;
        l1 = l1 * a1 + sum1;

        // rescale O
#pragma unroll
        for (int nt = 0; nt < 8; nt++) {
            o[nt][0] *= a0; o[nt][1] *= a0;
            o[nt][2] *= a1; o[nt][3] *= a1;
        }

        // ---- P -> smem (warp-local strip), re-read as A fragments ----
#pragma unroll
        for (int nt = 0; nt < 8; nt++) {
            float2 p01 = {s[nt][0], s[nt][1]};
            float2 p23 = {s[nt][2], s[nt][3]};
            *(float2*)&QP[prow0 + nt * 8 + 2 * gc] = p01;
            *(float2*)&QP[prow1 + nt * 8 + 2 * gc] = p23;
        }
        __syncwarp();

        // ---- O += P @ V ----
        const float* vsm = Vs[buf];
#pragma unroll
        for (int ks = 0; ks < 8; ks++) {
            const int k8 = ks * 8;
            uint32_t af[4];
            af[0] = f2tf32(QP[prow0 + k8 + gc]);
            af[1] = f2tf32(QP[prow1 + k8 + gc]);
            af[2] = f2tf32(QP[prow0 + k8 + gc + 4]);
            af[3] = f2tf32(QP[prow1 + k8 + gc + 4]);
            uint32_t bf[8][2];
#pragma unroll
            for (int nt = 0; nt < 8; nt++) {
                bf[nt][0] = f2tf32(vsm[(k8 + gc)     * VPP + nt * 8 + gr]);
                bf[nt][1] = f2tf32(vsm[(k8 + gc + 4) * VPP + nt * 8 + gr]);
            }
#pragma unroll
            for (int nt = 0; nt < 8; nt++)
                mma_tf32(o[nt][0], o[nt][1], o[nt][2], o[nt][3],
                         af[0], af[1], af[2], af[3],
                         bf[nt][0], bf[nt][1]);
        }
        __syncwarp();   // P reads done before next iteration overwrites strip
        buf ^= 1;
    }

    // ---- epilogue: normalize, write [B,T,C] head-concat ----
    const float inv0 = 1.f / l0;
    const float inv1 = 1.f / l1;
    const int r0g = b * SEQ + qbase + warp * 16 + gr;
#pragma unroll
    for (int nt = 0; nt < 8; nt++) {
        const int col = h * HDIM + nt * 8 + 2 * gc;
        float2 o0 = {o[nt][0] * inv0, o[nt][1] * inv0};
        float2 o1 = {o[nt][2] * inv1, o[nt][3] * inv1};
        *(float2*)&out[(size_t)r0g * EMB + col]       = o0;
        *(float2*)&out[(size_t)(r0g + 8) * EMB + col] = o1;
    }
}

// ---------------------------------------------------------------------------
extern "C" void kernel_launch(void* const* d_in, const int* in_sizes, int n_in,
                              void* d_out, int out_size)
{
    const float* x      = (const float*)d_in[0];   // [8,1024,768]
    const float* W_attn = (const float*)d_in[1];   // [768,2304]
    const float* b_attn = (const float*)d_in[2];   // [2304]
    const float* W_proj = (const float*)d_in[3];   // [768,768]
    const float* b_proj = (const float*)d_in[4];   // [768]
    float* out = (float*)d_out;                    // [8,1024,768]

    float *qkv = nullptr, *att = nullptr;
    cudaGetSymbolAddress((void**)&qkv, g_qkv);
    cudaGetSymbolAddress((void**)&att, g_att);

    const int M = BATCH * SEQ;  // 8192

    // 1) QKV = x @ W_attn + b_attn   (tf32 tensor cores)
    gemm_tf32_kernel<<<dim3(EMB3 / 128, M / 128), 256>>>(
        x, W_attn, b_attn, qkv, M, EMB3, EMB);

    // 2) causal multi-head attention (tf32 tensor cores) -> [B,T,C]
    attn_mma_kernel<<<dim3(SEQ / 64, BATCH * NHEAD), 128>>>(qkv, att);

    // 3) out = att @ W_proj + b_proj  (tf32 tensor cores)
    gemm_tf32_kernel<<<dim3(EMB / 128, M / 128), 256>>>(
        att, W_proj, b_proj, out, M, EMB, EMB);
}

// round 5
// speedup vs baseline: 2.7882x; 1.1055x over previous
#include <cuda_runtime.h>
#include <cstdint>

#define EMB   768
#define EMB3  2304
#define NHEAD 12
#define HDIM  64
#define SEQ   1024
#define BATCH 8

// Scratch (no cudaMalloc allowed).
__device__ float g_qkv[(size_t)BATCH * SEQ * EMB3];   // qkv (tf32-rounded)
__device__ float g_att[(size_t)BATCH * SEQ * EMB];    // attn out (tf32-rounded)
__device__ float g_xc [(size_t)BATCH * SEQ * EMB];    // x   (tf32-rounded)
__device__ float g_wac[(size_t)EMB * EMB3];           // W_attn (tf32-rounded)
__device__ float g_wpc[(size_t)EMB * EMB];            // W_proj (tf32-rounded)

// ---------------------------------------------------------------------------
__device__ __forceinline__ uint32_t f2tf32(float f) {
    uint32_t u;
    asm("cvt.rna.tf32.f32 %0, %1;" : "=r"(u) : "f"(f));
    return u;
}
__device__ __forceinline__ float rtf(float f) { return __uint_as_float(f2tf32(f)); }

__device__ __forceinline__ void cpa16(void* smem_dst, const void* gmem_src) {
    uint32_t s = (uint32_t)__cvta_generic_to_shared(smem_dst);
    asm volatile("cp.async.cg.shared.global [%0], [%1], 16;\n" :: "r"(s), "l"(gmem_src));
}
__device__ __forceinline__ void cpa_commit() { asm volatile("cp.async.commit_group;\n"); }
__device__ __forceinline__ void cpa_wait0()  { asm volatile("cp.async.wait_group 0;\n" ::: "memory"); }

__device__ __forceinline__ void mma_tf32(float& d0, float& d1, float& d2, float& d3,
                                         uint32_t a0, uint32_t a1, uint32_t a2, uint32_t a3,
                                         uint32_t b0, uint32_t b1) {
    asm volatile(
        "mma.sync.aligned.m16n8k8.row.col.f32.tf32.tf32.f32 "
        "{%0,%1,%2,%3}, {%4,%5,%6,%7}, {%8,%9}, {%0,%1,%2,%3};\n"
        : "+f"(d0), "+f"(d1), "+f"(d2), "+f"(d3)
        : "r"(a0), "r"(a1), "r"(a2), "r"(a3), "r"(b0), "r"(b1));
}

// ---------------------------------------------------------------------------
// Elementwise fp32 -> tf32-rounded pre-pass (float4 vectorized).
// ---------------------------------------------------------------------------
__global__ void cvt_tf32_kernel(const float* __restrict__ in, float* __restrict__ out, int n4)
{
    int i = blockIdx.x * blockDim.x + threadIdx.x;
    if (i < n4) {
        float4 v = ((const float4*)in)[i];
        v.x = rtf(v.x); v.y = rtf(v.y); v.z = rtf(v.z); v.w = rtf(v.w);
        ((float4*)out)[i] = v;
    }
}

// ---------------------------------------------------------------------------
// TF32 tensor-core GEMM, inputs pre-rounded to tf32 bits (NO cvt in mainloop).
// C[M,N] = A[M,K] @ B[K,N] + bias[N]; 128x128 tile, BK=16, 256 thr, m16n8k8.
// ---------------------------------------------------------------------------
#define APITCH 20
#define BPITCH 132

template<bool ROUND_OUT>
__global__ __launch_bounds__(256)
void gemm_tf32_kernel(const float* __restrict__ A, const float* __restrict__ B,
                      const float* __restrict__ bias, float* __restrict__ C,
                      int M, int N, int K)
{
    __shared__ float As[2][128 * APITCH];
    __shared__ float Bs[2][16 * BPITCH];

    const int tid    = threadIdx.x;
    const int lane   = tid & 31;
    const int warp   = tid >> 5;
    const int warp_m = warp >> 2;
    const int warp_n = warp & 3;
    const int gr     = lane >> 2;
    const int gc     = lane & 3;

    const int brow = blockIdx.y * 128;
    const int bcol = blockIdx.x * 128;

    const int a_row = tid >> 1;
    const int a_c4  = (tid & 1) * 2;
    const int b_row = tid >> 4;
    const int b_c4  = (tid & 15) * 2;

    const float* gA = A + (size_t)(brow + a_row) * K + a_c4 * 4;
    const float* gB = B + (size_t)b_row * N + bcol + b_c4 * 4;

    float acc[4][4][4];
#pragma unroll
    for (int i = 0; i < 4; i++)
#pragma unroll
        for (int j = 0; j < 4; j++)
#pragma unroll
            for (int v = 0; v < 4; v++) acc[i][j][v] = 0.f;

    const int KT = K / 16;

    {
        float* as = &As[0][a_row * APITCH + a_c4 * 4];
        cpa16(as,     gA);
        cpa16(as + 4, gA + 4);
        float* bs = &Bs[0][b_row * BPITCH + b_c4 * 4];
        cpa16(bs,     gB);
        cpa16(bs + 4, gB + 4);
        cpa_commit();
    }

    int buf = 0;
    for (int kt = 0; kt < KT; kt++) {
        cpa_wait0();
        __syncthreads();   // tile(kt) visible AND all reads of the buffer we
                           // are about to overwrite (from kt-1) are done.

        if (kt + 1 < KT) {
            const int k0 = (kt + 1) * 16;
            float* as = &As[buf ^ 1][a_row * APITCH + a_c4 * 4];
            cpa16(as,     gA + k0);
            cpa16(as + 4, gA + k0 + 4);
            float* bs = &Bs[buf ^ 1][b_row * BPITCH + b_c4 * 4];
            cpa16(bs,     gB + (size_t)k0 * N);
            cpa16(bs + 4, gB + (size_t)k0 * N + 4);
            cpa_commit();
        }

        const uint32_t* as = (const uint32_t*)As[buf];
        const uint32_t* bs = (const uint32_t*)Bs[buf];

#pragma unroll
        for (int ks = 0; ks < 2; ks++) {
            const int k8 = ks * 8;
            uint32_t af[4][4], bf[4][2];
#pragma unroll
            for (int mi = 0; mi < 4; mi++) {
                const int m0 = warp_m * 64 + mi * 16;
                af[mi][0] = as[(m0 + gr)     * APITCH + k8 + gc];
                af[mi][1] = as[(m0 + gr + 8) * APITCH + k8 + gc];
                af[mi][2] = as[(m0 + gr)     * APITCH + k8 + gc + 4];
                af[mi][3] = as[(m0 + gr + 8) * APITCH + k8 + gc + 4];
            }
#pragma unroll
            for (int ni = 0; ni < 4; ni++) {
                const int n0 = warp_n * 32 + ni * 8;
                bf[ni][0] = bs[(k8 + gc)     * BPITCH + n0 + gr];
                bf[ni][1] = bs[(k8 + gc + 4) * BPITCH + n0 + gr];
            }
#pragma unroll
            for (int mi = 0; mi < 4; mi++)
#pragma unroll
                for (int ni = 0; ni < 4; ni++)
                    mma_tf32(acc[mi][ni][0], acc[mi][ni][1],
                             acc[mi][ni][2], acc[mi][ni][3],
                             af[mi][0], af[mi][1], af[mi][2], af[mi][3],
                             bf[ni][0], bf[ni][1]);
        }
        buf ^= 1;
    }

#pragma unroll
    for (int ni = 0; ni < 4; ni++) {
        const int col = bcol + warp_n * 32 + ni * 8 + 2 * gc;
        const float bv0 = bias[col];
        const float bv1 = bias[col + 1];
#pragma unroll
        for (int mi = 0; mi < 4; mi++) {
            const int row = brow + warp_m * 64 + mi * 16 + gr;
            float2 o0, o1;
            if (ROUND_OUT) {
                o0 = make_float2(rtf(acc[mi][ni][0] + bv0), rtf(acc[mi][ni][1] + bv1));
                o1 = make_float2(rtf(acc[mi][ni][2] + bv0), rtf(acc[mi][ni][3] + bv1));
            } else {
                o0 = make_float2(acc[mi][ni][0] + bv0, acc[mi][ni][1] + bv1);
                o1 = make_float2(acc[mi][ni][2] + bv0, acc[mi][ni][3] + bv1);
            }
            *(float2*)&C[(size_t)row * N + col]       = o0;
            *(float2*)&C[(size_t)(row + 8) * N + col] = o1;
        }
    }
}

// ---------------------------------------------------------------------------
// Tensor-core flash attention (causal, tf32 mma, fp32 accum).
// Block = 256 threads (8 warps), 128-query tile; warp w owns rows [16w,16w+16).
// ALL causal comparisons in the GLOBAL frame: grow = qbase + local row,
// key = kt*64 + local col.   Dynamic smem (104 KB) with opt-in.
// ---------------------------------------------------------------------------
#define QPP 68
#define KPP 68
#define VPP 72
#define ATTN_SMEM ((128 * QPP + 2 * 64 * KPP + 2 * 64 * VPP) * 4)

__global__ __launch_bounds__(256, 2)
void attn_mma_kernel(const float* __restrict__ qkv, float* __restrict__ out)
{
    extern __shared__ float sm[];
    float* QP = sm;                       // 128 x QPP : Q tile, later P strips
    float* Ks0 = QP + 128 * QPP;          // 2 x 64 x KPP
    float* Vs0 = Ks0 + 2 * 64 * KPP;      // 2 x 64 x VPP

    const int tid  = threadIdx.x;
    const int lane = tid & 31;
    const int warp = tid >> 5;          // 0..7
    const int gr   = lane >> 2;
    const int gc   = lane & 3;

    const int bh = blockIdx.y;
    const int b  = bh / NHEAD;
    const int h  = bh % NHEAD;
    const int qt = 7 - blockIdx.x;      // heavy tiles first
    const int qbase = qt * 128;
    const int ktmax = 2 * qt + 1;       // last k-tile index (keys < qbase+128)

    // Q tile load (128 rows): 2 threads per row
    {
        const int r  = tid >> 1;
        const int c0 = (tid & 1) * 32;
        const float* src = qkv + (size_t)(b * SEQ + qbase + r) * EMB3 + h * HDIM + c0;
        float* dst = &QP[r * QPP + c0];
#pragma unroll
        for (int i = 0; i < 8; i++)
            cpa16(dst + 4 * i, src + 4 * i);
    }
    // K/V tile 0 (64 rows): 4 threads per row
    {
        const int r  = tid >> 2;
        const int c0 = (tid & 3) * 16;
        const float* kp = qkv + (size_t)(b * SEQ + r) * EMB3 + EMB + h * HDIM + c0;
        float* ks = &Ks0[r * KPP + c0];
        float* vs = &Vs0[r * VPP + c0];
#pragma unroll
        for (int i = 0; i < 4; i++) {
            cpa16(ks + 4 * i, kp + 4 * i);
            cpa16(vs + 4 * i, kp + EMB + 4 * i);
        }
    }
    cpa_commit();
    cpa_wait0();
    __syncthreads();

    // Q fragments (raw tf32 bits), held in registers for the whole loop
    uint32_t qf[8][4];
    {
        const uint32_t* qp = (const uint32_t*)QP;
        const int m0 = warp * 16;
#pragma unroll
        for (int ks = 0; ks < 8; ks++) {
            const int k8 = ks * 8;
            qf[ks][0] = qp[(m0 + gr)     * QPP + k8 + gc];
            qf[ks][1] = qp[(m0 + gr + 8) * QPP + k8 + gc];
            qf[ks][2] = qp[(m0 + gr)     * QPP + k8 + gc + 4];
            qf[ks][3] = qp[(m0 + gr + 8) * QPP + k8 + gc + 4];
        }
    }

    float o[8][4];
#pragma unroll
    for (int i = 0; i < 8; i++)
#pragma unroll
        for (int j = 0; j < 4; j++) o[i][j] = 0.f;
    float mr0 = -1e30f, mr1 = -1e30f, l0 = 0.f, l1 = 0.f;

    const int lrow0 = warp * 16 + gr;       // block-local query row of this lane
    const int grow0 = qbase + lrow0;        // GLOBAL query row
    const int prow0 = lrow0 * QPP;
    const int prow1 = (lrow0 + 8) * QPP;

    int buf = 0;
    for (int kt = 0; kt <= ktmax; kt++) {
        const int kbase = kt * 64;          // GLOBAL key base
        cpa_wait0();
        __syncthreads();

        if (kt < ktmax) {
            const int r  = tid >> 2;
            const int c0 = (tid & 3) * 16;
            const float* kp = qkv + (size_t)(b * SEQ + (kt + 1) * 64 + r) * EMB3
                              + EMB + h * HDIM + c0;
            float* ks = &Ks0[(buf ^ 1) * 64 * KPP + r * KPP + c0];
            float* vs = &Vs0[(buf ^ 1) * 64 * VPP + r * VPP + c0];
#pragma unroll
            for (int i = 0; i < 4; i++) {
                cpa16(ks + 4 * i, kp + 4 * i);
                cpa16(vs + 4 * i, kp + EMB + 4 * i);
            }
            cpa_commit();
        }

        // Entire warp strip masked for this tile? (GLOBAL frame)
        if (kbase > qbase + warp * 16 + 15) { buf ^= 1; continue; }

        // ---- S = Q @ K^T  (16 x 64 per warp) ----
        float s[8][4];
#pragma unroll
        for (int i = 0; i < 8; i++)
#pragma unroll
            for (int j = 0; j < 4; j++) s[i][j] = 0.f;

        const uint32_t* ksm = (const uint32_t*)(Ks0 + buf * 64 * KPP);
#pragma unroll
        for (int ks = 0; ks < 8; ks++) {
            const int k8 = ks * 8;
            uint32_t bf[8][2];
#pragma unroll
            for (int nt = 0; nt < 8; nt++) {
                bf[nt][0] = ksm[(nt * 8 + gr) * KPP + k8 + gc];
                bf[nt][1] = ksm[(nt * 8 + gr) * KPP + k8 + gc + 4];
            }
#pragma unroll
            for (int nt = 0; nt < 8; nt++)
                mma_tf32(s[nt][0], s[nt][1], s[nt][2], s[nt][3],
                         qf[ks][0], qf[ks][1], qf[ks][2], qf[ks][3],
                         bf[nt][0], bf[nt][1]);
        }

        // ---- scale + causal mask (GLOBAL frame) ----
        if (kbase + 63 > grow0) {
            const int lr0 = grow0;
            const int lr1 = grow0 + 8;
#pragma unroll
            for (int nt = 0; nt < 8; nt++) {
                const int c0 = kbase + nt * 8 + 2 * gc;   // global key index
                s[nt][0] = (c0     > lr0) ? -1e30f : s[nt][0] * 0.125f;
                s[nt][1] = (c0 + 1 > lr0) ? -1e30f : s[nt][1] * 0.125f;
                s[nt][2] = (c0     > lr1) ? -1e30f : s[nt][2] * 0.125f;
                s[nt][3] = (c0 + 1 > lr1) ? -1e30f : s[nt][3] * 0.125f;
            }
        } else {
#pragma unroll
            for (int nt = 0; nt < 8; nt++) {
                s[nt][0] *= 0.125f; s[nt][1] *= 0.125f;
                s[nt][2] *= 0.125f; s[nt][3] *= 0.125f;
            }
        }

        // ---- online softmax (register, quad shuffles) ----
        float mx0 = -1e30f, mx1 = -1e30f;
#pragma unroll
        for (int nt = 0; nt < 8; nt++) {
            mx0 = fmaxf(mx0, fmaxf(s[nt][0], s[nt][1]));
            mx1 = fmaxf(mx1, fmaxf(s[nt][2], s[nt][3]));
        }
        mx0 = fmaxf(mx0, __shfl_xor_sync(0xffffffffu, mx0, 1));
        mx0 = fmaxf(mx0, __shfl_xor_sync(0xffffffffu, mx0, 2));
        mx1 = fmaxf(mx1, __shfl_xor_sync(0xffffffffu, mx1, 1));
        mx1 = fmaxf(mx1, __shfl_xor_sync(0xffffffffu, mx1, 2));

        const float mn0 = fmaxf(mr0, mx0);
        const float mn1 = fmaxf(mr1, mx1);
        const float a0  = __expf(mr0 - mn0);
        const float a1  = __expf(mr1 - mn1);
        mr0 = mn0; mr1 = mn1;

        float sum0 = 0.f, sum1 = 0.f;
#pragma unroll
        for (int nt = 0; nt < 8; nt++) {
            s[nt][0] = __expf(s[nt][0] - mn0);
            s[nt][1] = __expf(s[nt][1] - mn0);
            s[nt][2] = __expf(s[nt][2] - mn1);
            s[nt][3] = __expf(s[nt][3] - mn1);
            sum0 += s[nt][0] + s[nt][1];
            sum1 += s[nt][2] + s[nt][3];
        }
        sum0 += __shfl_xor_sync(0xffffffffu, sum0, 1);
        sum0 += __shfl_xor_sync(0xffffffffu, sum0, 2);
        sum1 += __shfl_xor_sync(0xffffffffu, sum1, 1);
        sum1 += __shfl_xor_sync(0xffffffffu, sum1, 2);
        l0 = l0 * a0 + sum0;
        l1 = l1 * a1 + sum1;

#pragma unroll
        for (int nt = 0; nt < 8; nt++) {
            o[nt][0] *= a0; o[nt][1] *= a0;
            o[nt][2] *= a1; o[nt][3] *= a1;
        }

        // ---- P -> warp-local smem strip (tf32 bits), re-read as A frags ----
        uint32_t* qpw = (uint32_t*)QP;
#pragma unroll
        for (int nt = 0; nt < 8; nt++) {
            uint2 p01 = make_uint2(f2tf32(s[nt][0]), f2tf32(s[nt][1]));
            uint2 p23 = make_uint2(f2tf32(s[nt][2]), f2tf32(s[nt][3]));
            *(uint2*)&qpw[prow0 + nt * 8 + 2 * gc] = p01;
            *(uint2*)&qpw[prow1 + nt * 8 + 2 * gc] = p23;
        }
        __syncwarp();

        // ---- O += P @ V ----
        const uint32_t* pp  = (const uint32_t*)QP;
        const uint32_t* vsm = (const uint32_t*)(Vs0 + buf * 64 * VPP);
#pragma unroll
        for (int ks = 0; ks < 8; ks++) {
            const int k8 = ks * 8;
            uint32_t af[4];
            af[0] = pp[prow0 + k8 + gc];
            af[1] = pp[prow1 + k8 + gc];
            af[2] = pp[prow0 + k8 + gc + 4];
            af[3] = pp[prow1 + k8 + gc + 4];
            uint32_t bf[8][2];
#pragma unroll
            for (int nt = 0; nt < 8; nt++) {
                bf[nt][0] = vsm[(k8 + gc)     * VPP + nt * 8 + gr];
                bf[nt][1] = vsm[(k8 + gc + 4) * VPP + nt * 8 + gr];
            }
#pragma unroll
            for (int nt = 0; nt < 8; nt++)
                mma_tf32(o[nt][0], o[nt][1], o[nt][2], o[nt][3],
                         af[0], af[1], af[2], af[3],
                         bf[nt][0], bf[nt][1]);
        }
        __syncwarp();
        buf ^= 1;
    }

    // ---- epilogue: normalize, round to tf32, write head-concat [B,T,C] ----
    const float inv0 = 1.f / l0;
    const float inv1 = 1.f / l1;
    const int r0g = b * SEQ + grow0;
#pragma unroll
    for (int nt = 0; nt < 8; nt++) {
        const int col = h * HDIM + nt * 8 + 2 * gc;
        float2 o0 = make_float2(rtf(o[nt][0] * inv0), rtf(o[nt][1] * inv0));
        float2 o1 = make_float2(rtf(o[nt][2] * inv1), rtf(o[nt][3] * inv1));
        *(float2*)&out[(size_t)r0g * EMB + col]       = o0;
        *(float2*)&out[(size_t)(r0g + 8) * EMB + col] = o1;
    }
}

// ---------------------------------------------------------------------------
extern "C" void kernel_launch(void* const* d_in, const int* in_sizes, int n_in,
                              void* d_out, int out_size)
{
    const float* x      = (const float*)d_in[0];
    const float* W_attn = (const float*)d_in[1];
    const float* b_attn = (const float*)d_in[2];
    const float* W_proj = (const float*)d_in[3];
    const float* b_proj = (const float*)d_in[4];
    float* out = (float*)d_out;

    float *qkv, *att, *xc, *wac, *wpc;
    cudaGetSymbolAddress((void**)&qkv, g_qkv);
    cudaGetSymbolAddress((void**)&att, g_att);
    cudaGetSymbolAddress((void**)&xc,  g_xc);
    cudaGetSymbolAddress((void**)&wac, g_wac);
    cudaGetSymbolAddress((void**)&wpc, g_wpc);

    cudaFuncSetAttribute(attn_mma_kernel,
                         cudaFuncAttributeMaxDynamicSharedMemorySize, ATTN_SMEM);

    const int M = BATCH * SEQ;  // 8192

    // 0) pre-round inputs to tf32
    cvt_tf32_kernel<<<(M * EMB / 4 + 255) / 256, 256>>>(x, xc, M * EMB / 4);
    cvt_tf32_kernel<<<(EMB * EMB3 / 4 + 255) / 256, 256>>>(W_attn, wac, EMB * EMB3 / 4);
    cvt_tf32_kernel<<<(EMB * EMB / 4 + 255) / 256, 256>>>(W_proj, wpc, EMB * EMB / 4);

    // 1) QKV = x @ W_attn + b_attn  (output tf32-rounded)
    gemm_tf32_kernel<true><<<dim3(EMB3 / 128, M / 128), 256>>>(
        xc, wac, b_attn, qkv, M, EMB3, EMB);

    // 2) causal MHA (output tf32-rounded)
    attn_mma_kernel<<<dim3(SEQ / 128, BATCH * NHEAD), 256, ATTN_SMEM>>>(qkv, att);

    // 3) out = att @ W_proj + b_proj  (full fp32 output)
    gemm_tf32_kernel<false><<<dim3(EMB / 128, M / 128), 256>>>(
        att, wpc, b_proj, out, M, EMB, EMB);
}

// round 6
// speedup vs baseline: 2.7999x; 1.0042x over previous
#include <cuda_runtime.h>
#include <cstdint>

#define EMB   768
#define EMB3  2304
#define NHEAD 12
#define HDIM  64
#define SEQ   1024
#define BATCH 8

// Scratch (no cudaMalloc allowed).
__device__ float g_qkv[(size_t)BATCH * SEQ * EMB3];   // qkv (tf32-rounded)
__device__ float g_att[(size_t)BATCH * SEQ * EMB];    // attn out (tf32-rounded)
__device__ float g_xc [(size_t)BATCH * SEQ * EMB];    // x   (tf32-rounded)
__device__ float g_wac[(size_t)EMB * EMB3];           // W_attn (tf32-rounded)
__device__ float g_wpc[(size_t)EMB * EMB];            // W_proj (tf32-rounded)

// ---------------------------------------------------------------------------
__device__ __forceinline__ uint32_t f2tf32(float f) {
    uint32_t u;
    asm("cvt.rna.tf32.f32 %0, %1;" : "=r"(u) : "f"(f));
    return u;
}
__device__ __forceinline__ float rtf(float f) { return __uint_as_float(f2tf32(f)); }

__device__ __forceinline__ void cpa16(void* smem_dst, const void* gmem_src) {
    uint32_t s = (uint32_t)__cvta_generic_to_shared(smem_dst);
    asm volatile("cp.async.cg.shared.global [%0], [%1], 16;\n" :: "r"(s), "l"(gmem_src));
}
__device__ __forceinline__ void cpa_commit() { asm volatile("cp.async.commit_group;\n"); }
template<int N>
__device__ __forceinline__ void cpa_wait()  { asm volatile("cp.async.wait_group %0;\n" :: "n"(N) : "memory"); }

__device__ __forceinline__ void mma_tf32(float& d0, float& d1, float& d2, float& d3,
                                         uint32_t a0, uint32_t a1, uint32_t a2, uint32_t a3,
                                         uint32_t b0, uint32_t b1) {
    asm volatile(
        "mma.sync.aligned.m16n8k8.row.col.f32.tf32.tf32.f32 "
        "{%0,%1,%2,%3}, {%4,%5,%6,%7}, {%8,%9}, {%0,%1,%2,%3};\n"
        : "+f"(d0), "+f"(d1), "+f"(d2), "+f"(d3)
        : "r"(a0), "r"(a1), "r"(a2), "r"(a3), "r"(b0), "r"(b1));
}

// ---------------------------------------------------------------------------
// Elementwise fp32 -> tf32-rounded pre-pass (float4 vectorized).
// ---------------------------------------------------------------------------
__global__ void cvt_tf32_kernel(const float* __restrict__ in, float* __restrict__ out, int n4)
{
    int i = blockIdx.x * blockDim.x + threadIdx.x;
    if (i < n4) {
        float4 v = ((const float4*)in)[i];
        v.x = rtf(v.x); v.y = rtf(v.y); v.z = rtf(v.z); v.w = rtf(v.w);
        ((float4*)out)[i] = v;
    }
}

// ---------------------------------------------------------------------------
// TF32 tensor-core GEMM, 4-stage cp.async pipeline (wait_group 2).
// C[M,N] = A[M,K] @ B[K,N] + bias[N]; 128x128 tile, BK=16, 256 thr, m16n8k8.
// Inputs pre-rounded to tf32 -> raw fragment loads.  Dynamic smem 74.8 KB.
// ---------------------------------------------------------------------------
#define APITCH 20
#define BPITCH 132
#define GSTAGE (128 * APITCH + 16 * BPITCH)          // floats per stage (4672)
#define GEMM_SMEM (4 * GSTAGE * 4)                   // bytes (74752)

template<bool ROUND_OUT>
__global__ __launch_bounds__(256)
void gemm_tf32_kernel(const float* __restrict__ A, const float* __restrict__ B,
                      const float* __restrict__ bias, float* __restrict__ C,
                      int M, int N, int K)
{
    extern __shared__ float gsm[];

    const int tid    = threadIdx.x;
    const int lane   = tid & 31;
    const int warp   = tid >> 5;
    const int warp_m = warp >> 2;
    const int warp_n = warp & 3;
    const int gr     = lane >> 2;
    const int gc     = lane & 3;

    const int brow = blockIdx.y * 128;
    const int bcol = blockIdx.x * 128;

    const int a_row = tid >> 1;
    const int a_c4  = (tid & 1) * 2;
    const int b_row = tid >> 4;
    const int b_c4  = (tid & 15) * 2;

    const float* gA = A + (size_t)(brow + a_row) * K + a_c4 * 4;
    const float* gB = B + (size_t)b_row * N + bcol + b_c4 * 4;

    const int a_off = a_row * APITCH + a_c4 * 4;             // within A part
    const int b_off = 128 * APITCH + b_row * BPITCH + b_c4 * 4;  // B part

    float acc[4][4][4];
#pragma unroll
    for (int i = 0; i < 4; i++)
#pragma unroll
        for (int j = 0; j < 4; j++)
#pragma unroll
            for (int v = 0; v < 4; v++) acc[i][j][v] = 0.f;

    const int KT = K / 16;

    // Prologue: stages 0..2 <- tiles 0..2
#pragma unroll
    for (int s = 0; s < 3; s++) {
        const int k0 = s * 16;
        float* st = gsm + s * GSTAGE;
        cpa16(st + a_off,     gA + k0);
        cpa16(st + a_off + 4, gA + k0 + 4);
        cpa16(st + b_off,     gB + (size_t)k0 * N);
        cpa16(st + b_off + 4, gB + (size_t)k0 * N + 4);
        cpa_commit();
    }

    for (int kt = 0; kt < KT; kt++) {
        cpa_wait<2>();       // tile kt resident (3+kt commits issued, keep <=2 younger)
        __syncthreads();     // stage (kt+3)&3 readers from iter kt-1 are done

        // Prefetch tile kt+3 (empty commit group keeps accounting aligned)
        if (kt + 3 < KT) {
            const int k0 = (kt + 3) * 16;
            float* st = gsm + ((kt + 3) & 3) * GSTAGE;
            cpa16(st + a_off,     gA + k0);
            cpa16(st + a_off + 4, gA + k0 + 4);
            cpa16(st + b_off,     gB + (size_t)k0 * N);
            cpa16(st + b_off + 4, gB + (size_t)k0 * N + 4);
        }
        cpa_commit();

        const uint32_t* as = (const uint32_t*)(gsm + (kt & 3) * GSTAGE);
        const uint32_t* bs = as + 128 * APITCH;

#pragma unroll
        for (int ks = 0; ks < 2; ks++) {
            const int k8 = ks * 8;
            uint32_t af[4][4], bf[4][2];
#pragma unroll
            for (int mi = 0; mi < 4; mi++) {
                const int m0 = warp_m * 64 + mi * 16;
                af[mi][0] = as[(m0 + gr)     * APITCH + k8 + gc];
                af[mi][1] = as[(m0 + gr + 8) * APITCH + k8 + gc];
                af[mi][2] = as[(m0 + gr)     * APITCH + k8 + gc + 4];
                af[mi][3] = as[(m0 + gr + 8) * APITCH + k8 + gc + 4];
            }
#pragma unroll
            for (int ni = 0; ni < 4; ni++) {
                const int n0 = warp_n * 32 + ni * 8;
                bf[ni][0] = bs[(k8 + gc)     * BPITCH + n0 + gr];
                bf[ni][1] = bs[(k8 + gc + 4) * BPITCH + n0 + gr];
            }
#pragma unroll
            for (int mi = 0; mi < 4; mi++)
#pragma unroll
                for (int ni = 0; ni < 4; ni++)
                    mma_tf32(acc[mi][ni][0], acc[mi][ni][1],
                             acc[mi][ni][2], acc[mi][ni][3],
                             af[mi][0], af[mi][1], af[mi][2], af[mi][3],
                             bf[ni][0], bf[ni][1]);
        }
    }

#pragma unroll
    for (int ni = 0; ni < 4; ni++) {
        const int col = bcol + warp_n * 32 + ni * 8 + 2 * gc;
        const float bv0 = bias[col];
        const float bv1 = bias[col + 1];
#pragma unroll
        for (int mi = 0; mi < 4; mi++) {
            const int row = brow + warp_m * 64 + mi * 16 + gr;
            float2 o0, o1;
            if (ROUND_OUT) {
                o0 = make_float2(rtf(acc[mi][ni][0] + bv0), rtf(acc[mi][ni][1] + bv1));
                o1 = make_float2(rtf(acc[mi][ni][2] + bv0), rtf(acc[mi][ni][3] + bv1));
            } else {
                o0 = make_float2(acc[mi][ni][0] + bv0, acc[mi][ni][1] + bv1);
                o1 = make_float2(acc[mi][ni][2] + bv0, acc[mi][ni][3] + bv1);
            }
            *(float2*)&C[(size_t)row * N + col]       = o0;
            *(float2*)&C[(size_t)(row + 8) * N + col] = o1;
        }
    }
}

// ---------------------------------------------------------------------------
// Tensor-core flash attention (causal, tf32 mma, fp32 accum) — unchanged
// from round 5 (passing, rel_err 6.4e-4).
// ---------------------------------------------------------------------------
#define QPP 68
#define KPP 68
#define VPP 72
#define ATTN_SMEM ((128 * QPP + 2 * 64 * KPP + 2 * 64 * VPP) * 4)

__global__ __launch_bounds__(256, 2)
void attn_mma_kernel(const float* __restrict__ qkv, float* __restrict__ out)
{
    extern __shared__ float sm[];
    float* QP = sm;
    float* Ks0 = QP + 128 * QPP;
    float* Vs0 = Ks0 + 2 * 64 * KPP;

    const int tid  = threadIdx.x;
    const int lane = tid & 31;
    const int warp = tid >> 5;
    const int gr   = lane >> 2;
    const int gc   = lane & 3;

    const int bh = blockIdx.y;
    const int b  = bh / NHEAD;
    const int h  = bh % NHEAD;
    const int qt = 7 - blockIdx.x;
    const int qbase = qt * 128;
    const int ktmax = 2 * qt + 1;

    {
        const int r  = tid >> 1;
        const int c0 = (tid & 1) * 32;
        const float* src = qkv + (size_t)(b * SEQ + qbase + r) * EMB3 + h * HDIM + c0;
        float* dst = &QP[r * QPP + c0];
#pragma unroll
        for (int i = 0; i < 8; i++)
            cpa16(dst + 4 * i, src + 4 * i);
    }
    {
        const int r  = tid >> 2;
        const int c0 = (tid & 3) * 16;
        const float* kp = qkv + (size_t)(b * SEQ + r) * EMB3 + EMB + h * HDIM + c0;
        float* ks = &Ks0[r * KPP + c0];
        float* vs = &Vs0[r * VPP + c0];
#pragma unroll
        for (int i = 0; i < 4; i++) {
            cpa16(ks + 4 * i, kp + 4 * i);
            cpa16(vs + 4 * i, kp + EMB + 4 * i);
        }
    }
    cpa_commit();
    cpa_wait<0>();
    __syncthreads();

    uint32_t qf[8][4];
    {
        const uint32_t* qp = (const uint32_t*)QP;
        const int m0 = warp * 16;
#pragma unroll
        for (int ks = 0; ks < 8; ks++) {
            const int k8 = ks * 8;
            qf[ks][0] = qp[(m0 + gr)     * QPP + k8 + gc];
            qf[ks][1] = qp[(m0 + gr + 8) * QPP + k8 + gc];
            qf[ks][2] = qp[(m0 + gr)     * QPP + k8 + gc + 4];
            qf[ks][3] = qp[(m0 + gr + 8) * QPP + k8 + gc + 4];
        }
    }

    float o[8][4];
#pragma unroll
    for (int i = 0; i < 8; i++)
#pragma unroll
        for (int j = 0; j < 4; j++) o[i][j] = 0.f;
    float mr0 = -1e30f, mr1 = -1e30f, l0 = 0.f, l1 = 0.f;

    const int lrow0 = warp * 16 + gr;
    const int grow0 = qbase + lrow0;
    const int prow0 = lrow0 * QPP;
    const int prow1 = (lrow0 + 8) * QPP;

    int buf = 0;
    for (int kt = 0; kt <= ktmax; kt++) {
        const int kbase = kt * 64;
        cpa_wait<0>();
        __syncthreads();

        if (kt < ktmax) {
            const int r  = tid >> 2;
            const int c0 = (tid & 3) * 16;
            const float* kp = qkv + (size_t)(b * SEQ + (kt + 1) * 64 + r) * EMB3
                              + EMB + h * HDIM + c0;
            float* ks = &Ks0[(buf ^ 1) * 64 * KPP + r * KPP + c0];
            float* vs = &Vs0[(buf ^ 1) * 64 * VPP + r * VPP + c0];
#pragma unroll
            for (int i = 0; i < 4; i++) {
                cpa16(ks + 4 * i, kp + 4 * i);
                cpa16(vs + 4 * i, kp + EMB + 4 * i);
            }
            cpa_commit();
        }

        if (kbase > qbase + warp * 16 + 15) { buf ^= 1; continue; }

        float s[8][4];
#pragma unroll
        for (int i = 0; i < 8; i++)
#pragma unroll
            for (int j = 0; j < 4; j++) s[i][j] = 0.f;

        const uint32_t* ksm = (const uint32_t*)(Ks0 + buf * 64 * KPP);
#pragma unroll
        for (int ks = 0; ks < 8; ks++) {
            const int k8 = ks * 8;
            uint32_t bf[8][2];
#pragma unroll
            for (int nt = 0; nt < 8; nt++) {
                bf[nt][0] = ksm[(nt * 8 + gr) * KPP + k8 + gc];
                bf[nt][1] = ksm[(nt * 8 + gr) * KPP + k8 + gc + 4];
            }
#pragma unroll
            for (int nt = 0; nt < 8; nt++)
                mma_tf32(s[nt][0], s[nt][1], s[nt][2], s[nt][3],
                         qf[ks][0], qf[ks][1], qf[ks][2], qf[ks][3],
                         bf[nt][0], bf[nt][1]);
        }

        if (kbase + 63 > grow0) {
            const int lr0 = grow0;
            const int lr1 = grow0 + 8;
#pragma unroll
            for (int nt = 0; nt < 8; nt++) {
                const int c0 = kbase + nt * 8 + 2 * gc;
                s[nt][0] = (c0     > lr0) ? -1e30f : s[nt][0] * 0.125f;
                s[nt][1] = (c0 + 1 > lr0) ? -1e30f : s[nt][1] * 0.125f;
                s[nt][2] = (c0     > lr1) ? -1e30f : s[nt][2] * 0.125f;
                s[nt][3] = (c0 + 1 > lr1) ? -1e30f : s[nt][3] * 0.125f;
            }
        } else {
#pragma unroll
            for (int nt = 0; nt < 8; nt++) {
                s[nt][0] *= 0.125f; s[nt][1] *= 0.125f;
                s[nt][2] *= 0.125f; s[nt][3] *= 0.125f;
            }
        }

        float mx0 = -1e30f, mx1 = -1e30f;
#pragma unroll
        for (int nt = 0; nt < 8; nt++) {
            mx0 = fmaxf(mx0, fmaxf(s[nt][0], s[nt][1]));
            mx1 = fmaxf(mx1, fmaxf(s[nt][2], s[nt][3]));
        }
        mx0 = fmaxf(mx0, __shfl_xor_sync(0xffffffffu, mx0, 1));
        mx0 = fmaxf(mx0, __shfl_xor_sync(0xffffffffu, mx0, 2));
        mx1 = fmaxf(mx1, __shfl_xor_sync(0xffffffffu, mx1, 1));
        mx1 = fmaxf(mx1, __shfl_xor_sync(0xffffffffu, mx1, 2));

        const float mn0 = fmaxf(mr0, mx0);
        const float mn1 = fmaxf(mr1, mx1);
        const float a0  = __expf(mr0 - mn0);
        const float a1  = __expf(mr1 - mn1);
        mr0 = mn0; mr1 = mn1;

        float sum0 = 0.f, sum1 = 0.f;
#pragma unroll
        for (int nt = 0; nt < 8; nt++) {
            s[nt][0] = __expf(s[nt][0] - mn0);
            s[nt][1] = __expf(s[nt][1] - mn0);
            s[nt][2] = __expf(s[nt][2] - mn1);
            s[nt][3] = __expf(s[nt][3] - mn1);
            sum0 += s[nt][0] + s[nt][1];
            sum1 += s[nt][2] + s[nt][3];
        }
        sum0 += __shfl_xor_sync(0xffffffffu, sum0, 1);
        sum0 += __shfl_xor_sync(0xffffffffu, sum0, 2);
        sum1 += __shfl_xor_sync(0xffffffffu, sum1, 1);
        sum1 += __shfl_xor_sync(0xffffffffu, sum1, 2);
        l0 = l0 * a0 + sum0;
        l1 = l1 * a1 + sum1;

#pragma unroll
        for (int nt = 0; nt < 8; nt++) {
            o[nt][0] *= a0; o[nt][1] *= a0;
            o[nt][2] *= a1; o[nt][3] *= a1;
        }

        uint32_t* qpw = (uint32_t*)QP;
#pragma unroll
        for (int nt = 0; nt < 8; nt++) {
            uint2 p01 = make_uint2(f2tf32(s[nt][0]), f2tf32(s[nt][1]));
            uint2 p23 = make_uint2(f2tf32(s[nt][2]), f2tf32(s[nt][3]));
            *(uint2*)&qpw[prow0 + nt * 8 + 2 * gc] = p01;
            *(uint2*)&qpw[prow1 + nt * 8 + 2 * gc] = p23;
        }
        __syncwarp();

        const uint32_t* pp  = (const uint32_t*)QP;
        const uint32_t* vsm = (const uint32_t*)(Vs0 + buf * 64 * VPP);
#pragma unroll
        for (int ks = 0; ks < 8; ks++) {
            const int k8 = ks * 8;
            uint32_t af[4];
            af[0] = pp[prow0 + k8 + gc];
            af[1] = pp[prow1 + k8 + gc];
            af[2] = pp[prow0 + k8 + gc + 4];
            af[3] = pp[prow1 + k8 + gc + 4];
            uint32_t bf[8][2];
#pragma unroll
            for (int nt = 0; nt < 8; nt++) {
                bf[nt][0] = vsm[(k8 + gc)     * VPP + nt * 8 + gr];
                bf[nt][1] = vsm[(k8 + gc + 4) * VPP + nt * 8 + gr];
            }
#pragma unroll
            for (int nt = 0; nt < 8; nt++)
                mma_tf32(o[nt][0], o[nt][1], o[nt][2], o[nt][3],
                         af[0], af[1], af[2], af[3],
                         bf[nt][0], bf[nt][1]);
        }
        __syncwarp();
        buf ^= 1;
    }

    const float inv0 = 1.f / l0;
    const float inv1 = 1.f / l1;
    const int r0g = b * SEQ + grow0;
#pragma unroll
    for (int nt = 0; nt < 8; nt++) {
        const int col = h * HDIM + nt * 8 + 2 * gc;
        float2 o0 = make_float2(rtf(o[nt][0] * inv0), rtf(o[nt][1] * inv0));
        float2 o1 = make_float2(rtf(o[nt][2] * inv1), rtf(o[nt][3] * inv1));
        *(float2*)&out[(size_t)r0g * EMB + col]       = o0;
        *(float2*)&out[(size_t)(r0g + 8) * EMB + col] = o1;
    }
}

// ---------------------------------------------------------------------------
extern "C" void kernel_launch(void* const* d_in, const int* in_sizes, int n_in,
                              void* d_out, int out_size)
{
    const float* x      = (const float*)d_in[0];
    const float* W_attn = (const float*)d_in[1];
    const float* b_attn = (const float*)d_in[2];
    const float* W_proj = (const float*)d_in[3];
    const float* b_proj = (const float*)d_in[4];
    float* out = (float*)d_out;

    float *qkv, *att, *xc, *wac, *wpc;
    cudaGetSymbolAddress((void**)&qkv, g_qkv);
    cudaGetSymbolAddress((void**)&att, g_att);
    cudaGetSymbolAddress((void**)&xc,  g_xc);
    cudaGetSymbolAddress((void**)&wac, g_wac);
    cudaGetSymbolAddress((void**)&wpc, g_wpc);

    cudaFuncSetAttribute(attn_mma_kernel,
                         cudaFuncAttributeMaxDynamicSharedMemorySize, ATTN_SMEM);
    cudaFuncSetAttribute(gemm_tf32_kernel<true>,
                         cudaFuncAttributeMaxDynamicSharedMemorySize, GEMM_SMEM);
    cudaFuncSetAttribute(gemm_tf32_kernel<false>,
                         cudaFuncAttributeMaxDynamicSharedMemorySize, GEMM_SMEM);

    const int M = BATCH * SEQ;  // 8192

    // 0) pre-round inputs to tf32
    cvt_tf32_kernel<<<(M * EMB / 4 + 255) / 256, 256>>>(x, xc, M * EMB / 4);
    cvt_tf32_kernel<<<(EMB * EMB3 / 4 + 255) / 256, 256>>>(W_attn, wac, EMB * EMB3 / 4);
    cvt_tf32_kernel<<<(EMB * EMB / 4 + 255) / 256, 256>>>(W_proj, wpc, EMB * EMB / 4);

    // 1) QKV = x @ W_attn + b_attn  (output tf32-rounded)
    gemm_tf32_kernel<true><<<dim3(EMB3 / 128, M / 128), 256, GEMM_SMEM>>>(
        xc, wac, b_attn, qkv, M, EMB3, EMB);

    // 2) causal MHA (output tf32-rounded)
    attn_mma_kernel<<<dim3(SEQ / 128, BATCH * NHEAD), 256, ATTN_SMEM>>>(qkv, att);

    // 3) out = att @ W_proj + b_proj  (full fp32 output)
    gemm_tf32_kernel<false><<<dim3(EMB / 128, M / 128), 256, GEMM_SMEM>>>(
        att, wpc, b_proj, out, M, EMB, EMB);
}

// round 9
// speedup vs baseline: 3.9891x; 1.4247x over previous
#include <cuda_runtime.h>
#include <cuda_fp16.h>
#include <cstdint>

#define EMB   768
#define EMB3  2304
#define NHEAD 12
#define HDIM  64
#define SEQ   1024
#define BATCH 8
#define MROWS (BATCH * SEQ)   // 8192

// ---------------------------------------------------------------------------
// Scratch (no cudaMalloc allowed).
// ---------------------------------------------------------------------------
__device__ float g_qkv[(size_t)MROWS * EMB3];                        // GEMM1 out (tf32-rounded)
__device__ __align__(256) __half g_x16 [(size_t)MROWS * EMB];       // x fp16
__device__ __align__(256) __half g_wat16[(size_t)EMB3 * EMB];       // W_attn^T [N,K] fp16
__device__ __align__(256) __half g_wpt16[(size_t)EMB * EMB];        // W_proj^T [N,K] fp16
__device__ __align__(256) __half g_at16[(size_t)MROWS * EMB];       // attn out fp16

// ---------------------------------------------------------------------------
// Helpers
// ---------------------------------------------------------------------------
__device__ __forceinline__ uint32_t f2tf32(float f) {
    uint32_t u; asm("cvt.rna.tf32.f32 %0, %1;" : "=r"(u) : "f"(f)); return u;
}
__device__ __forceinline__ float rtf(float f) { return __uint_as_float(f2tf32(f)); }

__device__ __forceinline__ void cpa16(void* smem_dst, const void* gmem_src) {
    uint32_t s = (uint32_t)__cvta_generic_to_shared(smem_dst);
    asm volatile("cp.async.cg.shared.global [%0], [%1], 16;\n" :: "r"(s), "l"(gmem_src));
}
__device__ __forceinline__ void cpa_commit() { asm volatile("cp.async.commit_group;\n"); }
template<int N>
__device__ __forceinline__ void cpa_wait() { asm volatile("cp.async.wait_group %0;\n" :: "n"(N) : "memory"); }

__device__ __forceinline__ void mma_tf32(float& d0, float& d1, float& d2, float& d3,
                                         uint32_t a0, uint32_t a1, uint32_t a2, uint32_t a3,
                                         uint32_t b0, uint32_t b1) {
    asm volatile(
        "mma.sync.aligned.m16n8k8.row.col.f32.tf32.tf32.f32 "
        "{%0,%1,%2,%3}, {%4,%5,%6,%7}, {%8,%9}, {%0,%1,%2,%3};\n"
        : "+f"(d0), "+f"(d1), "+f"(d2), "+f"(d3)
        : "r"(a0), "r"(a1), "r"(a2), "r"(a3), "r"(b0), "r"(b1));
}

__device__ __forceinline__ void mma_f16(float& d0, float& d1, float& d2, float& d3,
                                        uint32_t a0, uint32_t a1, uint32_t a2, uint32_t a3,
                                        uint32_t b0, uint32_t b1) {
    asm volatile(
        "mma.sync.aligned.m16n8k16.row.col.f32.f16.f16.f32 "
        "{%0,%1,%2,%3}, {%4,%5,%6,%7}, {%8,%9}, {%0,%1,%2,%3};\n"
        : "+f"(d0), "+f"(d1), "+f"(d2), "+f"(d3)
        : "r"(a0), "r"(a1), "r"(a2), "r"(a3), "r"(b0), "r"(b1));
}

// ---------------------------------------------------------------------------
// Pre-pass 1: fp32 -> fp16 (float4 -> 2x half2)
// ---------------------------------------------------------------------------
__global__ void cvt_fp16_kernel(const float* __restrict__ in, __half* __restrict__ out, int n4)
{
    int i = blockIdx.x * blockDim.x + threadIdx.x;
    if (i < n4) {
        float4 v = ((const float4*)in)[i];
        ((__half2*)out)[2 * i]     = __floats2half2_rn(v.x, v.y);
        ((__half2*)out)[2 * i + 1] = __floats2half2_rn(v.z, v.w);
    }
}

// ---------------------------------------------------------------------------
// Pre-pass 2: W[K,N] fp32 -> W^T[N,K] fp16 (32x32 smem-tiled transpose)
// ---------------------------------------------------------------------------
__global__ void transpose_fp16_kernel(const float* __restrict__ W,
                                      __half* __restrict__ T, int K, int N)
{
    __shared__ float t[32][33];
    const int tx = threadIdx.x, ty = threadIdx.y;
    const int n0 = blockIdx.x * 32, k0 = blockIdx.y * 32;
#pragma unroll
    for (int i = 0; i < 4; i++)
        t[ty + i * 8][tx] = W[(size_t)(k0 + ty + i * 8) * N + n0 + tx];
    __syncthreads();
#pragma unroll
    for (int i = 0; i < 4; i++) {
        const int n = ty + i * 8;
        T[(size_t)(n0 + n) * K + k0 + tx] = __float2half_rn(t[tx][n]);
    }
}

// ---------------------------------------------------------------------------
// FP16 tensor-core GEMM: C[M,N] = A @ B^T + bias.
// A = [M,K] fp16 row-major; B = [N,K] fp16 row-major (pre-transposed weight).
// 128x128 block tile, BK=32 fp16, 256 thr = 8 warps (2m x 4n), m16n8k16.
// smem pitch 20 words (16 data + 4 pad): banks 20*gr+gc cover 0..31 ->
// conflict-free fragment loads.  Double-buffered cp.async.
// ---------------------------------------------------------------------------
#define GP 20   // smem pitch in 32-bit words

template<bool ROUND_OUT>
__global__ __launch_bounds__(256)
void gemm_fp16_kernel(const __half* __restrict__ A, const __half* __restrict__ B,
                      const float* __restrict__ bias, float* __restrict__ C,
                      int M, int N, int K)
{
    __shared__ uint32_t As[2][128 * GP];
    __shared__ uint32_t Bs[2][128 * GP];

    const int tid    = threadIdx.x;
    const int lane   = tid & 31;
    const int warp   = tid >> 5;
    const int warp_m = warp >> 2;          // 0..1 -> 64-row slab
    const int warp_n = warp & 3;           // 0..3 -> 32-col slab
    const int gr     = lane >> 2;
    const int gc     = lane & 3;

    const int brow = blockIdx.y * 128;
    const int bcol = blockIdx.x * 128;

    // Loaders: 128 rows x 2 16B-units per matrix; thread -> (row, unit-pair)
    const int ld_r = tid >> 1;             // 0..127
    const int ld_u = (tid & 1) * 2;        // unit 0 or 2 (each thread does 2 units)

    const __half* gA = A + (size_t)(brow + ld_r) * K + ld_u * 8;
    const __half* gB = B + (size_t)(bcol + ld_r) * K + ld_u * 8;

    float acc[4][4][4];
#pragma unroll
    for (int i = 0; i < 4; i++)
#pragma unroll
        for (int j = 0; j < 4; j++)
#pragma unroll
            for (int v = 0; v < 4; v++) acc[i][j][v] = 0.f;

    const int NCH = K / 32;

    // Prologue: chunk 0 -> buffer 0
    {
        cpa16(&As[0][ld_r * GP + ld_u * 4],       gA);
        cpa16(&As[0][ld_r * GP + (ld_u + 1) * 4], gA + 8);
        cpa16(&Bs[0][ld_r * GP + ld_u * 4],       gB);
        cpa16(&Bs[0][ld_r * GP + (ld_u + 1) * 4], gB + 8);
        cpa_commit();
    }

    int buf = 0;
    for (int c = 0; c < NCH; c++) {
        cpa_wait<0>();
        __syncthreads();   // chunk c resident; all reads of buf^1 (from c-1) done

        if (c + 1 < NCH) {
            const int kc = (c + 1) * 32;
            cpa16(&As[buf ^ 1][ld_r * GP + ld_u * 4],       gA + kc);
            cpa16(&As[buf ^ 1][ld_r * GP + (ld_u + 1) * 4], gA + kc + 8);
            cpa16(&Bs[buf ^ 1][ld_r * GP + ld_u * 4],       gB + kc);
            cpa16(&Bs[buf ^ 1][ld_r * GP + (ld_u + 1) * 4], gB + kc + 8);
            cpa_commit();
        }

        const uint32_t* as = As[buf];
        const uint32_t* bs = Bs[buf];

#pragma unroll
        for (int ks = 0; ks < 2; ks++) {
            const int w0 = ks * 8;
            uint32_t af[4][4], bf[4][2];
#pragma unroll
            for (int mi = 0; mi < 4; mi++) {
                const int m0 = warp_m * 64 + mi * 16;
                af[mi][0] = as[(m0 + gr)     * GP + w0 + gc];
                af[mi][1] = as[(m0 + gr + 8) * GP + w0 + gc];
                af[mi][2] = as[(m0 + gr)     * GP + w0 + gc + 4];
                af[mi][3] = as[(m0 + gr + 8) * GP + w0 + gc + 4];
            }
#pragma unroll
            for (int ni = 0; ni < 4; ni++) {
                const int n0 = warp_n * 32 + ni * 8;
                bf[ni][0] = bs[(n0 + gr) * GP + w0 + gc];
                bf[ni][1] = bs[(n0 + gr) * GP + w0 + gc + 4];
            }
#pragma unroll
            for (int mi = 0; mi < 4; mi++)
#pragma unroll
                for (int ni = 0; ni < 4; ni++)
                    mma_f16(acc[mi][ni][0], acc[mi][ni][1],
                            acc[mi][ni][2], acc[mi][ni][3],
                            af[mi][0], af[mi][1], af[mi][2], af[mi][3],
                            bf[ni][0], bf[ni][1]);
        }
        buf ^= 1;
    }

    // Epilogue: c0,c1 at (row gr, cols 2gc,2gc+1); c2,c3 at row gr+8.
#pragma unroll
    for (int ni = 0; ni < 4; ni++) {
        const int col = bcol + warp_n * 32 + ni * 8 + 2 * gc;
        const float bv0 = bias[col];
        const float bv1 = bias[col + 1];
#pragma unroll
        for (int mi = 0; mi < 4; mi++) {
            const int row = brow + warp_m * 64 + mi * 16 + gr;
            float2 o0, o1;
            if (ROUND_OUT) {
                o0 = make_float2(rtf(acc[mi][ni][0] + bv0), rtf(acc[mi][ni][1] + bv1));
                o1 = make_float2(rtf(acc[mi][ni][2] + bv0), rtf(acc[mi][ni][3] + bv1));
            } else {
                o0 = make_float2(acc[mi][ni][0] + bv0, acc[mi][ni][1] + bv1);
                o1 = make_float2(acc[mi][ni][2] + bv0, acc[mi][ni][3] + bv1);
            }
            *(float2*)&C[(size_t)row * N + col]       = o0;
            *(float2*)&C[(size_t)(row + 8) * N + col] = o1;
        }
    }
}

// ---------------------------------------------------------------------------
// Tensor-core flash attention (causal, tf32 mma, fp32 accum) — round-6 logic,
// epilogue emits fp16 for the fp16 GEMM2.
// ---------------------------------------------------------------------------
#define QPP 68
#define KPP 68
#define VPP 72
#define ATTN_SMEM ((128 * QPP + 2 * 64 * KPP + 2 * 64 * VPP) * 4)

__global__ __launch_bounds__(256, 2)
void attn_mma_kernel(const float* __restrict__ qkv, __half* __restrict__ out16)
{
    extern __shared__ float sm[];
    float* QP = sm;
    float* Ks0 = QP + 128 * QPP;
    float* Vs0 = Ks0 + 2 * 64 * KPP;

    const int tid  = threadIdx.x;
    const int lane = tid & 31;
    const int warp = tid >> 5;
    const int gr   = lane >> 2;
    const int gc   = lane & 3;

    const int bh = blockIdx.y;
    const int b  = bh / NHEAD;
    const int h  = bh % NHEAD;
    const int qt = 7 - blockIdx.x;
    const int qbase = qt * 128;
    const int ktmax = 2 * qt + 1;

    {
        const int r  = tid >> 1;
        const int c0 = (tid & 1) * 32;
        const float* src = qkv + (size_t)(b * SEQ + qbase + r) * EMB3 + h * HDIM + c0;
        float* dst = &QP[r * QPP + c0];
#pragma unroll
        for (int i = 0; i < 8; i++)
            cpa16(dst + 4 * i, src + 4 * i);
    }
    {
        const int r  = tid >> 2;
        const int c0 = (tid & 3) * 16;
        const float* kp = qkv + (size_t)(b * SEQ + r) * EMB3 + EMB + h * HDIM + c0;
        float* ks = &Ks0[r * KPP + c0];
        float* vs = &Vs0[r * VPP + c0];
#pragma unroll
        for (int i = 0; i < 4; i++) {
            cpa16(ks + 4 * i, kp + 4 * i);
            cpa16(vs + 4 * i, kp + EMB + 4 * i);
        }
    }
    cpa_commit();
    cpa_wait<0>();
    __syncthreads();

    uint32_t qf[8][4];
    {
        const uint32_t* qp = (const uint32_t*)QP;
        const int m0 = warp * 16;
#pragma unroll
        for (int ks = 0; ks < 8; ks++) {
            const int k8 = ks * 8;
            qf[ks][0] = qp[(m0 + gr)     * QPP + k8 + gc];
            qf[ks][1] = qp[(m0 + gr + 8) * QPP + k8 + gc];
            qf[ks][2] = qp[(m0 + gr)     * QPP + k8 + gc + 4];
            qf[ks][3] = qp[(m0 + gr + 8) * QPP + k8 + gc + 4];
        }
    }

    float o[8][4];
#pragma unroll
    for (int i = 0; i < 8; i++)
#pragma unroll
        for (int j = 0; j < 4; j++) o[i][j] = 0.f;
    float mr0 = -1e30f, mr1 = -1e30f, l0 = 0.f, l1 = 0.f;

    const int lrow0 = warp * 16 + gr;
    const int grow0 = qbase + lrow0;
    const int prow0 = lrow0 * QPP;
    const int prow1 = (lrow0 + 8) * QPP;

    int buf = 0;
    for (int kt = 0; kt <= ktmax; kt++) {
        const int kbase = kt * 64;
        cpa_wait<0>();
        __syncthreads();

        if (kt < ktmax) {
            const int r  = tid >> 2;
            const int c0 = (tid & 3) * 16;
            const float* kp = qkv + (size_t)(b * SEQ + (kt + 1) * 64 + r) * EMB3
                              + EMB + h * HDIM + c0;
            float* ks = &Ks0[(buf ^ 1) * 64 * KPP + r * KPP + c0];
            float* vs = &Vs0[(buf ^ 1) * 64 * VPP + r * VPP + c0];
#pragma unroll
            for (int i = 0; i < 4; i++) {
                cpa16(ks + 4 * i, kp + 4 * i);
                cpa16(vs + 4 * i, kp + EMB + 4 * i);
            }
            cpa_commit();
        }

        if (kbase > qbase + warp * 16 + 15) { buf ^= 1; continue; }

        float s[8][4];
#pragma unroll
        for (int i = 0; i < 8; i++)
#pragma unroll
            for (int j = 0; j < 4; j++) s[i][j] = 0.f;

        const uint32_t* ksm = (const uint32_t*)(Ks0 + buf * 64 * KPP);
#pragma unroll
        for (int ks = 0; ks < 8; ks++) {
            const int k8 = ks * 8;
            uint32_t bf[8][2];
#pragma unroll
            for (int nt = 0; nt < 8; nt++) {
                bf[nt][0] = ksm[(nt * 8 + gr) * KPP + k8 + gc];
                bf[nt][1] = ksm[(nt * 8 + gr) * KPP + k8 + gc + 4];
            }
#pragma unroll
            for (int nt = 0; nt < 8; nt++)
                mma_tf32(s[nt][0], s[nt][1], s[nt][2], s[nt][3],
                         qf[ks][0], qf[ks][1], qf[ks][2], qf[ks][3],
                         bf[nt][0], bf[nt][1]);
        }

        if (kbase + 63 > grow0) {
            const int lr0 = grow0;
            const int lr1 = grow0 + 8;
#pragma unroll
            for (int nt = 0; nt < 8; nt++) {
                const int c0 = kbase + nt * 8 + 2 * gc;
                s[nt][0] = (c0     > lr0) ? -1e30f : s[nt][0] * 0.125f;
                s[nt][1] = (c0 + 1 > lr0) ? -1e30f : s[nt][1] * 0.125f;
                s[nt][2] = (c0     > lr1) ? -1e30f : s[nt][2] * 0.125f;
                s[nt][3] = (c0 + 1 > lr1) ? -1e30f : s[nt][3] * 0.125f;
            }
        } else {
#pragma unroll
            for (int nt = 0; nt < 8; nt++) {
                s[nt][0] *= 0.125f; s[nt][1] *= 0.125f;
                s[nt][2] *= 0.125f; s[nt][3] *= 0.125f;
            }
        }

        float mx0 = -1e30f, mx1 = -1e30f;
#pragma unroll
        for (int nt = 0; nt < 8; nt++) {
            mx0 = fmaxf(mx0, fmaxf(s[nt][0], s[nt][1]));
            mx1 = fmaxf(mx1, fmaxf(s[nt][2], s[nt][3]));
        }
        mx0 = fmaxf(mx0, __shfl_xor_sync(0xffffffffu, mx0, 1));
        mx0 = fmaxf(mx0, __shfl_xor_sync(0xffffffffu, mx0, 2));
        mx1 = fmaxf(mx1, __shfl_xor_sync(0xffffffffu, mx1, 1));
        mx1 = fmaxf(mx1, __shfl_xor_sync(0xffffffffu, mx1, 2));

        const float mn0 = fmaxf(mr0, mx0);
        const float mn1 = fmaxf(mr1, mx1);
        const float a0  = __expf(mr0 - mn0);
        const float a1  = __expf(mr1 - mn1);
        mr0 = mn0; mr1 = mn1;

        float sum0 = 0.f, sum1 = 0.f;
#pragma unroll
        for (int nt = 0; nt < 8; nt++) {
            s[nt][0] = __expf(s[nt][0] - mn0);
            s[nt][1] = __expf(s[nt][1] - mn0);
            s[nt][2] = __expf(s[nt][2] - mn1);
            s[nt][3] = __expf(s[nt][3] - mn1);
            sum0 += s[nt][0] + s[nt][1];
            sum1 += s[nt][2] + s[nt][3];
        }
        sum0 += __shfl_xor_sync(0xffffffffu, sum0, 1);
        sum0 += __shfl_xor_sync(0xffffffffu, sum0, 2);
        sum1 += __shfl_xor_sync(0xffffffffu, sum1, 1);
        sum1 += __shfl_xor_sync(0xffffffffu, sum1, 2);
        l0 = l0 * a0 + sum0;
        l1 = l1 * a1 + sum1;

#pragma unroll
        for (int nt = 0; nt < 8; nt++) {
            o[nt][0] *= a0; o[nt][1] *= a0;
            o[nt][2] *= a1; o[nt][3] *= a1;
        }

        uint32_t* qpw = (uint32_t*)QP;
#pragma unroll
        for (int nt = 0; nt < 8; nt++) {
            uint2 p01 = make_uint2(f2tf32(s[nt][0]), f2tf32(s[nt][1]));
            uint2 p23 = make_uint2(f2tf32(s[nt][2]), f2tf32(s[nt][3]));
            *(uint2*)&qpw[prow0 + nt * 8 + 2 * gc] = p01;
            *(uint2*)&qpw[prow1 + nt * 8 + 2 * gc] = p23;
        }
        __syncwarp();

        const uint32_t* pp  = (const uint32_t*)QP;
        const uint32_t* vsm = (const uint32_t*)(Vs0 + buf * 64 * VPP);
#pragma unroll
        for (int ks = 0; ks < 8; ks++) {
            const int k8 = ks * 8;
            uint32_t af[4];
            af[0] = pp[prow0 + k8 + gc];
            af[1] = pp[prow1 + k8 + gc];
            af[2] = pp[prow0 + k8 + gc + 4];
            af[3] = pp[prow1 + k8 + gc + 4];
            uint32_t bf[8][2];
#pragma unroll
            for (int nt = 0; nt < 8; nt++) {
                bf[nt][0] = vsm[(k8 + gc)     * VPP + nt * 8 + gr];
                bf[nt][1] = vsm[(k8 + gc + 4) * VPP + nt * 8 + gr];
            }
#pragma unroll
            for (int nt = 0; nt < 8; nt++)
                mma_tf32(o[nt][0], o[nt][1], o[nt][2], o[nt][3],
                         af[0], af[1], af[2], af[3],
                         bf[nt][0], bf[nt][1]);
        }
        __syncwarp();
        buf ^= 1;
    }

    // Epilogue: normalize, convert fp16, write head-concat [B,T,C]
    const float inv0 = 1.f / l0;
    const float inv1 = 1.f / l1;
    const int r0g = b * SEQ + grow0;
#pragma unroll
    for (int nt = 0; nt < 8; nt++) {
        const int col = h * HDIM + nt * 8 + 2 * gc;
        *(__half2*)&out16[(size_t)r0g * EMB + col] =
            __floats2half2_rn(o[nt][0] * inv0, o[nt][1] * inv0);
        *(__half2*)&out16[(size_t)(r0g + 8) * EMB + col] =
            __floats2half2_rn(o[nt][2] * inv1, o[nt][3] * inv1);
    }
}

// ---------------------------------------------------------------------------
extern "C" void kernel_launch(void* const* d_in, const int* in_sizes, int n_in,
                              void* d_out, int out_size)
{
    const float* x      = (const float*)d_in[0];
    const float* W_attn = (const float*)d_in[1];
    const float* b_attn = (const float*)d_in[2];
    const float* W_proj = (const float*)d_in[3];
    const float* b_proj = (const float*)d_in[4];
    float* out = (float*)d_out;

    float* qkv;
    __half *x16, *wat16, *wpt16, *at16;
    cudaGetSymbolAddress((void**)&qkv,   g_qkv);
    cudaGetSymbolAddress((void**)&x16,   g_x16);
    cudaGetSymbolAddress((void**)&wat16, g_wat16);
    cudaGetSymbolAddress((void**)&wpt16, g_wpt16);
    cudaGetSymbolAddress((void**)&at16,  g_at16);

    cudaFuncSetAttribute(attn_mma_kernel,
                         cudaFuncAttributeMaxDynamicSharedMemorySize, ATTN_SMEM);

    const int M = MROWS;  // 8192

    // 0) convert x -> fp16; transpose+convert weights -> [N,K] fp16
    cvt_fp16_kernel<<<(M * EMB / 4 + 255) / 256, 256>>>(x, x16, M * EMB / 4);
    transpose_fp16_kernel<<<dim3(EMB3 / 32, EMB / 32), dim3(32, 8)>>>(
        W_attn, wat16, EMB, EMB3);
    transpose_fp16_kernel<<<dim3(EMB / 32, EMB / 32), dim3(32, 8)>>>(
        W_proj, wpt16, EMB, EMB);

    // 1) QKV = x @ W_attn + b_attn  (fp16 mma, fp32 accum; tf32-rounded out)
    gemm_fp16_kernel<true><<<dim3(EMB3 / 128, M / 128), 256>>>(
        x16, wat16, b_attn, qkv, M, EMB3, EMB);

    // 2) causal MHA (tf32 mma) -> fp16
    attn_mma_kernel<<<dim3(SEQ / 128, BATCH * NHEAD), 256, ATTN_SMEM>>>(qkv, at16);

    // 3) out = att @ W_proj + b_proj  (fp16 mma, fp32 out)
    gemm_fp16_kernel<false><<<dim3(EMB / 128, M / 128), 256>>>(
        at16, wpt16, b_proj, out, M, EMB, EMB);
}

// round 11
// speedup vs baseline: 5.1014x; 1.2788x over previous
#include <cuda_runtime.h>
#include <cuda_fp16.h>
#include <cstdint>

#define EMB   768
#define EMB3  2304
#define NHEAD 12
#define HDIM  64
#define SEQ   1024
#define BATCH 8
#define MROWS (BATCH * SEQ)   // 8192

// ---------------------------------------------------------------------------
// Scratch (no cudaMalloc allowed).
// ---------------------------------------------------------------------------
__device__ __align__(256) __half g_x16 [(size_t)MROWS * EMB];       // x fp16
__device__ __align__(256) __half g_wat16[(size_t)EMB3 * EMB];       // W_attn^T [N,K] fp16
__device__ __align__(256) __half g_wpt16[(size_t)EMB * EMB];        // W_proj^T [N,K] fp16
__device__ __align__(256) __half g_qk16[(size_t)MROWS * 2 * EMB];   // Q|K fp16 [M,1536]
__device__ __align__(256) __half g_vt16[(size_t)BATCH * NHEAD * HDIM * SEQ]; // V^T fp16 [B,H,d,t]
__device__ __align__(256) __half g_at16[(size_t)MROWS * EMB];       // attn out fp16

// ---------------------------------------------------------------------------
// Helpers
// ---------------------------------------------------------------------------
__device__ __forceinline__ void cpa16(void* smem_dst, const void* gmem_src) {
    uint32_t s = (uint32_t)__cvta_generic_to_shared(smem_dst);
    asm volatile("cp.async.cg.shared.global [%0], [%1], 16;\n" :: "r"(s), "l"(gmem_src));
}
__device__ __forceinline__ void cpa_commit() { asm volatile("cp.async.commit_group;\n"); }
template<int N>
__device__ __forceinline__ void cpa_wait() { asm volatile("cp.async.wait_group %0;\n" :: "n"(N) : "memory"); }

__device__ __forceinline__ void mma_f16(float& d0, float& d1, float& d2, float& d3,
                                        uint32_t a0, uint32_t a1, uint32_t a2, uint32_t a3,
                                        uint32_t b0, uint32_t b1) {
    asm volatile(
        "mma.sync.aligned.m16n8k16.row.col.f32.f16.f16.f32 "
        "{%0,%1,%2,%3}, {%4,%5,%6,%7}, {%8,%9}, {%0,%1,%2,%3};\n"
        : "+f"(d0), "+f"(d1), "+f"(d2), "+f"(d3)
        : "r"(a0), "r"(a1), "r"(a2), "r"(a3), "r"(b0), "r"(b1));
}

// Pack two fp32 -> one fp16x2 word (lo = first arg, hi = second arg).
__device__ __forceinline__ uint32_t pack_f16x2(float lo, float hi) {
    uint32_t u;
    asm("cvt.rn.f16x2.f32 %0, %1, %2;" : "=r"(u) : "f"(hi), "f"(lo));
    return u;
}

// ---------------------------------------------------------------------------
// Pre-pass 1: fp32 -> fp16 (float4 -> 2x half2)
// ---------------------------------------------------------------------------
__global__ void cvt_fp16_kernel(const float* __restrict__ in, __half* __restrict__ out, int n4)
{
    int i = blockIdx.x * blockDim.x + threadIdx.x;
    if (i < n4) {
        float4 v = ((const float4*)in)[i];
        ((__half2*)out)[2 * i]     = __floats2half2_rn(v.x, v.y);
        ((__half2*)out)[2 * i + 1] = __floats2half2_rn(v.z, v.w);
    }
}

// ---------------------------------------------------------------------------
// Pre-pass 2: W[K,N] fp32 -> W^T[N,K] fp16 (32x32 smem-tiled transpose)
// ---------------------------------------------------------------------------
__global__ void transpose_fp16_kernel(const float* __restrict__ W,
                                      __half* __restrict__ T, int K, int N)
{
    __shared__ float t[32][33];
    const int tx = threadIdx.x, ty = threadIdx.y;
    const int n0 = blockIdx.x * 32, k0 = blockIdx.y * 32;
#pragma unroll
    for (int i = 0; i < 4; i++)
        t[ty + i * 8][tx] = W[(size_t)(k0 + ty + i * 8) * N + n0 + tx];
    __syncthreads();
#pragma unroll
    for (int i = 0; i < 4; i++) {
        const int n = ty + i * 8;
        T[(size_t)(n0 + n) * K + k0 + tx] = __float2half_rn(t[tx][n]);
    }
}

// ---------------------------------------------------------------------------
// FP16 tensor-core GEMM: C = A @ B^T + bias.
// A=[M,K] fp16, B=[N,K] fp16.  128x128 tile, BK=32, 256 thr, m16n8k16.
// MODE 0: C fp32 [M,N]            (projection GEMM -> harness output)
// MODE 1: QKV layout: cols<1536 -> g_qk16 [M,1536] fp16;
//         cols>=1536 (V) -> g_vt16 [B,H,d,t] fp16 (transposed for attention)
// ---------------------------------------------------------------------------
#define GP 20   // smem pitch in 32-bit words

template<int MODE>
__global__ __launch_bounds__(256)
void gemm_fp16_kernel(const __half* __restrict__ A, const __half* __restrict__ B,
                      const float* __restrict__ bias, float* __restrict__ C,
                      __half* __restrict__ QK, __half* __restrict__ VT,
                      int M, int N, int K)
{
    __shared__ uint32_t As[2][128 * GP];
    __shared__ uint32_t Bs[2][128 * GP];

    const int tid    = threadIdx.x;
    const int lane   = tid & 31;
    const int warp   = tid >> 5;
    const int warp_m = warp >> 2;
    const int warp_n = warp & 3;
    const int gr     = lane >> 2;
    const int gc     = lane & 3;

    const int brow = blockIdx.y * 128;
    const int bcol = blockIdx.x * 128;

    const int ld_r = tid >> 1;
    const int ld_u = (tid & 1) * 2;

    const __half* gA = A + (size_t)(brow + ld_r) * K + ld_u * 8;
    const __half* gB = B + (size_t)(bcol + ld_r) * K + ld_u * 8;

    float acc[4][4][4];
#pragma unroll
    for (int i = 0; i < 4; i++)
#pragma unroll
        for (int j = 0; j < 4; j++)
#pragma unroll
            for (int v = 0; v < 4; v++) acc[i][j][v] = 0.f;

    const int NCH = K / 32;

    {
        cpa16(&As[0][ld_r * GP + ld_u * 4],       gA);
        cpa16(&As[0][ld_r * GP + (ld_u + 1) * 4], gA + 8);
        cpa16(&Bs[0][ld_r * GP + ld_u * 4],       gB);
        cpa16(&Bs[0][ld_r * GP + (ld_u + 1) * 4], gB + 8);
        cpa_commit();
    }

    int buf = 0;
    for (int c = 0; c < NCH; c++) {
        cpa_wait<0>();
        __syncthreads();

        if (c + 1 < NCH) {
            const int kc = (c + 1) * 32;
            cpa16(&As[buf ^ 1][ld_r * GP + ld_u * 4],       gA + kc);
            cpa16(&As[buf ^ 1][ld_r * GP + (ld_u + 1) * 4], gA + kc + 8);
            cpa16(&Bs[buf ^ 1][ld_r * GP + ld_u * 4],       gB + kc);
            cpa16(&Bs[buf ^ 1][ld_r * GP + (ld_u + 1) * 4], gB + kc + 8);
            cpa_commit();
        }

        const uint32_t* as = As[buf];
        const uint32_t* bs = Bs[buf];

#pragma unroll
        for (int ks = 0; ks < 2; ks++) {
            const int w0 = ks * 8;
            uint32_t af[4][4], bf[4][2];
#pragma unroll
            for (int mi = 0; mi < 4; mi++) {
                const int m0 = warp_m * 64 + mi * 16;
                af[mi][0] = as[(m0 + gr)     * GP + w0 + gc];
                af[mi][1] = as[(m0 + gr + 8) * GP + w0 + gc];
                af[mi][2] = as[(m0 + gr)     * GP + w0 + gc + 4];
                af[mi][3] = as[(m0 + gr + 8) * GP + w0 + gc + 4];
            }
#pragma unroll
            for (int ni = 0; ni < 4; ni++) {
                const int n0 = warp_n * 32 + ni * 8;
                bf[ni][0] = bs[(n0 + gr) * GP + w0 + gc];
                bf[ni][1] = bs[(n0 + gr) * GP + w0 + gc + 4];
            }
#pragma unroll
            for (int mi = 0; mi < 4; mi++)
#pragma unroll
                for (int ni = 0; ni < 4; ni++)
                    mma_f16(acc[mi][ni][0], acc[mi][ni][1],
                            acc[mi][ni][2], acc[mi][ni][3],
                            af[mi][0], af[mi][1], af[mi][2], af[mi][3],
                            bf[ni][0], bf[ni][1]);
        }
        buf ^= 1;
    }

    // Epilogue
#pragma unroll
    for (int ni = 0; ni < 4; ni++) {
        const int col = bcol + warp_n * 32 + ni * 8 + 2 * gc;
        const float bv0 = bias[col];
        const float bv1 = bias[col + 1];
#pragma unroll
        for (int mi = 0; mi < 4; mi++) {
            const int row = brow + warp_m * 64 + mi * 16 + gr;
            const float v00 = acc[mi][ni][0] + bv0, v01 = acc[mi][ni][1] + bv1;
            const float v10 = acc[mi][ni][2] + bv0, v11 = acc[mi][ni][3] + bv1;
            if (MODE == 0) {
                *(float2*)&C[(size_t)row * N + col]       = make_float2(v00, v01);
                *(float2*)&C[(size_t)(row + 8) * N + col] = make_float2(v10, v11);
            } else {
                if (col < 1536) {
                    *(__half2*)&QK[(size_t)row * 1536 + col] = __floats2half2_rn(v00, v01);
                    *(__half2*)&QK[(size_t)(row + 8) * 1536 + col] = __floats2half2_rn(v10, v11);
                } else {
                    const int cc = col - 1536;
                    const int h  = cc >> 6;
                    const int d0 = cc & 63;
                    const int b  = row >> 10;
                    const int t  = row & 1023;
                    __half* base = VT + ((size_t)(b * NHEAD + h) * HDIM) * SEQ;
                    base[(size_t)d0 * SEQ + t]           = __float2half_rn(v00);
                    base[(size_t)(d0 + 1) * SEQ + t]     = __float2half_rn(v01);
                    base[(size_t)d0 * SEQ + t + 8]       = __float2half_rn(v10);
                    base[(size_t)(d0 + 1) * SEQ + t + 8] = __float2half_rn(v11);
                }
            }
        }
    }
}

// ---------------------------------------------------------------------------
// FP16 tensor-core flash attention (causal, m16n8k16, fp32 accum/softmax).
// 256 thr (8 warps), 128-query tile; warp w owns rows [16w, 16w+16).
// Q/K from g_qk16 [M,1536]; V from g_vt16 [B,H,d,t] (keys contiguous ->
// word-packed B fragments).  All smem pitches 36 words (conflict-free:
// bank = 4*gr + gc covers 0..31).
// ---------------------------------------------------------------------------
#define APW 36   // pitch in words (32 data + 4 pad)
#define AT2_SMEM ((128 * APW + 2 * 64 * APW + 2 * 64 * APW) * 4)

__global__ __launch_bounds__(256, 2)
void attn_f16_kernel(const __half* __restrict__ qk, const __half* __restrict__ vt,
                     __half* __restrict__ out16)
{
    extern __shared__ uint32_t smw[];
    uint32_t* QP  = smw;                   // 128 x APW : Q tile, later P strips
    uint32_t* Ks0 = QP + 128 * APW;        // 2 x 64 x APW
    uint32_t* Vt0 = Ks0 + 2 * 64 * APW;    // 2 x 64 x APW

    const int tid  = threadIdx.x;
    const int lane = tid & 31;
    const int warp = tid >> 5;
    const int gr   = lane >> 2;
    const int gc   = lane & 3;

    const int bh = blockIdx.y;
    const int b  = bh / NHEAD;
    const int h  = bh % NHEAD;
    const int qt = 7 - blockIdx.x;
    const int qbase = qt * 128;
    const int ktmax = 2 * qt + 1;

    // Q tile: 128 rows x 64 halves (8 x 16B units); 2 threads/row, 4 units each
    {
        const int r = tid >> 1;
        const int u = (tid & 1) * 4;
        const __half* src = qk + (size_t)(b * SEQ + qbase + r) * 1536 + h * HDIM + u * 8;
        uint32_t* dst = QP + r * APW + u * 4;
#pragma unroll
        for (int i = 0; i < 4; i++)
            cpa16(dst + 4 * i, src + 8 * i);
    }
    // K + Vt tile 0: 64 rows x 8 units; 4 threads/row, 2 units each
    {
        const int r = tid >> 2;
        const int u = (tid & 3) * 2;
        const __half* ksrc = qk + (size_t)(b * SEQ + r) * 1536 + 768 + h * HDIM + u * 8;
        const __half* vsrc = vt + ((size_t)(b * NHEAD + h) * HDIM + r) * SEQ + u * 8;
        cpa16(Ks0 + r * APW + u * 4,     ksrc);
        cpa16(Ks0 + r * APW + u * 4 + 4, ksrc + 8);
        cpa16(Vt0 + r * APW + u * 4,     vsrc);
        cpa16(Vt0 + r * APW + u * 4 + 4, vsrc + 8);
    }
    cpa_commit();
    cpa_wait<0>();
    __syncthreads();

    // Q fragments in registers: 4 k16-chunks x 4 words
    uint32_t qf[4][4];
    {
        const int m0 = warp * 16;
#pragma unroll
        for (int c = 0; c < 4; c++) {
            const int w0 = c * 8;
            qf[c][0] = QP[(m0 + gr)     * APW + w0 + gc];
            qf[c][1] = QP[(m0 + gr + 8) * APW + w0 + gc];
            qf[c][2] = QP[(m0 + gr)     * APW + w0 + gc + 4];
            qf[c][3] = QP[(m0 + gr + 8) * APW + w0 + gc + 4];
        }
    }

    float o[8][4];
#pragma unroll
    for (int i = 0; i < 8; i++)
#pragma unroll
        for (int j = 0; j < 4; j++) o[i][j] = 0.f;
    float mr0 = -1e30f, mr1 = -1e30f, l0 = 0.f, l1 = 0.f;

    const int lrow = warp * 16 + gr;        // block-local query row
    const int grow0 = qbase + lrow;         // global query row
    const int prow0 = lrow * APW;
    const int prow1 = (lrow + 8) * APW;

    int buf = 0;
    for (int kt = 0; kt <= ktmax; kt++) {
        const int kbase = kt * 64;
        cpa_wait<0>();
        __syncthreads();

        if (kt < ktmax) {
            const int r = tid >> 2;
            const int u = (tid & 3) * 2;
            const __half* ksrc = qk + (size_t)(b * SEQ + (kt + 1) * 64 + r) * 1536
                                 + 768 + h * HDIM + u * 8;
            const __half* vsrc = vt + ((size_t)(b * NHEAD + h) * HDIM + r) * SEQ
                                 + (kt + 1) * 64 + u * 8;
            uint32_t* kd = Ks0 + (buf ^ 1) * 64 * APW + r * APW + u * 4;
            uint32_t* vd = Vt0 + (buf ^ 1) * 64 * APW + r * APW + u * 4;
            cpa16(kd,     ksrc);
            cpa16(kd + 4, ksrc + 8);
            cpa16(vd,     vsrc);
            cpa16(vd + 4, vsrc + 8);
            cpa_commit();
        }

        if (kbase > qbase + warp * 16 + 15) { buf ^= 1; continue; }

        // ---- S = Q @ K^T (16 x 64 per warp), fp16 m16n8k16 ----
        float s[8][4];
#pragma unroll
        for (int i = 0; i < 8; i++)
#pragma unroll
            for (int j = 0; j < 4; j++) s[i][j] = 0.f;

        const uint32_t* ksm = Ks0 + buf * 64 * APW;
#pragma unroll
        for (int c = 0; c < 4; c++) {
            const int w0 = c * 8;
            uint32_t bf[8][2];
#pragma unroll
            for (int nt = 0; nt < 8; nt++) {
                bf[nt][0] = ksm[(nt * 8 + gr) * APW + w0 + gc];
                bf[nt][1] = ksm[(nt * 8 + gr) * APW + w0 + gc + 4];
            }
#pragma unroll
            for (int nt = 0; nt < 8; nt++)
                mma_f16(s[nt][0], s[nt][1], s[nt][2], s[nt][3],
                        qf[c][0], qf[c][1], qf[c][2], qf[c][3],
                        bf[nt][0], bf[nt][1]);
        }

        // ---- scale + causal mask (global frame) ----
        if (kbase + 63 > grow0) {
            const int lr0 = grow0;
            const int lr1 = grow0 + 8;
#pragma unroll
            for (int nt = 0; nt < 8; nt++) {
                const int c0 = kbase + nt * 8 + 2 * gc;
                s[nt][0] = (c0     > lr0) ? -1e30f : s[nt][0] * 0.125f;
                s[nt][1] = (c0 + 1 > lr0) ? -1e30f : s[nt][1] * 0.125f;
                s[nt][2] = (c0     > lr1) ? -1e30f : s[nt][2] * 0.125f;
                s[nt][3] = (c0 + 1 > lr1) ? -1e30f : s[nt][3] * 0.125f;
            }
        } else {
#pragma unroll
            for (int nt = 0; nt < 8; nt++) {
                s[nt][0] *= 0.125f; s[nt][1] *= 0.125f;
                s[nt][2] *= 0.125f; s[nt][3] *= 0.125f;
            }
        }

        // ---- online softmax (registers + quad shuffles) ----
        float mx0 = -1e30f, mx1 = -1e30f;
#pragma unroll
        for (int nt = 0; nt < 8; nt++) {
            mx0 = fmaxf(mx0, fmaxf(s[nt][0], s[nt][1]));
            mx1 = fmaxf(mx1, fmaxf(s[nt][2], s[nt][3]));
        }
        mx0 = fmaxf(mx0, __shfl_xor_sync(0xffffffffu, mx0, 1));
        mx0 = fmaxf(mx0, __shfl_xor_sync(0xffffffffu, mx0, 2));
        mx1 = fmaxf(mx1, __shfl_xor_sync(0xffffffffu, mx1, 1));
        mx1 = fmaxf(mx1, __shfl_xor_sync(0xffffffffu, mx1, 2));

        const float mn0 = fmaxf(mr0, mx0);
        const float mn1 = fmaxf(mr1, mx1);
        const float a0  = __expf(mr0 - mn0);
        const float a1  = __expf(mr1 - mn1);
        mr0 = mn0; mr1 = mn1;

        float sum0 = 0.f, sum1 = 0.f;
#pragma unroll
        for (int nt = 0; nt < 8; nt++) {
            s[nt][0] = __expf(s[nt][0] - mn0);
            s[nt][1] = __expf(s[nt][1] - mn0);
            s[nt][2] = __expf(s[nt][2] - mn1);
            s[nt][3] = __expf(s[nt][3] - mn1);
            sum0 += s[nt][0] + s[nt][1];
            sum1 += s[nt][2] + s[nt][3];
        }
        sum0 += __shfl_xor_sync(0xffffffffu, sum0, 1);
        sum0 += __shfl_xor_sync(0xffffffffu, sum0, 2);
        sum1 += __shfl_xor_sync(0xffffffffu, sum1, 1);
        sum1 += __shfl_xor_sync(0xffffffffu, sum1, 2);
        l0 = l0 * a0 + sum0;
        l1 = l1 * a1 + sum1;

#pragma unroll
        for (int nt = 0; nt < 8; nt++) {
            o[nt][0] *= a0; o[nt][1] *= a0;
            o[nt][2] *= a1; o[nt][3] *= a1;
        }

        // ---- P (fp16) -> warp-local smem strip; reload as A fragments ----
#pragma unroll
        for (int nt = 0; nt < 8; nt++) {
            QP[prow0 + nt * 4 + gc] = pack_f16x2(s[nt][0], s[nt][1]);
            QP[prow1 + nt * 4 + gc] = pack_f16x2(s[nt][2], s[nt][3]);
        }
        __syncwarp();

        // ---- O += P @ V  (A = P strip, B = Vt word-packed) ----
        const uint32_t* vsm = Vt0 + buf * 64 * APW;
#pragma unroll
        for (int c = 0; c < 4; c++) {
            const int w0 = c * 8;
            uint32_t af[4];
            af[0] = QP[prow0 + w0 + gc];
            af[1] = QP[prow1 + w0 + gc];
            af[2] = QP[prow0 + w0 + gc + 4];
            af[3] = QP[prow1 + w0 + gc + 4];
            uint32_t bf[8][2];
#pragma unroll
            for (int nt = 0; nt < 8; nt++) {
                bf[nt][0] = vsm[(nt * 8 + gr) * APW + w0 + gc];
                bf[nt][1] = vsm[(nt * 8 + gr) * APW + w0 + gc + 4];
            }
#pragma unroll
            for (int nt = 0; nt < 8; nt++)
                mma_f16(o[nt][0], o[nt][1], o[nt][2], o[nt][3],
                        af[0], af[1], af[2], af[3],
                        bf[nt][0], bf[nt][1]);
        }
        __syncwarp();
        buf ^= 1;
    }

    // ---- epilogue: normalize, fp16, head-concat [M,768] ----
    const float inv0 = 1.f / l0;
    const float inv1 = 1.f / l1;
    const int r0g = b * SEQ + grow0;
#pragma unroll
    for (int nt = 0; nt < 8; nt++) {
        const int col = h * HDIM + nt * 8 + 2 * gc;
        *(__half2*)&out16[(size_t)r0g * EMB + col] =
            __floats2half2_rn(o[nt][0] * inv0, o[nt][1] * inv0);
        *(__half2*)&out16[(size_t)(r0g + 8) * EMB + col] =
            __floats2half2_rn(o[nt][2] * inv1, o[nt][3] * inv1);
    }
}

// ---------------------------------------------------------------------------
extern "C" void kernel_launch(void* const* d_in, const int* in_sizes, int n_in,
                              void* d_out, int out_size)
{
    const float* x      = (const float*)d_in[0];
    const float* W_attn = (const float*)d_in[1];
    const float* b_attn = (const float*)d_in[2];
    const float* W_proj = (const float*)d_in[3];
    const float* b_proj = (const float*)d_in[4];
    float* out = (float*)d_out;

    __half *x16, *wat16, *wpt16, *qk16, *vt16, *at16;
    cudaGetSymbolAddress((void**)&x16,   g_x16);
    cudaGetSymbolAddress((void**)&wat16, g_wat16);
    cudaGetSymbolAddress((void**)&wpt16, g_wpt16);
    cudaGetSymbolAddress((void**)&qk16,  g_qk16);
    cudaGetSymbolAddress((void**)&vt16,  g_vt16);
    cudaGetSymbolAddress((void**)&at16,  g_at16);

    cudaFuncSetAttribute(attn_f16_kernel,
                         cudaFuncAttributeMaxDynamicSharedMemorySize, AT2_SMEM);

    const int M = MROWS;  // 8192

    // 0) convert x -> fp16; transpose+convert weights -> [N,K] fp16
    cvt_fp16_kernel<<<(M * EMB / 4 + 255) / 256, 256>>>(x, x16, M * EMB / 4);
    transpose_fp16_kernel<<<dim3(EMB3 / 32, EMB / 32), dim3(32, 8)>>>(
        W_attn, wat16, EMB, EMB3);
    transpose_fp16_kernel<<<dim3(EMB / 32, EMB / 32), dim3(32, 8)>>>(
        W_proj, wpt16, EMB, EMB);

    // 1) QKV GEMM (fp16 mma) -> Q|K fp16 [M,1536] + V^T fp16 [B,H,d,t]
    gemm_fp16_kernel<1><<<dim3(EMB3 / 128, M / 128), 256>>>(
        x16, wat16, b_attn, nullptr, qk16, vt16, M, EMB3, EMB);

    // 2) causal MHA (fp16 mma) -> fp16 [M,768]
    attn_f16_kernel<<<dim3(SEQ / 128, BATCH * NHEAD), 256, AT2_SMEM>>>(
        qk16, vt16, at16);

    // 3) out = att @ W_proj + b_proj  (fp16 mma, fp32 out)
    gemm_fp16_kernel<0><<<dim3(EMB / 128, M / 128), 256>>>(
        at16, wpt16, b_proj, out, nullptr, nullptr, M, EMB, EMB);
}

// round 12
// speedup vs baseline: 5.3757x; 1.0538x over previous
#include <cuda_runtime.h>
#include <cuda_fp16.h>
#include <cstdint>

#define EMB   768
#define EMB3  2304
#define NHEAD 12
#define HDIM  64
#define SEQ   1024
#define BATCH 8
#define MROWS (BATCH * SEQ)   // 8192

// ---------------------------------------------------------------------------
// Scratch (no cudaMalloc allowed).
// ---------------------------------------------------------------------------
__device__ __align__(256) __half g_x16 [(size_t)MROWS * EMB];       // x fp16
__device__ __align__(256) __half g_wat16[(size_t)EMB3 * EMB];       // W_attn^T [N,K] fp16
__device__ __align__(256) __half g_wpt16[(size_t)EMB * EMB];        // W_proj^T [N,K] fp16
__device__ __align__(256) __half g_qk16[(size_t)MROWS * 2 * EMB];   // Q|K fp16 [M,1536]
__device__ __align__(256) __half g_vt16[(size_t)BATCH * NHEAD * HDIM * SEQ]; // V^T fp16 [B,H,d,t]
__device__ __align__(256) __half g_at16[(size_t)MROWS * EMB];       // attn out fp16

// ---------------------------------------------------------------------------
// Helpers
// ---------------------------------------------------------------------------
__device__ __forceinline__ void cpa16(void* smem_dst, const void* gmem_src) {
    uint32_t s = (uint32_t)__cvta_generic_to_shared(smem_dst);
    asm volatile("cp.async.cg.shared.global [%0], [%1], 16;\n" :: "r"(s), "l"(gmem_src));
}
__device__ __forceinline__ void cpa_commit() { asm volatile("cp.async.commit_group;\n"); }
template<int N>
__device__ __forceinline__ void cpa_wait() { asm volatile("cp.async.wait_group %0;\n" :: "n"(N) : "memory"); }

__device__ __forceinline__ void mma_f16(float& d0, float& d1, float& d2, float& d3,
                                        uint32_t a0, uint32_t a1, uint32_t a2, uint32_t a3,
                                        uint32_t b0, uint32_t b1) {
    asm volatile(
        "mma.sync.aligned.m16n8k16.row.col.f32.f16.f16.f32 "
        "{%0,%1,%2,%3}, {%4,%5,%6,%7}, {%8,%9}, {%0,%1,%2,%3};\n"
        : "+f"(d0), "+f"(d1), "+f"(d2), "+f"(d3)
        : "r"(a0), "r"(a1), "r"(a2), "r"(a3), "r"(b0), "r"(b1));
}

// ldmatrix x4 (non-transposed): 4 8x8 b16 matrices; lane l of matrix q gets
// (row l>>2, word l&3).  Matrix q sourced from addresses of lanes 8q..8q+7.
__device__ __forceinline__ void ldsm4(uint32_t& r0, uint32_t& r1,
                                      uint32_t& r2, uint32_t& r3, uint32_t addr) {
    asm volatile("ldmatrix.sync.aligned.m8n8.x4.shared.b16 {%0,%1,%2,%3}, [%4];"
                 : "=r"(r0), "=r"(r1), "=r"(r2), "=r"(r3) : "r"(addr));
}

// Pack two fp32 -> one fp16x2 word (lo = first arg, hi = second arg).
__device__ __forceinline__ uint32_t pack_f16x2(float lo, float hi) {
    uint32_t u;
    asm("cvt.rn.f16x2.f32 %0, %1, %2;" : "=r"(u) : "f"(hi), "f"(lo));
    return u;
}

// ---------------------------------------------------------------------------
// Pre-pass 1: fp32 -> fp16 (float4 -> 2x half2)
// ---------------------------------------------------------------------------
__global__ void cvt_fp16_kernel(const float* __restrict__ in, __half* __restrict__ out, int n4)
{
    int i = blockIdx.x * blockDim.x + threadIdx.x;
    if (i < n4) {
        float4 v = ((const float4*)in)[i];
        ((__half2*)out)[2 * i]     = __floats2half2_rn(v.x, v.y);
        ((__half2*)out)[2 * i + 1] = __floats2half2_rn(v.z, v.w);
    }
}

// ---------------------------------------------------------------------------
// Pre-pass 2: W[K,N] fp32 -> W^T[N,K] fp16 (32x32 smem-tiled transpose)
// ---------------------------------------------------------------------------
__global__ void transpose_fp16_kernel(const float* __restrict__ W,
                                      __half* __restrict__ T, int K, int N)
{
    __shared__ float t[32][33];
    const int tx = threadIdx.x, ty = threadIdx.y;
    const int n0 = blockIdx.x * 32, k0 = blockIdx.y * 32;
#pragma unroll
    for (int i = 0; i < 4; i++)
        t[ty + i * 8][tx] = W[(size_t)(k0 + ty + i * 8) * N + n0 + tx];
    __syncthreads();
#pragma unroll
    for (int i = 0; i < 4; i++) {
        const int n = ty + i * 8;
        T[(size_t)(n0 + n) * K + k0 + tx] = __float2half_rn(t[tx][n]);
    }
}

// ---------------------------------------------------------------------------
// FP16 tensor-core GEMM: C = A @ B^T + bias.
// A=[M,K] fp16, B=[N,K] fp16.  128x128 tile, BK=32, 256 thr, m16n8k16.
// Fragment loads via ldmatrix.x4 (pitch 20 words -> conflict-free).
// MODE 0: C fp32 [M,N]; MODE 1: QKV layout (QK fp16 + V^T fp16).
// ---------------------------------------------------------------------------
#define GP 20   // smem pitch in 32-bit words

template<int MODE>
__global__ __launch_bounds__(256)
void gemm_fp16_kernel(const __half* __restrict__ A, const __half* __restrict__ B,
                      const float* __restrict__ bias, float* __restrict__ C,
                      __half* __restrict__ QK, __half* __restrict__ VT,
                      int M, int N, int K)
{
    __shared__ uint32_t As[2][128 * GP];
    __shared__ uint32_t Bs[2][128 * GP];

    const int tid    = threadIdx.x;
    const int lane   = tid & 31;
    const int warp   = tid >> 5;
    const int warp_m = warp >> 2;
    const int warp_n = warp & 3;
    const int gr     = lane >> 2;
    const int gc     = lane & 3;

    const int brow = blockIdx.y * 128;
    const int bcol = blockIdx.x * 128;

    const int ld_r = tid >> 1;
    const int ld_u = (tid & 1) * 2;

    const __half* gA = A + (size_t)(brow + ld_r) * K + ld_u * 8;
    const __half* gB = B + (size_t)(bcol + ld_r) * K + ld_u * 8;

    // ldmatrix per-lane offsets (in words)
    const int lrow8 = lane & 7;
    const int segA  = (lane >> 3) & 1;       // A: matrices 0,1 -> rows +0/+8
    const int segAc = lane >> 4;             // A: matrices 2,3 -> words +4
    const int aLw = (segA * 8 + lrow8) * GP + segAc * 4;
    const int bLw = (segAc * 8 + lrow8) * GP + segA * 4;   // B: row pairs outer, word pairs inner

    const uint32_t asb = (uint32_t)__cvta_generic_to_shared(&As[0][0]);
    const uint32_t bsb = (uint32_t)__cvta_generic_to_shared(&Bs[0][0]);

    float acc[4][4][4];
#pragma unroll
    for (int i = 0; i < 4; i++)
#pragma unroll
        for (int j = 0; j < 4; j++)
#pragma unroll
            for (int v = 0; v < 4; v++) acc[i][j][v] = 0.f;

    const int NCH = K / 32;

    {
        cpa16(&As[0][ld_r * GP + ld_u * 4],       gA);
        cpa16(&As[0][ld_r * GP + (ld_u + 1) * 4], gA + 8);
        cpa16(&Bs[0][ld_r * GP + ld_u * 4],       gB);
        cpa16(&Bs[0][ld_r * GP + (ld_u + 1) * 4], gB + 8);
        cpa_commit();
    }

    int buf = 0;
    for (int c = 0; c < NCH; c++) {
        cpa_wait<0>();
        __syncthreads();

        if (c + 1 < NCH) {
            const int kc = (c + 1) * 32;
            cpa16(&As[buf ^ 1][ld_r * GP + ld_u * 4],       gA + kc);
            cpa16(&As[buf ^ 1][ld_r * GP + (ld_u + 1) * 4], gA + kc + 8);
            cpa16(&Bs[buf ^ 1][ld_r * GP + ld_u * 4],       gB + kc);
            cpa16(&Bs[buf ^ 1][ld_r * GP + (ld_u + 1) * 4], gB + kc + 8);
            cpa_commit();
        }

        const uint32_t aBase = asb + (uint32_t)buf * (128 * GP * 4);
        const uint32_t bBase = bsb + (uint32_t)buf * (128 * GP * 4);

#pragma unroll
        for (int ks = 0; ks < 2; ks++) {
            const int w0 = ks * 8;
            uint32_t af[4][4], bf[4][2];
#pragma unroll
            for (int mi = 0; mi < 4; mi++)
                ldsm4(af[mi][0], af[mi][1], af[mi][2], af[mi][3],
                      aBase + (uint32_t)(((warp_m * 64 + mi * 16) * GP + w0 + aLw) * 4));
#pragma unroll
            for (int p = 0; p < 2; p++)
                ldsm4(bf[2 * p][0], bf[2 * p][1], bf[2 * p + 1][0], bf[2 * p + 1][1],
                      bBase + (uint32_t)(((warp_n * 32 + p * 16) * GP + w0 + bLw) * 4));
#pragma unroll
            for (int mi = 0; mi < 4; mi++)
#pragma unroll
                for (int ni = 0; ni < 4; ni++)
                    mma_f16(acc[mi][ni][0], acc[mi][ni][1],
                            acc[mi][ni][2], acc[mi][ni][3],
                            af[mi][0], af[mi][1], af[mi][2], af[mi][3],
                            bf[ni][0], bf[ni][1]);
        }
        buf ^= 1;
    }

    // Epilogue
#pragma unroll
    for (int ni = 0; ni < 4; ni++) {
        const int col = bcol + warp_n * 32 + ni * 8 + 2 * gc;
        const float bv0 = bias[col];
        const float bv1 = bias[col + 1];
#pragma unroll
        for (int mi = 0; mi < 4; mi++) {
            const int row = brow + warp_m * 64 + mi * 16 + gr;
            const float v00 = acc[mi][ni][0] + bv0, v01 = acc[mi][ni][1] + bv1;
            const float v10 = acc[mi][ni][2] + bv0, v11 = acc[mi][ni][3] + bv1;
            if (MODE == 0) {
                *(float2*)&C[(size_t)row * N + col]       = make_float2(v00, v01);
                *(float2*)&C[(size_t)(row + 8) * N + col] = make_float2(v10, v11);
            } else {
                if (col < 1536) {
                    *(__half2*)&QK[(size_t)row * 1536 + col] = __floats2half2_rn(v00, v01);
                    *(__half2*)&QK[(size_t)(row + 8) * 1536 + col] = __floats2half2_rn(v10, v11);
                } else {
                    const int cc = col - 1536;
                    const int h  = cc >> 6;
                    const int d0 = cc & 63;
                    const int b  = row >> 10;
                    const int t  = row & 1023;
                    __half* base = VT + ((size_t)(b * NHEAD + h) * HDIM) * SEQ;
                    base[(size_t)d0 * SEQ + t]           = __float2half_rn(v00);
                    base[(size_t)(d0 + 1) * SEQ + t]     = __float2half_rn(v01);
                    base[(size_t)d0 * SEQ + t + 8]       = __float2half_rn(v10);
                    base[(size_t)(d0 + 1) * SEQ + t + 8] = __float2half_rn(v11);
                }
            }
        }
    }
}

// ---------------------------------------------------------------------------
// FP16 tensor-core flash attention (causal, m16n8k16, fp32 accum/softmax).
// Fragment loads via ldmatrix.x4 (pitch 36 words -> conflict-free).
// ---------------------------------------------------------------------------
#define APW 36   // pitch in words (32 data + 4 pad)
#define AT2_SMEM ((128 * APW + 2 * 64 * APW + 2 * 64 * APW) * 4)

__global__ __launch_bounds__(256, 2)
void attn_f16_kernel(const __half* __restrict__ qk, const __half* __restrict__ vt,
                     __half* __restrict__ out16)
{
    extern __shared__ uint32_t smw[];
    uint32_t* QP  = smw;                   // 128 x APW : Q tile, later P strips
    uint32_t* Ks0 = QP + 128 * APW;        // 2 x 64 x APW
    uint32_t* Vt0 = Ks0 + 2 * 64 * APW;    // 2 x 64 x APW

    const int tid  = threadIdx.x;
    const int lane = tid & 31;
    const int warp = tid >> 5;
    const int gr   = lane >> 2;
    const int gc   = lane & 3;

    const int bh = blockIdx.y;
    const int b  = bh / NHEAD;
    const int h  = bh % NHEAD;
    const int qt = 7 - blockIdx.x;
    const int qbase = qt * 128;
    const int ktmax = 2 * qt + 1;

    // ldmatrix per-lane offsets (words, pitch APW)
    const int lrow8 = lane & 7;
    const int segA  = (lane >> 3) & 1;
    const int segAc = lane >> 4;
    const int aLw = (segA * 8 + lrow8) * APW + segAc * 4;
    const int bLw = (segAc * 8 + lrow8) * APW + segA * 4;

    const uint32_t qpb = (uint32_t)__cvta_generic_to_shared(QP);
    const uint32_t ksb = (uint32_t)__cvta_generic_to_shared(Ks0);
    const uint32_t vtb = (uint32_t)__cvta_generic_to_shared(Vt0);

    // Q tile: 128 rows x 8 16B-units; 2 threads/row, 4 units each
    {
        const int r = tid >> 1;
        const int u = (tid & 1) * 4;
        const __half* src = qk + (size_t)(b * SEQ + qbase + r) * 1536 + h * HDIM + u * 8;
        uint32_t* dst = QP + r * APW + u * 4;
#pragma unroll
        for (int i = 0; i < 4; i++)
            cpa16(dst + 4 * i, src + 8 * i);
    }
    // K + Vt tile 0: 64 rows x 8 units; 4 threads/row, 2 units each
    {
        const int r = tid >> 2;
        const int u = (tid & 3) * 2;
        const __half* ksrc = qk + (size_t)(b * SEQ + r) * 1536 + 768 + h * HDIM + u * 8;
        const __half* vsrc = vt + ((size_t)(b * NHEAD + h) * HDIM + r) * SEQ + u * 8;
        cpa16(Ks0 + r * APW + u * 4,     ksrc);
        cpa16(Ks0 + r * APW + u * 4 + 4, ksrc + 8);
        cpa16(Vt0 + r * APW + u * 4,     vsrc);
        cpa16(Vt0 + r * APW + u * 4 + 4, vsrc + 8);
    }
    cpa_commit();
    cpa_wait<0>();
    __syncthreads();

    // Q fragments in registers: 4 k16-chunks x 4 words (ldmatrix)
    uint32_t qf[4][4];
#pragma unroll
    for (int c = 0; c < 4; c++)
        ldsm4(qf[c][0], qf[c][1], qf[c][2], qf[c][3],
              qpb + (uint32_t)(((warp * 16) * APW + c * 8 + aLw) * 4));

    float o[8][4];
#pragma unroll
    for (int i = 0; i < 8; i++)
#pragma unroll
        for (int j = 0; j < 4; j++) o[i][j] = 0.f;
    float mr0 = -1e30f, mr1 = -1e30f, l0 = 0.f, l1 = 0.f;

    const int lrow = warp * 16 + gr;        // block-local query row
    const int grow0 = qbase + lrow;         // global query row
    const int prow0 = lrow * APW;
    const int prow1 = (lrow + 8) * APW;

    int buf = 0;
    for (int kt = 0; kt <= ktmax; kt++) {
        const int kbase = kt * 64;
        cpa_wait<0>();
        __syncthreads();

        if (kt < ktmax) {
            const int r = tid >> 2;
            const int u = (tid & 3) * 2;
            const __half* ksrc = qk + (size_t)(b * SEQ + (kt + 1) * 64 + r) * 1536
                                 + 768 + h * HDIM + u * 8;
            const __half* vsrc = vt + ((size_t)(b * NHEAD + h) * HDIM + r) * SEQ
                                 + (kt + 1) * 64 + u * 8;
            uint32_t* kd = Ks0 + (buf ^ 1) * 64 * APW + r * APW + u * 4;
            uint32_t* vd = Vt0 + (buf ^ 1) * 64 * APW + r * APW + u * 4;
            cpa16(kd,     ksrc);
            cpa16(kd + 4, ksrc + 8);
            cpa16(vd,     vsrc);
            cpa16(vd + 4, vsrc + 8);
            cpa_commit();
        }

        if (kbase > qbase + warp * 16 + 15) { buf ^= 1; continue; }

        // ---- S = Q @ K^T (16 x 64 per warp), fp16 m16n8k16 ----
        float s[8][4];
#pragma unroll
        for (int i = 0; i < 8; i++)
#pragma unroll
            for (int j = 0; j < 4; j++) s[i][j] = 0.f;

        const uint32_t kBase = ksb + (uint32_t)buf * (64 * APW * 4);
#pragma unroll
        for (int c = 0; c < 4; c++) {
            const int w0 = c * 8;
            uint32_t bf[8][2];
#pragma unroll
            for (int p = 0; p < 4; p++)
                ldsm4(bf[2 * p][0], bf[2 * p][1], bf[2 * p + 1][0], bf[2 * p + 1][1],
                      kBase + (uint32_t)(((p * 16) * APW + w0 + bLw) * 4));
#pragma unroll
            for (int nt = 0; nt < 8; nt++)
                mma_f16(s[nt][0], s[nt][1], s[nt][2], s[nt][3],
                        qf[c][0], qf[c][1], qf[c][2], qf[c][3],
                        bf[nt][0], bf[nt][1]);
        }

        // ---- scale + causal mask (global frame) ----
        if (kbase + 63 > grow0) {
            const int lr0 = grow0;
            const int lr1 = grow0 + 8;
#pragma unroll
            for (int nt = 0; nt < 8; nt++) {
                const int c0 = kbase + nt * 8 + 2 * gc;
                s[nt][0] = (c0     > lr0) ? -1e30f : s[nt][0] * 0.125f;
                s[nt][1] = (c0 + 1 > lr0) ? -1e30f : s[nt][1] * 0.125f;
                s[nt][2] = (c0     > lr1) ? -1e30f : s[nt][2] * 0.125f;
                s[nt][3] = (c0 + 1 > lr1) ? -1e30f : s[nt][3] * 0.125f;
            }
        } else {
#pragma unroll
            for (int nt = 0; nt < 8; nt++) {
                s[nt][0] *= 0.125f; s[nt][1] *= 0.125f;
                s[nt][2] *= 0.125f; s[nt][3] *= 0.125f;
            }
        }

        // ---- online softmax (registers + quad shuffles) ----
        float mx0 = -1e30f, mx1 = -1e30f;
#pragma unroll
        for (int nt = 0; nt < 8; nt++) {
            mx0 = fmaxf(mx0, fmaxf(s[nt][0], s[nt][1]));
            mx1 = fmaxf(mx1, fmaxf(s[nt][2], s[nt][3]));
        }
        mx0 = fmaxf(mx0, __shfl_xor_sync(0xffffffffu, mx0, 1));
        mx0 = fmaxf(mx0, __shfl_xor_sync(0xffffffffu, mx0, 2));
        mx1 = fmaxf(mx1, __shfl_xor_sync(0xffffffffu, mx1, 1));
        mx1 = fmaxf(mx1, __shfl_xor_sync(0xffffffffu, mx1, 2));

        const float mn0 = fmaxf(mr0, mx0);
        const float mn1 = fmaxf(mr1, mx1);
        const float a0  = __expf(mr0 - mn0);
        const float a1  = __expf(mr1 - mn1);
        mr0 = mn0; mr1 = mn1;

        float sum0 = 0.f, sum1 = 0.f;
#pragma unroll
        for (int nt = 0; nt < 8; nt++) {
            s[nt][0] = __expf(s[nt][0] - mn0);
            s[nt][1] = __expf(s[nt][1] - mn0);
            s[nt][2] = __expf(s[nt][2] - mn1);
            s[nt][3] = __expf(s[nt][3] - mn1);
            sum0 += s[nt][0] + s[nt][1];
            sum1 += s[nt][2] + s[nt][3];
        }
        sum0 += __shfl_xor_sync(0xffffffffu, sum0, 1);
        sum0 += __shfl_xor_sync(0xffffffffu, sum0, 2);
        sum1 += __shfl_xor_sync(0xffffffffu, sum1, 1);
        sum1 += __shfl_xor_sync(0xffffffffu, sum1, 2);
        l0 = l0 * a0 + sum0;
        l1 = l1 * a1 + sum1;

#pragma unroll
        for (int nt = 0; nt < 8; nt++) {
            o[nt][0] *= a0; o[nt][1] *= a0;
            o[nt][2] *= a1; o[nt][3] *= a1;
        }

        // ---- P (fp16) -> warp-local smem strip; reload via ldmatrix ----
#pragma unroll
        for (int nt = 0; nt < 8; nt++) {
            QP[prow0 + nt * 4 + gc] = pack_f16x2(s[nt][0], s[nt][1]);
            QP[prow1 + nt * 4 + gc] = pack_f16x2(s[nt][2], s[nt][3]);
        }
        __syncwarp();

        // ---- O += P @ V  (A = P strip via ldmatrix, B = Vt) ----
        const uint32_t vBase = vtb + (uint32_t)buf * (64 * APW * 4);
#pragma unroll
        for (int c = 0; c < 4; c++) {
            const int w0 = c * 8;
            uint32_t af[4];
            ldsm4(af[0], af[1], af[2], af[3],
                  qpb + (uint32_t)(((warp * 16) * APW + w0 + aLw) * 4));
            uint32_t bf[8][2];
#pragma unroll
            for (int p = 0; p < 4; p++)
                ldsm4(bf[2 * p][0], bf[2 * p][1], bf[2 * p + 1][0], bf[2 * p + 1][1],
                      vBase + (uint32_t)(((p * 16) * APW + w0 + bLw) * 4));
#pragma unroll
            for (int nt = 0; nt < 8; nt++)
                mma_f16(o[nt][0], o[nt][1], o[nt][2], o[nt][3],
                        af[0], af[1], af[2], af[3],
                        bf[nt][0], bf[nt][1]);
        }
        __syncwarp();
        buf ^= 1;
    }

    // ---- epilogue: normalize, fp16, head-concat [M,768] ----
    const float inv0 = 1.f / l0;
    const float inv1 = 1.f / l1;
    const int r0g = b * SEQ + grow0;
#pragma unroll
    for (int nt = 0; nt < 8; nt++) {
        const int col = h * HDIM + nt * 8 + 2 * gc;
        *(__half2*)&out16[(size_t)r0g * EMB + col] =
            __floats2half2_rn(o[nt][0] * inv0, o[nt][1] * inv0);
        *(__half2*)&out16[(size_t)(r0g + 8) * EMB + col] =
            __floats2half2_rn(o[nt][2] * inv1, o[nt][3] * inv1);
    }
}

// ---------------------------------------------------------------------------
extern "C" void kernel_launch(void* const* d_in, const int* in_sizes, int n_in,
                              void* d_out, int out_size)
{
    const float* x      = (const float*)d_in[0];
    const float* W_attn = (const float*)d_in[1];
    const float* b_attn = (const float*)d_in[2];
    const float* W_proj = (const float*)d_in[3];
    const float* b_proj = (const float*)d_in[4];
    float* out = (float*)d_out;

    __half *x16, *wat16, *wpt16, *qk16, *vt16, *at16;
    cudaGetSymbolAddress((void**)&x16,   g_x16);
    cudaGetSymbolAddress((void**)&wat16, g_wat16);
    cudaGetSymbolAddress((void**)&wpt16, g_wpt16);
    cudaGetSymbolAddress((void**)&qk16,  g_qk16);
    cudaGetSymbolAddress((void**)&vt16,  g_vt16);
    cudaGetSymbolAddress((void**)&at16,  g_at16);

    cudaFuncSetAttribute(attn_f16_kernel,
                         cudaFuncAttributeMaxDynamicSharedMemorySize, AT2_SMEM);

    const int M = MROWS;  // 8192

    // 0) convert x -> fp16; transpose+convert weights -> [N,K] fp16
    cvt_fp16_kernel<<<(M * EMB / 4 + 255) / 256, 256>>>(x, x16, M * EMB / 4);
    transpose_fp16_kernel<<<dim3(EMB3 / 32, EMB / 32), dim3(32, 8)>>>(
        W_attn, wat16, EMB, EMB3);
    transpose_fp16_kernel<<<dim3(EMB / 32, EMB / 32), dim3(32, 8)>>>(
        W_proj, wpt16, EMB, EMB);

    // 1) QKV GEMM (fp16 mma) -> Q|K fp16 [M,1536] + V^T fp16 [B,H,d,t]
    gemm_fp16_kernel<1><<<dim3(EMB3 / 128, M / 128), 256>>>(
        x16, wat16, b_attn, nullptr, qk16, vt16, M, EMB3, EMB);

    // 2) causal MHA (fp16 mma) -> fp16 [M,768]
    attn_f16_kernel<<<dim3(SEQ / 128, BATCH * NHEAD), 256, AT2_SMEM>>>(
        qk16, vt16, at16);

    // 3) out = att @ W_proj + b_proj  (fp16 mma, fp32 out)
    gemm_fp16_kernel<0><<<dim3(EMB / 128, M / 128), 256>>>(
        at16, wpt16, b_proj, out, nullptr, nullptr, M, EMB, EMB);
}

// round 13
// speedup vs baseline: 6.0082x; 1.1177x over previous
#include <cuda_runtime.h>
#include <cuda_fp16.h>
#include <cstdint>

#define EMB   768
#define EMB3  2304
#define NHEAD 12
#define HDIM  64
#define SEQ   1024
#define BATCH 8
#define MROWS (BATCH * SEQ)   // 8192

// Q pre-scale: 0.125 * log2(e)  (folded into Q at GEMM1 epilogue)
#define QSCALE 0.1803368787f

// ---------------------------------------------------------------------------
// Scratch (no cudaMalloc allowed).
// ---------------------------------------------------------------------------
__device__ __align__(256) __half g_x16 [(size_t)MROWS * EMB];       // x fp16
__device__ __align__(256) __half g_wat16[(size_t)EMB3 * EMB];       // W_attn^T [N,K] fp16
__device__ __align__(256) __half g_wpt16[(size_t)EMB * EMB];        // W_proj^T [N,K] fp16
__device__ __align__(256) __half g_qk16[(size_t)MROWS * 2 * EMB];   // Q|K fp16 [M,1536] (Q prescaled)
__device__ __align__(256) __half g_vt16[(size_t)BATCH * NHEAD * HDIM * SEQ]; // V^T fp16 [B,H,d,t]
__device__ __align__(256) __half g_at16[(size_t)MROWS * EMB];       // attn out fp16

// ---------------------------------------------------------------------------
// Helpers
// ---------------------------------------------------------------------------
__device__ __forceinline__ void cpa16(void* smem_dst, const void* gmem_src) {
    uint32_t s = (uint32_t)__cvta_generic_to_shared(smem_dst);
    asm volatile("cp.async.cg.shared.global [%0], [%1], 16;\n" :: "r"(s), "l"(gmem_src));
}
__device__ __forceinline__ void cpa_commit() { asm volatile("cp.async.commit_group;\n"); }
template<int N>
__device__ __forceinline__ void cpa_wait() { asm volatile("cp.async.wait_group %0;\n" :: "n"(N) : "memory"); }

__device__ __forceinline__ void mma_f16(float& d0, float& d1, float& d2, float& d3,
                                        uint32_t a0, uint32_t a1, uint32_t a2, uint32_t a3,
                                        uint32_t b0, uint32_t b1) {
    asm volatile(
        "mma.sync.aligned.m16n8k16.row.col.f32.f16.f16.f32 "
        "{%0,%1,%2,%3}, {%4,%5,%6,%7}, {%8,%9}, {%0,%1,%2,%3};\n"
        : "+f"(d0), "+f"(d1), "+f"(d2), "+f"(d3)
        : "r"(a0), "r"(a1), "r"(a2), "r"(a3), "r"(b0), "r"(b1));
}

__device__ __forceinline__ void ldsm4(uint32_t& r0, uint32_t& r1,
                                      uint32_t& r2, uint32_t& r3, uint32_t addr) {
    asm volatile("ldmatrix.sync.aligned.m8n8.x4.shared.b16 {%0,%1,%2,%3}, [%4];"
                 : "=r"(r0), "=r"(r1), "=r"(r2), "=r"(r3) : "r"(addr));
}

__device__ __forceinline__ uint32_t pack_f16x2(float lo, float hi) {
    uint32_t u;
    asm("cvt.rn.f16x2.f32 %0, %1, %2;" : "=r"(u) : "f"(hi), "f"(lo));
    return u;
}

__device__ __forceinline__ float ex2f(float x) {
    float y;
    asm("ex2.approx.f32 %0, %1;" : "=f"(y) : "f"(x));
    return y;
}

// ---------------------------------------------------------------------------
// Pre-pass 1: fp32 -> fp16 (float4 -> 2x half2)
// ---------------------------------------------------------------------------
__global__ void cvt_fp16_kernel(const float* __restrict__ in, __half* __restrict__ out, int n4)
{
    int i = blockIdx.x * blockDim.x + threadIdx.x;
    if (i < n4) {
        float4 v = ((const float4*)in)[i];
        ((__half2*)out)[2 * i]     = __floats2half2_rn(v.x, v.y);
        ((__half2*)out)[2 * i + 1] = __floats2half2_rn(v.z, v.w);
    }
}

// ---------------------------------------------------------------------------
// Pre-pass 2: W[K,N] fp32 -> W^T[N,K] fp16 (32x32 smem-tiled transpose)
// ---------------------------------------------------------------------------
__global__ void transpose_fp16_kernel(const float* __restrict__ W,
                                      __half* __restrict__ T, int K, int N)
{
    __shared__ float t[32][33];
    const int tx = threadIdx.x, ty = threadIdx.y;
    const int n0 = blockIdx.x * 32, k0 = blockIdx.y * 32;
#pragma unroll
    for (int i = 0; i < 4; i++)
        t[ty + i * 8][tx] = W[(size_t)(k0 + ty + i * 8) * N + n0 + tx];
    __syncthreads();
#pragma unroll
    for (int i = 0; i < 4; i++) {
        const int n = ty + i * 8;
        T[(size_t)(n0 + n) * K + k0 + tx] = __float2half_rn(t[tx][n]);
    }
}

// ---------------------------------------------------------------------------
// FP16 tensor-core GEMM: C = A @ B^T + bias.
// A=[M,K] fp16, B=[N,K] fp16.  MT x 128 tile (MT in {128,64}), BK=32,
// 256 thr = 8 warps (2m x 4n), m16n8k16, ldmatrix fragments.
// MODE 0: C fp32 [M,N]; MODE 1 (MT=128): QKV layout (QK fp16 + V^T fp16),
//         Q columns pre-scaled by QSCALE.
// ---------------------------------------------------------------------------
#define GP 20   // smem pitch in 32-bit words

template<int MODE, int MT>
__global__ __launch_bounds__(256)
void gemm_fp16_kernel(const __half* __restrict__ A, const __half* __restrict__ B,
                      const float* __restrict__ bias, float* __restrict__ C,
                      __half* __restrict__ QK, __half* __restrict__ VT,
                      int M, int N, int K)
{
    constexpr int MI = MT / 32;            // m16 tiles per warp_m slab
    __shared__ uint32_t As[2][MT * GP];
    __shared__ uint32_t Bs[2][128 * GP];

    const int tid    = threadIdx.x;
    const int lane   = tid & 31;
    const int warp   = tid >> 5;
    const int warp_m = warp >> 2;
    const int warp_n = warp & 3;
    const int gr     = lane >> 2;
    const int gc     = lane & 3;

    const int brow = blockIdx.y * MT;
    const int bcol = blockIdx.x * 128;

    // ldmatrix per-lane offsets (in words)
    const int lrow8 = lane & 7;
    const int segA  = (lane >> 3) & 1;
    const int segAc = lane >> 4;
    const int aLw = (segA * 8 + lrow8) * GP + segAc * 4;
    const int bLw = (segAc * 8 + lrow8) * GP + segA * 4;

    const uint32_t asb = (uint32_t)__cvta_generic_to_shared(&As[0][0]);
    const uint32_t bsb = (uint32_t)__cvta_generic_to_shared(&Bs[0][0]);

    float acc[MI][4][4];
#pragma unroll
    for (int i = 0; i < MI; i++)
#pragma unroll
        for (int j = 0; j < 4; j++)
#pragma unroll
            for (int v = 0; v < 4; v++) acc[i][j][v] = 0.f;

    const int NCH = K / 32;

    // Stage loader: A = MT rows x 4 16B-units, B = 128 rows x 4 units
    auto load_stage = [&](int s, int kc) {
#pragma unroll
        for (int i = tid; i < MT * 4; i += 256) {
            const int r = i >> 2, u = i & 3;
            cpa16(&As[s][r * GP + u * 4], A + (size_t)(brow + r) * K + kc + u * 8);
        }
#pragma unroll
        for (int i = tid; i < 512; i += 256) {
            const int r = i >> 2, u = i & 3;
            cpa16(&Bs[s][r * GP + u * 4], B + (size_t)(bcol + r) * K + kc + u * 8);
        }
    };

    load_stage(0, 0);
    cpa_commit();

    int buf = 0;
    for (int c = 0; c < NCH; c++) {
        cpa_wait<0>();
        __syncthreads();

        if (c + 1 < NCH) {
            load_stage(buf ^ 1, (c + 1) * 32);
            cpa_commit();
        }

        const uint32_t aBase = asb + (uint32_t)buf * (MT * GP * 4);
        const uint32_t bBase = bsb + (uint32_t)buf * (128 * GP * 4);

#pragma unroll
        for (int ks = 0; ks < 2; ks++) {
            const int w0 = ks * 8;
            uint32_t af[MI][4], bf[4][2];
#pragma unroll
            for (int mi = 0; mi < MI; mi++)
                ldsm4(af[mi][0], af[mi][1], af[mi][2], af[mi][3],
                      aBase + (uint32_t)(((warp_m * (MT / 2) + mi * 16) * GP + w0 + aLw) * 4));
#pragma unroll
            for (int p = 0; p < 2; p++)
                ldsm4(bf[2 * p][0], bf[2 * p][1], bf[2 * p + 1][0], bf[2 * p + 1][1],
                      bBase + (uint32_t)(((warp_n * 32 + p * 16) * GP + w0 + bLw) * 4));
#pragma unroll
            for (int mi = 0; mi < MI; mi++)
#pragma unroll
                for (int ni = 0; ni < 4; ni++)
                    mma_f16(acc[mi][ni][0], acc[mi][ni][1],
                            acc[mi][ni][2], acc[mi][ni][3],
                            af[mi][0], af[mi][1], af[mi][2], af[mi][3],
                            bf[ni][0], bf[ni][1]);
        }
        buf ^= 1;
    }

    // Epilogue
#pragma unroll
    for (int ni = 0; ni < 4; ni++) {
        const int col = bcol + warp_n * 32 + ni * 8 + 2 * gc;
        const float bv0 = bias[col];
        const float bv1 = bias[col + 1];
#pragma unroll
        for (int mi = 0; mi < MI; mi++) {
            const int row = brow + warp_m * (MT / 2) + mi * 16 + gr;
            float v00 = acc[mi][ni][0] + bv0, v01 = acc[mi][ni][1] + bv1;
            float v10 = acc[mi][ni][2] + bv0, v11 = acc[mi][ni][3] + bv1;
            if (MODE == 0) {
                *(float2*)&C[(size_t)row * N + col]       = make_float2(v00, v01);
                *(float2*)&C[(size_t)(row + 8) * N + col] = make_float2(v10, v11);
            } else {
                if (col < 1536) {
                    if (col < 768) {   // Q: fold in softmax scale (log2 domain)
                        v00 *= QSCALE; v01 *= QSCALE; v10 *= QSCALE; v11 *= QSCALE;
                    }
                    *(__half2*)&QK[(size_t)row * 1536 + col] = __floats2half2_rn(v00, v01);
                    *(__half2*)&QK[(size_t)(row + 8) * 1536 + col] = __floats2half2_rn(v10, v11);
                } else {
                    const int cc = col - 1536;
                    const int h  = cc >> 6;
                    const int d0 = cc & 63;
                    const int b  = row >> 10;
                    const int t  = row & 1023;
                    __half* base = VT + ((size_t)(b * NHEAD + h) * HDIM) * SEQ;
                    base[(size_t)d0 * SEQ + t]           = __float2half_rn(v00);
                    base[(size_t)(d0 + 1) * SEQ + t]     = __float2half_rn(v01);
                    base[(size_t)d0 * SEQ + t + 8]       = __float2half_rn(v10);
                    base[(size_t)(d0 + 1) * SEQ + t + 8] = __float2half_rn(v11);
                }
            }
        }
    }
}

// ---------------------------------------------------------------------------
// FP16 tensor-core flash attention (causal, m16n8k16, fp32 softmax in the
// log2 domain: Q is pre-scaled by 0.125*log2(e), so P = 2^(S - m)).
// ---------------------------------------------------------------------------
#define APW 36   // pitch in words (32 data + 4 pad)
#define AT2_SMEM ((128 * APW + 2 * 64 * APW + 2 * 64 * APW) * 4)

__global__ __launch_bounds__(256, 2)
void attn_f16_kernel(const __half* __restrict__ qk, const __half* __restrict__ vt,
                     __half* __restrict__ out16)
{
    extern __shared__ uint32_t smw[];
    uint32_t* QP  = smw;                   // 128 x APW : Q tile, later P strips
    uint32_t* Ks0 = QP + 128 * APW;        // 2 x 64 x APW
    uint32_t* Vt0 = Ks0 + 2 * 64 * APW;    // 2 x 64 x APW

    const int tid  = threadIdx.x;
    const int lane = tid & 31;
    const int warp = tid >> 5;
    const int gr   = lane >> 2;
    const int gc   = lane & 3;

    const int bh = blockIdx.y;
    const int b  = bh / NHEAD;
    const int h  = bh % NHEAD;
    const int qt = 7 - blockIdx.x;
    const int qbase = qt * 128;
    const int ktmax = 2 * qt + 1;

    const int lrow8 = lane & 7;
    const int segA  = (lane >> 3) & 1;
    const int segAc = lane >> 4;
    const int aLw = (segA * 8 + lrow8) * APW + segAc * 4;
    const int bLw = (segAc * 8 + lrow8) * APW + segA * 4;

    const uint32_t qpb = (uint32_t)__cvta_generic_to_shared(QP);
    const uint32_t ksb = (uint32_t)__cvta_generic_to_shared(Ks0);
    const uint32_t vtb = (uint32_t)__cvta_generic_to_shared(Vt0);

    // Q tile load
    {
        const int r = tid >> 1;
        const int u = (tid & 1) * 4;
        const __half* src = qk + (size_t)(b * SEQ + qbase + r) * 1536 + h * HDIM + u * 8;
        uint32_t* dst = QP + r * APW + u * 4;
#pragma unroll
        for (int i = 0; i < 4; i++)
            cpa16(dst + 4 * i, src + 8 * i);
    }
    // K + Vt tile 0
    {
        const int r = tid >> 2;
        const int u = (tid & 3) * 2;
        const __half* ksrc = qk + (size_t)(b * SEQ + r) * 1536 + 768 + h * HDIM + u * 8;
        const __half* vsrc = vt + ((size_t)(b * NHEAD + h) * HDIM + r) * SEQ + u * 8;
        cpa16(Ks0 + r * APW + u * 4,     ksrc);
        cpa16(Ks0 + r * APW + u * 4 + 4, ksrc + 8);
        cpa16(Vt0 + r * APW + u * 4,     vsrc);
        cpa16(Vt0 + r * APW + u * 4 + 4, vsrc + 8);
    }
    cpa_commit();
    cpa_wait<0>();
    __syncthreads();

    uint32_t qf[4][4];
#pragma unroll
    for (int c = 0; c < 4; c++)
        ldsm4(qf[c][0], qf[c][1], qf[c][2], qf[c][3],
              qpb + (uint32_t)(((warp * 16) * APW + c * 8 + aLw) * 4));

    float o[8][4];
#pragma unroll
    for (int i = 0; i < 8; i++)
#pragma unroll
        for (int j = 0; j < 4; j++) o[i][j] = 0.f;
    float mr0 = -1e30f, mr1 = -1e30f, l0 = 0.f, l1 = 0.f;

    const int lrow = warp * 16 + gr;
    const int grow0 = qbase + lrow;
    const int prow0 = lrow * APW;
    const int prow1 = (lrow + 8) * APW;

    int buf = 0;
    for (int kt = 0; kt <= ktmax; kt++) {
        const int kbase = kt * 64;
        cpa_wait<0>();
        __syncthreads();

        if (kt < ktmax) {
            const int r = tid >> 2;
            const int u = (tid & 3) * 2;
            const __half* ksrc = qk + (size_t)(b * SEQ + (kt + 1) * 64 + r) * 1536
                                 + 768 + h * HDIM + u * 8;
            const __half* vsrc = vt + ((size_t)(b * NHEAD + h) * HDIM + r) * SEQ
                                 + (kt + 1) * 64 + u * 8;
            uint32_t* kd = Ks0 + (buf ^ 1) * 64 * APW + r * APW + u * 4;
            uint32_t* vd = Vt0 + (buf ^ 1) * 64 * APW + r * APW + u * 4;
            cpa16(kd,     ksrc);
            cpa16(kd + 4, ksrc + 8);
            cpa16(vd,     vsrc);
            cpa16(vd + 4, vsrc + 8);
            cpa_commit();
        }

        if (kbase > qbase + warp * 16 + 15) { buf ^= 1; continue; }

        // ---- S' = Qs @ K^T  (already in log2 domain) ----
        float s[8][4];
#pragma unroll
        for (int i = 0; i < 8; i++)
#pragma unroll
            for (int j = 0; j < 4; j++) s[i][j] = 0.f;

        const uint32_t kBase = ksb + (uint32_t)buf * (64 * APW * 4);
#pragma unroll
        for (int c = 0; c < 4; c++) {
            const int w0 = c * 8;
            uint32_t bf[8][2];
#pragma unroll
            for (int p = 0; p < 4; p++)
                ldsm4(bf[2 * p][0], bf[2 * p][1], bf[2 * p + 1][0], bf[2 * p + 1][1],
                      kBase + (uint32_t)(((p * 16) * APW + w0 + bLw) * 4));
#pragma unroll
            for (int nt = 0; nt < 8; nt++)
                mma_f16(s[nt][0], s[nt][1], s[nt][2], s[nt][3],
                        qf[c][0], qf[c][1], qf[c][2], qf[c][3],
                        bf[nt][0], bf[nt][1]);
        }

        // ---- causal mask (diagonal region only; no scale needed) ----
        if (kbase + 63 > grow0) {
            const int lr0 = grow0;
            const int lr1 = grow0 + 8;
#pragma unroll
            for (int nt = 0; nt < 8; nt++) {
                const int c0 = kbase + nt * 8 + 2 * gc;
                if (c0     > lr0) s[nt][0] = -1e30f;
                if (c0 + 1 > lr0) s[nt][1] = -1e30f;
                if (c0     > lr1) s[nt][2] = -1e30f;
                if (c0 + 1 > lr1) s[nt][3] = -1e30f;
            }
        }

        // ---- online softmax (log2 domain: P = 2^(S - m)) ----
        float mx0 = -1e30f, mx1 = -1e30f;
#pragma unroll
        for (int nt = 0; nt < 8; nt++) {
            mx0 = fmaxf(mx0, fmaxf(s[nt][0], s[nt][1]));
            mx1 = fmaxf(mx1, fmaxf(s[nt][2], s[nt][3]));
        }
        mx0 = fmaxf(mx0, __shfl_xor_sync(0xffffffffu, mx0, 1));
        mx0 = fmaxf(mx0, __shfl_xor_sync(0xffffffffu, mx0, 2));
        mx1 = fmaxf(mx1, __shfl_xor_sync(0xffffffffu, mx1, 1));
        mx1 = fmaxf(mx1, __shfl_xor_sync(0xffffffffu, mx1, 2));

        const float mn0 = fmaxf(mr0, mx0);
        const float mn1 = fmaxf(mr1, mx1);
        const float a0  = ex2f(mr0 - mn0);
        const float a1  = ex2f(mr1 - mn1);
        mr0 = mn0; mr1 = mn1;

        float sum0 = 0.f, sum1 = 0.f;
#pragma unroll
        for (int nt = 0; nt < 8; nt++) {
            s[nt][0] = ex2f(s[nt][0] - mn0);
            s[nt][1] = ex2f(s[nt][1] - mn0);
            s[nt][2] = ex2f(s[nt][2] - mn1);
            s[nt][3] = ex2f(s[nt][3] - mn1);
            sum0 += s[nt][0] + s[nt][1];
            sum1 += s[nt][2] + s[nt][3];
        }
        sum0 += __shfl_xor_sync(0xffffffffu, sum0, 1);
        sum0 += __shfl_xor_sync(0xffffffffu, sum0, 2);
        sum1 += __shfl_xor_sync(0xffffffffu, sum1, 1);
        sum1 += __shfl_xor_sync(0xffffffffu, sum1, 2);
        l0 = l0 * a0 + sum0;
        l1 = l1 * a1 + sum1;

#pragma unroll
        for (int nt = 0; nt < 8; nt++) {
            o[nt][0] *= a0; o[nt][1] *= a0;
            o[nt][2] *= a1; o[nt][3] *= a1;
        }

        // ---- P (fp16) -> warp-local smem strip ----
#pragma unroll
        for (int nt = 0; nt < 8; nt++) {
            QP[prow0 + nt * 4 + gc] = pack_f16x2(s[nt][0], s[nt][1]);
            QP[prow1 + nt * 4 + gc] = pack_f16x2(s[nt][2], s[nt][3]);
        }
        __syncwarp();

        // ---- O += P @ V ----
        const uint32_t vBase = vtb + (uint32_t)buf * (64 * APW * 4);
#pragma unroll
        for (int c = 0; c < 4; c++) {
            const int w0 = c * 8;
            uint32_t af[4];
            ldsm4(af[0], af[1], af[2], af[3],
                  qpb + (uint32_t)(((warp * 16) * APW + w0 + aLw) * 4));
            uint32_t bf[8][2];
#pragma unroll
            for (int p = 0; p < 4; p++)
                ldsm4(bf[2 * p][0], bf[2 * p][1], bf[2 * p + 1][0], bf[2 * p + 1][1],
                      vBase + (uint32_t)(((p * 16) * APW + w0 + bLw) * 4));
#pragma unroll
            for (int nt = 0; nt < 8; nt++)
                mma_f16(o[nt][0], o[nt][1], o[nt][2], o[nt][3],
                        af[0], af[1], af[2], af[3],
                        bf[nt][0], bf[nt][1]);
        }
        __syncwarp();
        buf ^= 1;
    }

    // ---- epilogue ----
    const float inv0 = 1.f / l0;
    const float inv1 = 1.f / l1;
    const int r0g = b * SEQ + grow0;
#pragma unroll
    for (int nt = 0; nt < 8; nt++) {
        const int col = h * HDIM + nt * 8 + 2 * gc;
        *(__half2*)&out16[(size_t)r0g * EMB + col] =
            __floats2half2_rn(o[nt][0] * inv0, o[nt][1] * inv0);
        *(__half2*)&out16[(size_t)(r0g + 8) * EMB + col] =
            __floats2half2_rn(o[nt][2] * inv1, o[nt][3] * inv1);
    }
}

// ---------------------------------------------------------------------------
extern "C" void kernel_launch(void* const* d_in, const int* in_sizes, int n_in,
                              void* d_out, int out_size)
{
    const float* x      = (const float*)d_in[0];
    const float* W_attn = (const float*)d_in[1];
    const float* b_attn = (const float*)d_in[2];
    const float* W_proj = (const float*)d_in[3];
    const float* b_proj = (const float*)d_in[4];
    float* out = (float*)d_out;

    __half *x16, *wat16, *wpt16, *qk16, *vt16, *at16;
    cudaGetSymbolAddress((void**)&x16,   g_x16);
    cudaGetSymbolAddress((void**)&wat16, g_wat16);
    cudaGetSymbolAddress((void**)&wpt16, g_wpt16);
    cudaGetSymbolAddress((void**)&qk16,  g_qk16);
    cudaGetSymbolAddress((void**)&vt16,  g_vt16);
    cudaGetSymbolAddress((void**)&at16,  g_at16);

    cudaFuncSetAttribute(attn_f16_kernel,
                         cudaFuncAttributeMaxDynamicSharedMemorySize, AT2_SMEM);

    const int M = MROWS;  // 8192

    // 0) convert x -> fp16; transpose+convert weights -> [N,K] fp16
    cvt_fp16_kernel<<<(M * EMB / 4 + 255) / 256, 256>>>(x, x16, M * EMB / 4);
    transpose_fp16_kernel<<<dim3(EMB3 / 32, EMB / 32), dim3(32, 8)>>>(
        W_attn, wat16, EMB, EMB3);
    transpose_fp16_kernel<<<dim3(EMB / 32, EMB / 32), dim3(32, 8)>>>(
        W_proj, wpt16, EMB, EMB);

    // 1) QKV GEMM (fp16 mma, 128-row tiles) -> Qs|K fp16 + V^T fp16
    gemm_fp16_kernel<1, 128><<<dim3(EMB3 / 128, M / 128), 256>>>(
        x16, wat16, b_attn, nullptr, qk16, vt16, M, EMB3, EMB);

    // 2) causal MHA (fp16 mma, log2-domain softmax) -> fp16 [M,768]
    attn_f16_kernel<<<dim3(SEQ / 128, BATCH * NHEAD), 256, AT2_SMEM>>>(
        qk16, vt16, at16);

    // 3) out = att @ W_proj + b_proj  (fp16 mma, 64-row tiles for tail balance)
    gemm_fp16_kernel<0, 64><<<dim3(EMB / 128, M / 64), 256>>>(
        at16, wpt16, b_proj, out, nullptr, nullptr, M, EMB, EMB);
}

// round 14
// speedup vs baseline: 6.5586x; 1.0916x over previous
#include <cuda_runtime.h>
#include <cuda_fp16.h>
#include <cstdint>

#define EMB   768
#define EMB3  2304
#define NHEAD 12
#define HDIM  64
#define SEQ   1024
#define BATCH 8
#define MROWS (BATCH * SEQ)   // 8192

// Q pre-scale: 0.125 * log2(e)  (folded into Q at GEMM1 epilogue)
#define QSCALE 0.1803368787f

// ---------------------------------------------------------------------------
// Scratch (no cudaMalloc allowed).
// ---------------------------------------------------------------------------
__device__ __align__(256) __half g_x16 [(size_t)MROWS * EMB];       // x fp16
__device__ __align__(256) __half g_wat16[(size_t)EMB3 * EMB];       // W_attn^T [N,K] fp16
__device__ __align__(256) __half g_wpt16[(size_t)EMB * EMB];        // W_proj^T [N,K] fp16
__device__ __align__(256) __half g_qk16[(size_t)MROWS * 2 * EMB];   // Qs|K fp16 [M,1536]
__device__ __align__(256) __half g_vt16[(size_t)BATCH * NHEAD * HDIM * SEQ]; // V^T fp16 [B,H,d,t]
__device__ __align__(256) __half g_at16[(size_t)MROWS * EMB];       // attn out fp16

// ---------------------------------------------------------------------------
// Helpers
// ---------------------------------------------------------------------------
__device__ __forceinline__ void cpa16(void* smem_dst, const void* gmem_src) {
    uint32_t s = (uint32_t)__cvta_generic_to_shared(smem_dst);
    asm volatile("cp.async.cg.shared.global [%0], [%1], 16;\n" :: "r"(s), "l"(gmem_src));
}
__device__ __forceinline__ void cpa_commit() { asm volatile("cp.async.commit_group;\n"); }
template<int N>
__device__ __forceinline__ void cpa_wait() { asm volatile("cp.async.wait_group %0;\n" :: "n"(N) : "memory"); }

__device__ __forceinline__ void mma_f16(float& d0, float& d1, float& d2, float& d3,
                                        uint32_t a0, uint32_t a1, uint32_t a2, uint32_t a3,
                                        uint32_t b0, uint32_t b1) {
    asm volatile(
        "mma.sync.aligned.m16n8k16.row.col.f32.f16.f16.f32 "
        "{%0,%1,%2,%3}, {%4,%5,%6,%7}, {%8,%9}, {%0,%1,%2,%3};\n"
        : "+f"(d0), "+f"(d1), "+f"(d2), "+f"(d3)
        : "r"(a0), "r"(a1), "r"(a2), "r"(a3), "r"(b0), "r"(b1));
}

__device__ __forceinline__ void ldsm4(uint32_t& r0, uint32_t& r1,
                                      uint32_t& r2, uint32_t& r3, uint32_t addr) {
    asm volatile("ldmatrix.sync.aligned.m8n8.x4.shared.b16 {%0,%1,%2,%3}, [%4];"
                 : "=r"(r0), "=r"(r1), "=r"(r2), "=r"(r3) : "r"(addr));
}

__device__ __forceinline__ uint32_t pack_f16x2(float lo, float hi) {
    uint32_t u;
    asm("cvt.rn.f16x2.f32 %0, %1, %2;" : "=r"(u) : "f"(hi), "f"(lo));
    return u;
}

__device__ __forceinline__ float ex2f(float x) {
    float y;
    asm("ex2.approx.f32 %0, %1;" : "=f"(y) : "f"(x));
    return y;
}

// ---------------------------------------------------------------------------
// Pre-pass 1: fp32 -> fp16 (float4 -> 2x half2)
// ---------------------------------------------------------------------------
__global__ void cvt_fp16_kernel(const float* __restrict__ in, __half* __restrict__ out, int n4)
{
    int i = blockIdx.x * blockDim.x + threadIdx.x;
    if (i < n4) {
        float4 v = ((const float4*)in)[i];
        ((__half2*)out)[2 * i]     = __floats2half2_rn(v.x, v.y);
        ((__half2*)out)[2 * i + 1] = __floats2half2_rn(v.z, v.w);
    }
}

// ---------------------------------------------------------------------------
// Pre-pass 2: W[K,N] fp32 -> W^T[N,K] fp16 (32x32 smem-tiled transpose)
// ---------------------------------------------------------------------------
__global__ void transpose_fp16_kernel(const float* __restrict__ W,
                                      __half* __restrict__ T, int K, int N)
{
    __shared__ float t[32][33];
    const int tx = threadIdx.x, ty = threadIdx.y;
    const int n0 = blockIdx.x * 32, k0 = blockIdx.y * 32;
#pragma unroll
    for (int i = 0; i < 4; i++)
        t[ty + i * 8][tx] = W[(size_t)(k0 + ty + i * 8) * N + n0 + tx];
    __syncthreads();
#pragma unroll
    for (int i = 0; i < 4; i++) {
        const int n = ty + i * 8;
        T[(size_t)(n0 + n) * K + k0 + tx] = __float2half_rn(t[tx][n]);
    }
}

// ---------------------------------------------------------------------------
// FP16 tensor-core GEMM: C = A @ B^T + bias.
// A=[M,K] fp16, B=[N,K] fp16.  MT x 128 tile, BK=64 (12 barriers for K=768),
// 256 thr = 8 warps (2m x 4n), m16n8k16, ldmatrix fragments, pitch 36 words.
// Dynamic smem, double-buffered cp.async (8 loads/thread/stage).
// MODE 0: C fp32 [M,N]; MODE 1 (MT=128): QKV layout, Q pre-scaled by QSCALE.
// ---------------------------------------------------------------------------
#define GW 36   // smem pitch in 32-bit words (32 data + 4 pad)

template<int MODE, int MT>
__global__ __launch_bounds__(256)
void gemm_fp16_kernel(const __half* __restrict__ A, const __half* __restrict__ B,
                      const float* __restrict__ bias, float* __restrict__ C,
                      __half* __restrict__ QK, __half* __restrict__ VT,
                      int M, int N, int K)
{
    constexpr int MI = MT / 32;            // m16 tiles per warp_m slab
    constexpr int AW = MT * GW;            // A part words per stage
    constexpr int SW = AW + 128 * GW;      // stage words

    extern __shared__ uint32_t gsm[];

    const int tid    = threadIdx.x;
    const int lane   = tid & 31;
    const int warp   = tid >> 5;
    const int warp_m = warp >> 2;
    const int warp_n = warp & 3;
    const int gr     = lane >> 2;
    const int gc     = lane & 3;

    const int brow = blockIdx.y * MT;
    const int bcol = blockIdx.x * 128;

    // ldmatrix per-lane offsets (in words)
    const int lrow8 = lane & 7;
    const int segA  = (lane >> 3) & 1;
    const int segAc = lane >> 4;
    const int aLw = (segA * 8 + lrow8) * GW + segAc * 4;
    const int bLw = (segAc * 8 + lrow8) * GW + segA * 4;

    const uint32_t smb = (uint32_t)__cvta_generic_to_shared(gsm);

    float acc[MI][4][4];
#pragma unroll
    for (int i = 0; i < MI; i++)
#pragma unroll
        for (int j = 0; j < 4; j++)
#pragma unroll
            for (int v = 0; v < 4; v++) acc[i][j][v] = 0.f;

    const int NCH = K / 64;

    // Stage loader: A = MT rows x 8 16B-units, B = 128 rows x 8 units
    auto load_stage = [&](int s, int kc) {
        uint32_t* st = gsm + s * SW;
#pragma unroll
        for (int i = tid; i < MT * 8; i += 256) {
            const int r = i >> 3, u = i & 7;
            cpa16(st + r * GW + u * 4, A + (size_t)(brow + r) * K + kc + u * 8);
        }
#pragma unroll
        for (int i = tid; i < 128 * 8; i += 256) {
            const int r = i >> 3, u = i & 7;
            cpa16(st + AW + r * GW + u * 4, B + (size_t)(bcol + r) * K + kc + u * 8);
        }
    };

    load_stage(0, 0);
    cpa_commit();

    int buf = 0;
    for (int c = 0; c < NCH; c++) {
        cpa_wait<0>();
        __syncthreads();

        if (c + 1 < NCH) {
            load_stage(buf ^ 1, (c + 1) * 64);
            cpa_commit();
        }

        const uint32_t aBase = smb + (uint32_t)(buf * SW) * 4;
        const uint32_t bBase = smb + (uint32_t)(buf * SW + AW) * 4;

#pragma unroll
        for (int ks = 0; ks < 4; ks++) {
            const int w0 = ks * 8;
            uint32_t af[MI][4], bf[4][2];
#pragma unroll
            for (int mi = 0; mi < MI; mi++)
                ldsm4(af[mi][0], af[mi][1], af[mi][2], af[mi][3],
                      aBase + (uint32_t)(((warp_m * (MT / 2) + mi * 16) * GW + w0 + aLw) * 4));
#pragma unroll
            for (int p = 0; p < 2; p++)
                ldsm4(bf[2 * p][0], bf[2 * p][1], bf[2 * p + 1][0], bf[2 * p + 1][1],
                      bBase + (uint32_t)(((warp_n * 32 + p * 16) * GW + w0 + bLw) * 4));
#pragma unroll
            for (int mi = 0; mi < MI; mi++)
#pragma unroll
                for (int ni = 0; ni < 4; ni++)
                    mma_f16(acc[mi][ni][0], acc[mi][ni][1],
                            acc[mi][ni][2], acc[mi][ni][3],
                            af[mi][0], af[mi][1], af[mi][2], af[mi][3],
                            bf[ni][0], bf[ni][1]);
        }
        buf ^= 1;
    }

    // Epilogue
#pragma unroll
    for (int ni = 0; ni < 4; ni++) {
        const int col = bcol + warp_n * 32 + ni * 8 + 2 * gc;
        const float bv0 = bias[col];
        const float bv1 = bias[col + 1];
#pragma unroll
        for (int mi = 0; mi < MI; mi++) {
            const int row = brow + warp_m * (MT / 2) + mi * 16 + gr;
            float v00 = acc[mi][ni][0] + bv0, v01 = acc[mi][ni][1] + bv1;
            float v10 = acc[mi][ni][2] + bv0, v11 = acc[mi][ni][3] + bv1;
            if (MODE == 0) {
                *(float2*)&C[(size_t)row * N + col]       = make_float2(v00, v01);
                *(float2*)&C[(size_t)(row + 8) * N + col] = make_float2(v10, v11);
            } else {
                if (col < 1536) {
                    if (col < 768) {   // Q: fold in softmax scale (log2 domain)
                        v00 *= QSCALE; v01 *= QSCALE; v10 *= QSCALE; v11 *= QSCALE;
                    }
                    *(__half2*)&QK[(size_t)row * 1536 + col] = __floats2half2_rn(v00, v01);
                    *(__half2*)&QK[(size_t)(row + 8) * 1536 + col] = __floats2half2_rn(v10, v11);
                } else {
                    const int cc = col - 1536;
                    const int h  = cc >> 6;
                    const int d0 = cc & 63;
                    const int b  = row >> 10;
                    const int t  = row & 1023;
                    __half* base = VT + ((size_t)(b * NHEAD + h) * HDIM) * SEQ;
                    base[(size_t)d0 * SEQ + t]           = __float2half_rn(v00);
                    base[(size_t)(d0 + 1) * SEQ + t]     = __float2half_rn(v01);
                    base[(size_t)d0 * SEQ + t + 8]       = __float2half_rn(v10);
                    base[(size_t)(d0 + 1) * SEQ + t + 8] = __float2half_rn(v11);
                }
            }
        }
    }
}

#define G1_SMEM (2 * (128 + 128) * GW * 4)   // 73728 B
#define G2_SMEM (2 * (64 + 128) * GW * 4)    // 55296 B

// ---------------------------------------------------------------------------
// FP16 tensor-core flash attention (causal, m16n8k16, fp32 softmax in the
// log2 domain: Q is pre-scaled by 0.125*log2(e), so P = 2^(S - m)).
// Unchanged from round 13.
// ---------------------------------------------------------------------------
#define APW 36
#define AT2_SMEM ((128 * APW + 2 * 64 * APW + 2 * 64 * APW) * 4)

__global__ __launch_bounds__(256, 2)
void attn_f16_kernel(const __half* __restrict__ qk, const __half* __restrict__ vt,
                     __half* __restrict__ out16)
{
    extern __shared__ uint32_t smw[];
    uint32_t* QP  = smw;                   // 128 x APW : Q tile, later P strips
    uint32_t* Ks0 = QP + 128 * APW;        // 2 x 64 x APW
    uint32_t* Vt0 = Ks0 + 2 * 64 * APW;    // 2 x 64 x APW

    const int tid  = threadIdx.x;
    const int lane = tid & 31;
    const int warp = tid >> 5;
    const int gr   = lane >> 2;
    const int gc   = lane & 3;

    const int bh = blockIdx.y;
    const int b  = bh / NHEAD;
    const int h  = bh % NHEAD;
    const int qt = 7 - blockIdx.x;
    const int qbase = qt * 128;
    const int ktmax = 2 * qt + 1;

    const int lrow8 = lane & 7;
    const int segA  = (lane >> 3) & 1;
    const int segAc = lane >> 4;
    const int aLw = (segA * 8 + lrow8) * APW + segAc * 4;
    const int bLw = (segAc * 8 + lrow8) * APW + segA * 4;

    const uint32_t qpb = (uint32_t)__cvta_generic_to_shared(QP);
    const uint32_t ksb = (uint32_t)__cvta_generic_to_shared(Ks0);
    const uint32_t vtb = (uint32_t)__cvta_generic_to_shared(Vt0);

    // Q tile load
    {
        const int r = tid >> 1;
        const int u = (tid & 1) * 4;
        const __half* src = qk + (size_t)(b * SEQ + qbase + r) * 1536 + h * HDIM + u * 8;
        uint32_t* dst = QP + r * APW + u * 4;
#pragma unroll
        for (int i = 0; i < 4; i++)
            cpa16(dst + 4 * i, src + 8 * i);
    }
    // K + Vt tile 0
    {
        const int r = tid >> 2;
        const int u = (tid & 3) * 2;
        const __half* ksrc = qk + (size_t)(b * SEQ + r) * 1536 + 768 + h * HDIM + u * 8;
        const __half* vsrc = vt + ((size_t)(b * NHEAD + h) * HDIM + r) * SEQ + u * 8;
        cpa16(Ks0 + r * APW + u * 4,     ksrc);
        cpa16(Ks0 + r * APW + u * 4 + 4, ksrc + 8);
        cpa16(Vt0 + r * APW + u * 4,     vsrc);
        cpa16(Vt0 + r * APW + u * 4 + 4, vsrc + 8);
    }
    cpa_commit();
    cpa_wait<0>();
    __syncthreads();

    uint32_t qf[4][4];
#pragma unroll
    for (int c = 0; c < 4; c++)
        ldsm4(qf[c][0], qf[c][1], qf[c][2], qf[c][3],
              qpb + (uint32_t)(((warp * 16) * APW + c * 8 + aLw) * 4));

    float o[8][4];
#pragma unroll
    for (int i = 0; i < 8; i++)
#pragma unroll
        for (int j = 0; j < 4; j++) o[i][j] = 0.f;
    float mr0 = -1e30f, mr1 = -1e30f, l0 = 0.f, l1 = 0.f;

    const int lrow = warp * 16 + gr;
    const int grow0 = qbase + lrow;
    const int prow0 = lrow * APW;
    const int prow1 = (lrow + 8) * APW;

    int buf = 0;
    for (int kt = 0; kt <= ktmax; kt++) {
        const int kbase = kt * 64;
        cpa_wait<0>();
        __syncthreads();

        if (kt < ktmax) {
            const int r = tid >> 2;
            const int u = (tid & 3) * 2;
            const __half* ksrc = qk + (size_t)(b * SEQ + (kt + 1) * 64 + r) * 1536
                                 + 768 + h * HDIM + u * 8;
            const __half* vsrc = vt + ((size_t)(b * NHEAD + h) * HDIM + r) * SEQ
                                 + (kt + 1) * 64 + u * 8;
            uint32_t* kd = Ks0 + (buf ^ 1) * 64 * APW + r * APW + u * 4;
            uint32_t* vd = Vt0 + (buf ^ 1) * 64 * APW + r * APW + u * 4;
            cpa16(kd,     ksrc);
            cpa16(kd + 4, ksrc + 8);
            cpa16(vd,     vsrc);
            cpa16(vd + 4, vsrc + 8);
            cpa_commit();
        }

        if (kbase > qbase + warp * 16 + 15) { buf ^= 1; continue; }

        // ---- S' = Qs @ K^T  (log2 domain) ----
        float s[8][4];
#pragma unroll
        for (int i = 0; i < 8; i++)
#pragma unroll
            for (int j = 0; j < 4; j++) s[i][j] = 0.f;

        const uint32_t kBase = ksb + (uint32_t)buf * (64 * APW * 4);
#pragma unroll
        for (int c = 0; c < 4; c++) {
            const int w0 = c * 8;
            uint32_t bf[8][2];
#pragma unroll
            for (int p = 0; p < 4; p++)
                ldsm4(bf[2 * p][0], bf[2 * p][1], bf[2 * p + 1][0], bf[2 * p + 1][1],
                      kBase + (uint32_t)(((p * 16) * APW + w0 + bLw) * 4));
#pragma unroll
            for (int nt = 0; nt < 8; nt++)
                mma_f16(s[nt][0], s[nt][1], s[nt][2], s[nt][3],
                        qf[c][0], qf[c][1], qf[c][2], qf[c][3],
                        bf[nt][0], bf[nt][1]);
        }

        // ---- causal mask ----
        if (kbase + 63 > grow0) {
            const int lr0 = grow0;
            const int lr1 = grow0 + 8;
#pragma unroll
            for (int nt = 0; nt < 8; nt++) {
                const int c0 = kbase + nt * 8 + 2 * gc;
                if (c0     > lr0) s[nt][0] = -1e30f;
                if (c0 + 1 > lr0) s[nt][1] = -1e30f;
                if (c0     > lr1) s[nt][2] = -1e30f;
                if (c0 + 1 > lr1) s[nt][3] = -1e30f;
            }
        }

        // ---- online softmax (log2 domain) ----
        float mx0 = -1e30f, mx1 = -1e30f;
#pragma unroll
        for (int nt = 0; nt < 8; nt++) {
            mx0 = fmaxf(mx0, fmaxf(s[nt][0], s[nt][1]));
            mx1 = fmaxf(mx1, fmaxf(s[nt][2], s[nt][3]));
        }
        mx0 = fmaxf(mx0, __shfl_xor_sync(0xffffffffu, mx0, 1));
        mx0 = fmaxf(mx0, __shfl_xor_sync(0xffffffffu, mx0, 2));
        mx1 = fmaxf(mx1, __shfl_xor_sync(0xffffffffu, mx1, 1));
        mx1 = fmaxf(mx1, __shfl_xor_sync(0xffffffffu, mx1, 2));

        const float mn0 = fmaxf(mr0, mx0);
        const float mn1 = fmaxf(mr1, mx1);
        const float a0  = ex2f(mr0 - mn0);
        const float a1  = ex2f(mr1 - mn1);
        mr0 = mn0; mr1 = mn1;

        float sum0 = 0.f, sum1 = 0.f;
#pragma unroll
        for (int nt = 0; nt < 8; nt++) {
            s[nt][0] = ex2f(s[nt][0] - mn0);
            s[nt][1] = ex2f(s[nt][1] - mn0);
            s[nt][2] = ex2f(s[nt][2] - mn1);
            s[nt][3] = ex2f(s[nt][3] - mn1);
            sum0 += s[nt][0] + s[nt][1];
            sum1 += s[nt][2] + s[nt][3];
        }
        sum0 += __shfl_xor_sync(0xffffffffu, sum0, 1);
        sum0 += __shfl_xor_sync(0xffffffffu, sum0, 2);
        sum1 += __shfl_xor_sync(0xffffffffu, sum1, 1);
        sum1 += __shfl_xor_sync(0xffffffffu, sum1, 2);
        l0 = l0 * a0 + sum0;
        l1 = l1 * a1 + sum1;

#pragma unroll
        for (int nt = 0; nt < 8; nt++) {
            o[nt][0] *= a0; o[nt][1] *= a0;
            o[nt][2] *= a1; o[nt][3] *= a1;
        }

        // ---- P (fp16) -> warp-local smem strip ----
#pragma unroll
        for (int nt = 0; nt < 8; nt++) {
            QP[prow0 + nt * 4 + gc] = pack_f16x2(s[nt][0], s[nt][1]);
            QP[prow1 + nt * 4 + gc] = pack_f16x2(s[nt][2], s[nt][3]);
        }
        __syncwarp();

        // ---- O += P @ V ----
        const uint32_t vBase = vtb + (uint32_t)buf * (64 * APW * 4);
#pragma unroll
        for (int c = 0; c < 4; c++) {
            const int w0 = c * 8;
            uint32_t af[4];
            ldsm4(af[0], af[1], af[2], af[3],
                  qpb + (uint32_t)(((warp * 16) * APW + w0 + aLw) * 4));
            uint32_t bf[8][2];
#pragma unroll
            for (int p = 0; p < 4; p++)
                ldsm4(bf[2 * p][0], bf[2 * p][1], bf[2 * p + 1][0], bf[2 * p + 1][1],
                      vBase + (uint32_t)(((p * 16) * APW + w0 + bLw) * 4));
#pragma unroll
            for (int nt = 0; nt < 8; nt++)
                mma_f16(o[nt][0], o[nt][1], o[nt][2], o[nt][3],
                        af[0], af[1], af[2], af[3],
                        bf[nt][0], bf[nt][1]);
        }
        __syncwarp();
        buf ^= 1;
    }

    // ---- epilogue ----
    const float inv0 = 1.f / l0;
    const float inv1 = 1.f / l1;
    const int r0g = b * SEQ + grow0;
#pragma unroll
    for (int nt = 0; nt < 8; nt++) {
        const int col = h * HDIM + nt * 8 + 2 * gc;
        *(__half2*)&out16[(size_t)r0g * EMB + col] =
            __floats2half2_rn(o[nt][0] * inv0, o[nt][1] * inv0);
        *(__half2*)&out16[(size_t)(r0g + 8) * EMB + col] =
            __floats2half2_rn(o[nt][2] * inv1, o[nt][3] * inv1);
    }
}

// ---------------------------------------------------------------------------
extern "C" void kernel_launch(void* const* d_in, const int* in_sizes, int n_in,
                              void* d_out, int out_size)
{
    const float* x      = (const float*)d_in[0];
    const float* W_attn = (const float*)d_in[1];
    const float* b_attn = (const float*)d_in[2];
    const float* W_proj = (const float*)d_in[3];
    const float* b_proj = (const float*)d_in[4];
    float* out = (float*)d_out;

    __half *x16, *wat16, *wpt16, *qk16, *vt16, *at16;
    cudaGetSymbolAddress((void**)&x16,   g_x16);
    cudaGetSymbolAddress((void**)&wat16, g_wat16);
    cudaGetSymbolAddress((void**)&wpt16, g_wpt16);
    cudaGetSymbolAddress((void**)&qk16,  g_qk16);
    cudaGetSymbolAddress((void**)&vt16,  g_vt16);
    cudaGetSymbolAddress((void**)&at16,  g_at16);

    cudaFuncSetAttribute(attn_f16_kernel,
                         cudaFuncAttributeMaxDynamicSharedMemorySize, AT2_SMEM);
    cudaFuncSetAttribute(gemm_fp16_kernel<1, 128>,
                         cudaFuncAttributeMaxDynamicSharedMemorySize, G1_SMEM);
    cudaFuncSetAttribute(gemm_fp16_kernel<0, 64>,
                         cudaFuncAttributeMaxDynamicSharedMemorySize, G2_SMEM);

    const int M = MROWS;  // 8192

    // 0) convert x -> fp16; transpose+convert weights -> [N,K] fp16
    cvt_fp16_kernel<<<(M * EMB / 4 + 255) / 256, 256>>>(x, x16, M * EMB / 4);
    transpose_fp16_kernel<<<dim3(EMB3 / 32, EMB / 32), dim3(32, 8)>>>(
        W_attn, wat16, EMB, EMB3);
    transpose_fp16_kernel<<<dim3(EMB / 32, EMB / 32), dim3(32, 8)>>>(
        W_proj, wpt16, EMB, EMB);

    // 1) QKV GEMM (fp16 mma, BK=64) -> Qs|K fp16 + V^T fp16
    gemm_fp16_kernel<1, 128><<<dim3(EMB3 / 128, M / 128), 256, G1_SMEM>>>(
        x16, wat16, b_attn, nullptr, qk16, vt16, M, EMB3, EMB);

    // 2) causal MHA (fp16 mma, log2-domain softmax) -> fp16 [M,768]
    attn_f16_kernel<<<dim3(SEQ / 128, BATCH * NHEAD), 256, AT2_SMEM>>>(
        qk16, vt16, at16);

    // 3) out = att @ W_proj + b_proj  (fp16 mma, BK=64, 64-row tiles)
    gemm_fp16_kernel<0, 64><<<dim3(EMB / 128, M / 64), 256, G2_SMEM>>>(
        at16, wpt16, b_proj, out, nullptr, nullptr, M, EMB, EMB);
}